// round 1
// baseline (speedup 1.0000x reference)
#include <cuda_runtime.h>
#include <cstdint>

// Problem constants (fixed by the dataset): B=32, M=1024, E=1024, H=8, D=128
#define EDIM 1024
#define HEADS 8
#define DHEAD 128
#define MAXTOK 32768

// Scratch buffers (allocation-free rule: __device__ globals)
__device__ float g_q[(size_t)MAXTOK * EDIM];
__device__ float g_k[(size_t)MAXTOK * EDIM];
__device__ float g_v[(size_t)MAXTOK * EDIM];
__device__ float g_o[(size_t)MAXTOK * EDIM];

// ---------------------------------------------------------------------------
// Fused GEMM: C = A @ W^T + bias, optional CELU(1.3) + GroupNorm(128-chan grp)
// Tile: 128(rows) x 128(cols), BK=16, 256 threads, 8x8 register tile.
// The 128-wide column tile is exactly one GroupNorm group, so the normalize
// can be done entirely in-block with a row reduction over 16 tx lanes.
// ---------------------------------------------------------------------------
template <bool GN>
__global__ void __launch_bounds__(256, 2) gemm_fused(
    const float* __restrict__ A, const float* __restrict__ W,
    const float* __restrict__ bias, const float* __restrict__ gamma,
    const float* __restrict__ beta, float* __restrict__ C)
{
    __shared__ float As[16][128];
    __shared__ float Bs[16][128];

    const int tid = threadIdx.x;
    const int tx = tid & 15;       // column sub-tile
    const int ty = tid >> 4;       // row sub-tile
    const int row0 = blockIdx.y << 7;
    const int col0 = blockIdx.x << 7;

    const float* Ap = A + (size_t)row0 * EDIM;
    const float* Wp = W + (size_t)col0 * EDIM;

    float acc[8][8];
#pragma unroll
    for (int i = 0; i < 8; i++)
#pragma unroll
        for (int j = 0; j < 8; j++) acc[i][j] = 0.f;

    for (int kb = 0; kb < EDIM; kb += 16) {
        // Load A tile (128 rows x 16 k) and W tile (128 out-ch x 16 k),
        // stored k-major in shared for the compute loop.
#pragma unroll
        for (int l = 0; l < 2; l++) {
            int f = tid + l * 256;            // 0..511 float4 slots
            int m = f >> 2;                   // row / out-channel within tile
            int kq = (f & 3) << 2;            // k offset within BK
            float4 va = *(const float4*)&Ap[(size_t)m * EDIM + kb + kq];
            As[kq + 0][m] = va.x; As[kq + 1][m] = va.y;
            As[kq + 2][m] = va.z; As[kq + 3][m] = va.w;
            float4 vb = *(const float4*)&Wp[(size_t)m * EDIM + kb + kq];
            Bs[kq + 0][m] = vb.x; Bs[kq + 1][m] = vb.y;
            Bs[kq + 2][m] = vb.z; Bs[kq + 3][m] = vb.w;
        }
        __syncthreads();
#pragma unroll
        for (int k = 0; k < 16; k++) {
            float4 a0 = *(const float4*)&As[k][ty * 8];
            float4 a1 = *(const float4*)&As[k][ty * 8 + 4];
            float4 b0 = *(const float4*)&Bs[k][tx * 8];
            float4 b1 = *(const float4*)&Bs[k][tx * 8 + 4];
            float av[8] = {a0.x, a0.y, a0.z, a0.w, a1.x, a1.y, a1.z, a1.w};
            float bv[8] = {b0.x, b0.y, b0.z, b0.w, b1.x, b1.y, b1.z, b1.w};
#pragma unroll
            for (int i = 0; i < 8; i++)
#pragma unroll
                for (int j = 0; j < 8; j++)
                    acc[i][j] += av[i] * bv[j];
        }
        __syncthreads();
    }

    const int cbase = col0 + tx * 8;
    float4 bb0 = *(const float4*)&bias[cbase];
    float4 bb1 = *(const float4*)&bias[cbase + 4];
    float bvv[8] = {bb0.x, bb0.y, bb0.z, bb0.w, bb1.x, bb1.y, bb1.z, bb1.w};

    if (GN) {
        // bias + CELU(alpha=1.3)
#pragma unroll
        for (int i = 0; i < 8; i++)
#pragma unroll
            for (int j = 0; j < 8; j++) {
                float t = acc[i][j] + bvv[j];
                acc[i][j] = (t > 0.f) ? t : 1.3f * expm1f(t * (1.0f / 1.3f));
            }
        // per-row (token) mean/var over the 128-channel group in this block
        float* redS = &As[0][0];   // 2048 floats, reuse smem (safe: synced)
        float* redQ = &Bs[0][0];
#pragma unroll
        for (int i = 0; i < 8; i++) {
            float s = 0.f, s2 = 0.f;
#pragma unroll
            for (int j = 0; j < 8; j++) { s += acc[i][j]; s2 += acc[i][j] * acc[i][j]; }
            int r = ty * 8 + i;
            redS[r * 16 + tx] = s;
            redQ[r * 16 + tx] = s2;
        }
        __syncthreads();
        float4 g0 = *(const float4*)&gamma[cbase];
        float4 g1 = *(const float4*)&gamma[cbase + 4];
        float4 e0 = *(const float4*)&beta[cbase];
        float4 e1 = *(const float4*)&beta[cbase + 4];
        float gvv[8] = {g0.x, g0.y, g0.z, g0.w, g1.x, g1.y, g1.z, g1.w};
        float evv[8] = {e0.x, e0.y, e0.z, e0.w, e1.x, e1.y, e1.z, e1.w};
#pragma unroll
        for (int i = 0; i < 8; i++) {
            int r = ty * 8 + i;
            float s = 0.f, s2 = 0.f;
#pragma unroll
            for (int t = 0; t < 16; t++) { s += redS[r * 16 + t]; s2 += redQ[r * 16 + t]; }
            float mean = s * (1.0f / 128.0f);
            float var = s2 * (1.0f / 128.0f) - mean * mean;
            float rs = rsqrtf(var + 1e-5f);
#pragma unroll
            for (int j = 0; j < 8; j++)
                acc[i][j] = (acc[i][j] - mean) * rs * gvv[j] + evv[j];
        }
    } else {
#pragma unroll
        for (int i = 0; i < 8; i++)
#pragma unroll
            for (int j = 0; j < 8; j++)
                acc[i][j] += bvv[j];
    }

#pragma unroll
    for (int i = 0; i < 8; i++) {
        int r = row0 + ty * 8 + i;
        float4 r0 = make_float4(acc[i][0], acc[i][1], acc[i][2], acc[i][3]);
        float4 r1 = make_float4(acc[i][4], acc[i][5], acc[i][6], acc[i][7]);
        *(float4*)&C[(size_t)r * EDIM + cbase] = r0;
        *(float4*)&C[(size_t)r * EDIM + cbase + 4] = r1;
    }
}

// ---------------------------------------------------------------------------
// Flash-style attention, fp32. One block = 64 query rows of one (b, h).
// Streams 32-key K/V tiles, online softmax, honors int mask.
// Layout: q/k/v live in token-major [N, E] buffers; head h occupies
// channels [h*128, (h+1)*128) of each token row.
// ---------------------------------------------------------------------------
#define ATTN_SMEM_FLOATS (64*132 + 32*132 + 32*132 + 64*33 + 64*16 + 32)
#define ATTN_SMEM_BYTES  (ATTN_SMEM_FLOATS * 4)

__global__ void __launch_bounds__(256, 2) attn_kernel(
    const float* __restrict__ Q, const float* __restrict__ K,
    const float* __restrict__ V, const int* __restrict__ mask,
    float* __restrict__ O, int M)
{
    extern __shared__ float sm[];
    float* Qs = sm;                       // 64 x 132 (pad kills bank conflicts)
    float* Ks = Qs + 64 * 132;            // 32 x 132
    float* Vs = Ks + 32 * 132;            // 32 x 132
    float* Ps = Vs + 32 * 132;            // 64 x 33
    float* red = Ps + 64 * 33;            // 64 x 16
    int* smask = (int*)(red + 64 * 16);   // 32

    const int tid = threadIdx.x;
    const int tx = tid & 15, ty = tid >> 4;
    const int qrow0 = blockIdx.x * 64;
    const int h = blockIdx.y;
    const int b = blockIdx.z;
    const size_t baseQ = ((size_t)b * M + qrow0) * EDIM + h * DHEAD;
    const size_t baseK = ((size_t)b * M) * EDIM + h * DHEAD;

    // Load Q tile (64 x 128)
#pragma unroll
    for (int l = 0; l < 8; l++) {
        int f = tid + l * 256;            // float4 slot 0..2047
        int m = f >> 5;                   // q row 0..63
        int c = (f & 31) << 2;            // channel 0..124
        *(float4*)&Qs[m * 132 + c] = *(const float4*)&Q[baseQ + (size_t)m * EDIM + c];
    }

    float o[4][8];
    float mi[4], li[4];
#pragma unroll
    for (int i = 0; i < 4; i++) {
        mi[i] = -1e30f; li[i] = 0.f;
#pragma unroll
        for (int j = 0; j < 8; j++) o[i][j] = 0.f;
    }
    const float scaling = 0.08838834764831845f;  // 128^-0.5

    for (int kt = 0; kt < M; kt += 32) {
        // Load K/V tiles (32 x 128 each) + mask slice
#pragma unroll
        for (int l = 0; l < 4; l++) {
            int f = tid + l * 256;
            int m = f >> 5;
            int c = (f & 31) << 2;
            size_t g = baseK + (size_t)(kt + m) * EDIM + c;
            *(float4*)&Ks[m * 132 + c] = *(const float4*)&K[g];
            *(float4*)&Vs[m * 132 + c] = *(const float4*)&V[g];
        }
        if (tid < 32) smask[tid] = mask[(size_t)b * M + kt + tid];
        __syncthreads();

        // S = Q K^T for this tile: thread tile 4 rows x 2 cols
        float s[4][2] = {{0.f, 0.f}, {0.f, 0.f}, {0.f, 0.f}, {0.f, 0.f}};
#pragma unroll
        for (int d = 0; d < DHEAD; d += 4) {
            float4 qv[4], kv[2];
#pragma unroll
            for (int i = 0; i < 4; i++) qv[i] = *(const float4*)&Qs[(ty * 4 + i) * 132 + d];
#pragma unroll
            for (int j = 0; j < 2; j++) kv[j] = *(const float4*)&Ks[(tx * 2 + j) * 132 + d];
#pragma unroll
            for (int i = 0; i < 4; i++)
#pragma unroll
                for (int j = 0; j < 2; j++)
                    s[i][j] += qv[i].x * kv[j].x + qv[i].y * kv[j].y
                             + qv[i].z * kv[j].z + qv[i].w * kv[j].w;
        }
#pragma unroll
        for (int i = 0; i < 4; i++)
#pragma unroll
            for (int j = 0; j < 2; j++) {
                s[i][j] *= scaling;
                if (smask[tx * 2 + j] == 0) s[i][j] = -1e9f;
            }

        // row max across 16 tx lanes
#pragma unroll
        for (int i = 0; i < 4; i++)
            red[(ty * 4 + i) * 16 + tx] = fmaxf(s[i][0], s[i][1]);
        __syncthreads();
        float alpha[4];
#pragma unroll
        for (int i = 0; i < 4; i++) {
            int r = ty * 4 + i;
            float tm = -1e30f;
#pragma unroll
            for (int t = 0; t < 16; t++) tm = fmaxf(tm, red[r * 16 + t]);
            float mn = fmaxf(mi[i], tm);
            alpha[i] = __expf(mi[i] - mn);
            mi[i] = mn;
        }
        __syncthreads();  // red reuse

        // p = exp(s - m), row sum
#pragma unroll
        for (int i = 0; i < 4; i++) {
            int r = ty * 4 + i;
            float ps = 0.f;
#pragma unroll
            for (int j = 0; j < 2; j++) {
                float p = __expf(s[i][j] - mi[i]);
                Ps[r * 33 + tx * 2 + j] = p;
                ps += p;
            }
            red[r * 16 + tx] = ps;
        }
        __syncthreads();
#pragma unroll
        for (int i = 0; i < 4; i++) {
            int r = ty * 4 + i;
            float ts = 0.f;
#pragma unroll
            for (int t = 0; t < 16; t++) ts += red[r * 16 + t];
            li[i] = li[i] * alpha[i] + ts;
#pragma unroll
            for (int j = 0; j < 8; j++) o[i][j] *= alpha[i];
        }

        // O += P @ V   (thread tile 4 rows x 8 cols of D)
#pragma unroll 8
        for (int kk = 0; kk < 32; kk++) {
            float pa[4];
#pragma unroll
            for (int i = 0; i < 4; i++) pa[i] = Ps[(ty * 4 + i) * 33 + kk];
            float4 v0 = *(const float4*)&Vs[kk * 132 + tx * 8];
            float4 v1 = *(const float4*)&Vs[kk * 132 + tx * 8 + 4];
#pragma unroll
            for (int i = 0; i < 4; i++) {
                o[i][0] += pa[i] * v0.x; o[i][1] += pa[i] * v0.y;
                o[i][2] += pa[i] * v0.z; o[i][3] += pa[i] * v0.w;
                o[i][4] += pa[i] * v1.x; o[i][5] += pa[i] * v1.y;
                o[i][6] += pa[i] * v1.z; o[i][7] += pa[i] * v1.w;
            }
        }
        __syncthreads();  // before overwriting Ks/Vs/Ps next iter
    }

    // epilogue: O / l, write to token-major buffer
#pragma unroll
    for (int i = 0; i < 4; i++) {
        int r = ty * 4 + i;
        float inv = 1.0f / li[i];
        float4 r0 = make_float4(o[i][0] * inv, o[i][1] * inv, o[i][2] * inv, o[i][3] * inv);
        float4 r1 = make_float4(o[i][4] * inv, o[i][5] * inv, o[i][6] * inv, o[i][7] * inv);
        size_t g = ((size_t)b * M + qrow0 + r) * EDIM + h * DHEAD + tx * 8;
        *(float4*)&O[g] = r0;
        *(float4*)&O[g + 4] = r1;
    }
}

// ---------------------------------------------------------------------------
// Launch: 3 fused proj GEMMs -> attention -> output GEMM. Graph-capturable:
// only kernel launches + non-stream host API (GetSymbolAddress/FuncSetAttr).
// ---------------------------------------------------------------------------
extern "C" void kernel_launch(void* const* d_in, const int* in_sizes, int n_in,
                              void* d_out, int out_size)
{
    const float* query  = (const float*)d_in[0];
    const float* key    = (const float*)d_in[1];
    const int*   mask   = (const int*)d_in[2];
    // d_in[3] = value1, intentionally unused (matches reference)
    const float* value2 = (const float*)d_in[4];
    const float* Wq = (const float*)d_in[5];
    const float* bq = (const float*)d_in[6];
    const float* gq = (const float*)d_in[7];
    const float* betaq = (const float*)d_in[8];
    const float* Wk = (const float*)d_in[9];
    const float* bk = (const float*)d_in[10];
    const float* gk = (const float*)d_in[11];
    const float* betak = (const float*)d_in[12];
    const float* Wv = (const float*)d_in[13];
    const float* bv = (const float*)d_in[14];
    const float* gv = (const float*)d_in[15];
    const float* betav = (const float*)d_in[16];
    const float* Wm = (const float*)d_in[17];
    const float* bm = (const float*)d_in[18];

    const int B = in_sizes[3] / EDIM;   // value1 is [B, E]
    const int Ntok = in_sizes[2];       // mask is [B, M]
    const int M = Ntok / B;

    float *qb, *kb, *vb, *ob;
    cudaGetSymbolAddress((void**)&qb, g_q);
    cudaGetSymbolAddress((void**)&kb, g_k);
    cudaGetSymbolAddress((void**)&vb, g_v);
    cudaGetSymbolAddress((void**)&ob, g_o);

    dim3 blk(256);
    dim3 gg(EDIM / 128, Ntok / 128);

    gemm_fused<true><<<gg, blk>>>(query,  Wq, bq, gq, betaq, qb);
    gemm_fused<true><<<gg, blk>>>(key,    Wk, bk, gk, betak, kb);
    gemm_fused<true><<<gg, blk>>>(value2, Wv, bv, gv, betav, vb);

    cudaFuncSetAttribute(attn_kernel, cudaFuncAttributeMaxDynamicSharedMemorySize,
                         ATTN_SMEM_BYTES);
    dim3 ga(M / 64, HEADS, B);
    attn_kernel<<<ga, blk, ATTN_SMEM_BYTES>>>(qb, kb, vb, mask, ob, M);

    gemm_fused<false><<<gg, blk>>>(ob, Wm, bm, nullptr, nullptr, (float*)d_out);
}

// round 3
// speedup vs baseline: 1.5757x; 1.5757x over previous
#include <cuda_runtime.h>
#include <cuda_bf16.h>
#include <cstdint>

// Problem constants (fixed by dataset): B=32, M=1024, E=1024, H=8, D=128
#define EDIM 1024
#define HEADS 8
#define DHEAD 128
#define MAXTOK 32768
#define KP 3072          // packed K for 3xbf16 split
#define NCH 48           // KP / 64 k-chunks

// Scratch (__device__ globals: allocation-free rule)
__device__ __nv_bfloat16 g_abf[(size_t)MAXTOK * KP];   // packed activations
__device__ __nv_bfloat16 g_wbf[(size_t)EDIM * KP];     // packed weights
__device__ float g_q[(size_t)MAXTOK * EDIM];
__device__ float g_k[(size_t)MAXTOK * EDIM];
__device__ float g_v[(size_t)MAXTOK * EDIM];

// ---------------------------------------------------------------------------
// helpers (baseline PTX only: works on non-'a' sm_103 target)
// ---------------------------------------------------------------------------
__device__ __forceinline__ uint32_t s2u(const void* p) {
    uint32_t a;
    asm("{ .reg .u64 t; cvta.to.shared.u64 t, %1; cvt.u32.u64 %0, t; }"
        : "=r"(a) : "l"(p));
    return a;
}
__device__ __forceinline__ void ldsm_x4(uint32_t* r, uint32_t addr) {
    asm volatile("ldmatrix.sync.aligned.m8n8.x4.shared.b16 {%0,%1,%2,%3}, [%4];"
        : "=r"(r[0]), "=r"(r[1]), "=r"(r[2]), "=r"(r[3]) : "r"(addr));
}
__device__ __forceinline__ void mma16816(float* d, const uint32_t* a,
                                         const uint32_t* b) {
    asm volatile("mma.sync.aligned.m16n8k16.row.col.f32.bf16.bf16.f32 "
        "{%0,%1,%2,%3}, {%4,%5,%6,%7}, {%8,%9}, {%0,%1,%2,%3};"
        : "+f"(d[0]), "+f"(d[1]), "+f"(d[2]), "+f"(d[3])
        : "r"(a[0]), "r"(a[1]), "r"(a[2]), "r"(a[3]), "r"(b[0]), "r"(b[1]));
}
__device__ __forceinline__ void cpasync16(uint32_t dst, const void* src) {
    asm volatile("cp.async.cg.shared.global [%0], [%1], 16;"
                 :: "r"(dst), "l"(src) : "memory");
}

// ---------------------------------------------------------------------------
// fp32 -> packed 3xbf16.  ISA(true): [hi | lo | hi]  (activations)
//                         ISA(false): [hi | hi | lo] (weights)
// ---------------------------------------------------------------------------
template <bool ISA>
__global__ void convert3(const float* __restrict__ in,
                         __nv_bfloat16* __restrict__ out) {
    size_t i = ((size_t)blockIdx.x * 256 + threadIdx.x) * 4;
    float4 v = *(const float4*)(in + i);
    size_t r = i >> 10;
    int c = (int)(i & 1023);
    float f[4] = {v.x, v.y, v.z, v.w};
    __nv_bfloat16 h[4], l[4];
#pragma unroll
    for (int j = 0; j < 4; j++) {
        h[j] = __float2bfloat16(f[j]);
        l[j] = __float2bfloat16(f[j] - __bfloat162float(h[j]));
    }
    __nv_bfloat162 h01, h23, l01, l23;
    h01.x = h[0]; h01.y = h[1]; h23.x = h[2]; h23.y = h[3];
    l01.x = l[0]; l01.y = l[1]; l23.x = l[2]; l23.y = l[3];
    __nv_bfloat16* row = out + r * KP;
    *(__nv_bfloat162*)(row + c)            = h01;
    *(__nv_bfloat162*)(row + c + 2)        = h23;
    *(__nv_bfloat162*)(row + 1024 + c)     = ISA ? l01 : h01;
    *(__nv_bfloat162*)(row + 1024 + c + 2) = ISA ? l23 : h23;
    *(__nv_bfloat162*)(row + 2048 + c)     = ISA ? h01 : l01;
    *(__nv_bfloat162*)(row + 2048 + c + 2) = ISA ? h23 : l23;
}

// ---------------------------------------------------------------------------
// HMMA GEMM: C[m,n] = sum_k A'[m,k] W'[n,k], both K-major bf16, K'=3072.
// CTA 128x128, BK=64 (128B SW128 rows), 3-stage cp.async pipeline, 256 thr.
// 8 warps (2 M x 4 N), warp tile 64x32, m16n8k16 bf16 mma, f32 accum.
// Epilogue: +bias [+ CELU(1.3) + GroupNorm over the CTA's 128-col group].
// ---------------------------------------------------------------------------
#define STAGE_BYTES 32768                    // A 16KB + W 16KB
#define GEMM_SMEM (3 * STAGE_BYTES + 2048)   // stages + params

template <bool GN>
__global__ void __launch_bounds__(256, 2) gemm_tc(
    const __nv_bfloat16* __restrict__ A, const __nv_bfloat16* __restrict__ W,
    const float* __restrict__ bias, const float* __restrict__ gamma,
    const float* __restrict__ beta, float* __restrict__ C)
{
    extern __shared__ char dsm[];
    const uint32_t sb = s2u(dsm);
    const int tid = threadIdx.x;
    const int lane = tid & 31;
    const int wrp = tid >> 5;
    const int wm = wrp & 1;          // 2 M-bands of 64
    const int wn = wrp >> 1;         // 4 N-bands of 32
    const int row0 = blockIdx.y << 7;
    const int col0 = blockIdx.x << 7;

    float* sp = (float*)(dsm + 3 * STAGE_BYTES);   // bias/gamma/beta [128] each
    if (tid < 128) {
        sp[tid] = bias[col0 + tid];
        if (GN) {
            sp[128 + tid] = gamma[col0 + tid];
            sp[256 + tid] = beta[col0 + tid];
        }
    }

    // global load geometry: each thread copies 4x16B for A and 4x16B for W
    const int gr = tid >> 3;               // row 0..31 (+32*l)
    const int q16 = (tid & 7) << 4;        // 16B column within 128B chunk
    const char* Agp = (const char*)(A + (size_t)row0 * KP) + q16;
    const char* Bgp = (const char*)(W + (size_t)col0 * KP) + q16;
    const size_t rstride = (size_t)KP * 2; // 6144 B

    auto load_stage = [&](int c, int s) {
        uint32_t Ab = sb + s * STAGE_BYTES;
        uint32_t Bb = Ab + 16384;
#pragma unroll
        for (int l = 0; l < 4; l++) {
            int r = gr + (l << 5);
            int off = (r << 7) + q16;
            int sw = off ^ ((off >> 3) & 0x70);
            cpasync16(Ab + sw, Agp + (size_t)r * rstride + (size_t)c * 128);
            cpasync16(Bb + sw, Bgp + (size_t)r * rstride + (size_t)c * 128);
        }
        asm volatile("cp.async.commit_group;" ::: "memory");
    };

    load_stage(0, 0);
    load_stage(1, 1);

    // per-lane ldmatrix base offsets (within a stage)
    // A frag (m16k16): row = m0 + (lane&15), col16B-half = (lane>>4)
    uint32_t abase[4];
#pragma unroll
    for (int i = 0; i < 4; i++) {
        int row = wm * 64 + i * 16 + (lane & 15);
        abase[i] = (row << 7) + ((lane >> 4) << 4);
    }
    // B frag pair (n16k16): row = n0 + (lane&7) + ((lane>>4)<<3),
    //                       col16B-half = (lane>>3)&1
    uint32_t bbase[2];
#pragma unroll
    for (int j2 = 0; j2 < 2; j2++) {
        int row = wn * 32 + j2 * 16 + (lane & 7) + ((lane >> 4) << 3);
        bbase[j2] = (row << 7) + (((lane >> 3) & 1) << 4);
    }

    float acc[4][4][4];
#pragma unroll
    for (int i = 0; i < 4; i++)
#pragma unroll
        for (int j = 0; j < 4; j++)
#pragma unroll
            for (int t = 0; t < 4; t++) acc[i][j][t] = 0.f;

    for (int c = 0; c < NCH; c++) {
        if (c < NCH - 2) asm volatile("cp.async.wait_group 1;" ::: "memory");
        else             asm volatile("cp.async.wait_group 0;" ::: "memory");
        __syncthreads();
        if (c + 2 < NCH) load_stage(c + 2, (c + 2) % 3);

        const uint32_t Ab = sb + (c % 3) * STAGE_BYTES;
        const uint32_t Bb = Ab + 16384;
#pragma unroll
        for (int ks = 0; ks < 4; ks++) {
            const int kb = ks << 5;   // 32 bytes per k16
            uint32_t a[4][4], b[2][4];
#pragma unroll
            for (int i = 0; i < 4; i++) {
                uint32_t off = abase[i] + kb;
                ldsm_x4(a[i], Ab + (off ^ ((off >> 3) & 0x70)));
            }
#pragma unroll
            for (int j2 = 0; j2 < 2; j2++) {
                uint32_t off = bbase[j2] + kb;
                ldsm_x4(b[j2], Bb + (off ^ ((off >> 3) & 0x70)));
            }
#pragma unroll
            for (int i = 0; i < 4; i++)
#pragma unroll
                for (int j2 = 0; j2 < 2; j2++) {
                    mma16816(acc[i][j2 * 2 + 0], a[i], &b[j2][0]);
                    mma16816(acc[i][j2 * 2 + 1], a[i], &b[j2][2]);
                }
        }
        __syncthreads();
    }

    // ---------------- epilogue ----------------
    // acc lane mapping: d0,d1 -> (row=lane>>2, col=(lane&3)*2 +0/1),
    //                   d2,d3 -> row+8.
    const int lr = lane >> 2;       // 0..7
    const int lc = (lane & 3) << 1; // 0,2,4,6

    if (GN) {
        float* redS = (float*)dsm;          // [128][4] sums (stage smem reuse)
        float* redQ = redS + 512;           // [128][4] sumsq
        // pass 0: bias + CELU (overwrite acc), per-row partial sums
#pragma unroll
        for (int i = 0; i < 4; i++) {
            float s0 = 0.f, q0 = 0.f, s1 = 0.f, q1 = 0.f;
#pragma unroll
            for (int j = 0; j < 4; j++) {
                int cl = wn * 32 + j * 8 + lc;
#pragma unroll
                for (int t = 0; t < 4; t++) {
                    float v = acc[i][j][t] + sp[cl + (t & 1)];
                    v = v > 0.f ? v : 1.3f * expm1f(v * (1.0f / 1.3f));
                    acc[i][j][t] = v;
                    if (t < 2) { s0 += v; q0 += v * v; }
                    else       { s1 += v; q1 += v * v; }
                }
            }
#pragma unroll
            for (int o = 1; o < 4; o <<= 1) {
                s0 += __shfl_xor_sync(0xFFFFFFFFu, s0, o);
                q0 += __shfl_xor_sync(0xFFFFFFFFu, q0, o);
                s1 += __shfl_xor_sync(0xFFFFFFFFu, s1, o);
                q1 += __shfl_xor_sync(0xFFFFFFFFu, q1, o);
            }
            if ((lane & 3) == 0) {
                int r = wm * 64 + i * 16 + lr;
                redS[r * 4 + wn] = s0;  redQ[r * 4 + wn] = q0;
                redS[(r + 8) * 4 + wn] = s1;  redQ[(r + 8) * 4 + wn] = q1;
            }
        }
        __syncthreads();
#pragma unroll
        for (int i = 0; i < 4; i++) {
            int r0 = wm * 64 + i * 16 + lr;
#pragma unroll
            for (int half = 0; half < 2; half++) {
                int r = r0 + half * 8;
                float s = redS[r * 4] + redS[r * 4 + 1] + redS[r * 4 + 2] + redS[r * 4 + 3];
                float q = redQ[r * 4] + redQ[r * 4 + 1] + redQ[r * 4 + 2] + redQ[r * 4 + 3];
                float mean = s * (1.f / 128.f);
                float var = q * (1.f / 128.f) - mean * mean;
                float rs = rsqrtf(var + 1e-5f);
                float* crow = C + (size_t)(row0 + r) * EDIM + col0;
#pragma unroll
                for (int j = 0; j < 4; j++) {
                    int cl = wn * 32 + j * 8 + lc;
                    float v0 = acc[i][j][half * 2 + 0];
                    float v1 = acc[i][j][half * 2 + 1];
                    float2 ov;
                    ov.x = (v0 - mean) * rs * sp[128 + cl]     + sp[256 + cl];
                    ov.y = (v1 - mean) * rs * sp[128 + cl + 1] + sp[256 + cl + 1];
                    *(float2*)(crow + cl) = ov;
                }
            }
        }
    } else {
#pragma unroll
        for (int i = 0; i < 4; i++) {
#pragma unroll
            for (int half = 0; half < 2; half++) {
                int r = wm * 64 + i * 16 + lr + half * 8;
                float* crow = C + (size_t)(row0 + r) * EDIM + col0;
#pragma unroll
                for (int j = 0; j < 4; j++) {
                    int cl = wn * 32 + j * 8 + lc;
                    float2 ov;
                    ov.x = acc[i][j][half * 2 + 0] + sp[cl];
                    ov.y = acc[i][j][half * 2 + 1] + sp[cl + 1];
                    *(float2*)(crow + cl) = ov;
                }
            }
        }
    }
}

// ---------------------------------------------------------------------------
// Flash-style attention, fp32 — epilogue emits packed 3xbf16 [hi|lo|hi]
// directly into the GEMM activation buffer (stride KP).
// ---------------------------------------------------------------------------
#define ATTN_SMEM_FLOATS (64*132 + 32*132 + 32*132 + 64*33 + 64*16 + 32)
#define ATTN_SMEM_BYTES  (ATTN_SMEM_FLOATS * 4)

__global__ void __launch_bounds__(256, 2) attn_kernel(
    const float* __restrict__ Q, const float* __restrict__ K,
    const float* __restrict__ V, const int* __restrict__ mask,
    __nv_bfloat16* __restrict__ OB, int M)
{
    extern __shared__ float sm[];
    float* Qs = sm;                       // 64 x 132
    float* Ks = Qs + 64 * 132;            // 32 x 132
    float* Vs = Ks + 32 * 132;            // 32 x 132
    float* Ps = Vs + 32 * 132;            // 64 x 33
    float* red = Ps + 64 * 33;            // 64 x 16
    int* smask = (int*)(red + 64 * 16);   // 32

    const int tid = threadIdx.x;
    const int tx = tid & 15, ty = tid >> 4;
    const int qrow0 = blockIdx.x * 64;
    const int h = blockIdx.y;
    const int b = blockIdx.z;
    const size_t baseQ = ((size_t)b * M + qrow0) * EDIM + h * DHEAD;
    const size_t baseK = ((size_t)b * M) * EDIM + h * DHEAD;

#pragma unroll
    for (int l = 0; l < 8; l++) {
        int f = tid + l * 256;
        int m = f >> 5;
        int c = (f & 31) << 2;
        *(float4*)&Qs[m * 132 + c] = *(const float4*)&Q[baseQ + (size_t)m * EDIM + c];
    }

    float o[4][8];
    float mi[4], li[4];
#pragma unroll
    for (int i = 0; i < 4; i++) {
        mi[i] = -1e30f; li[i] = 0.f;
#pragma unroll
        for (int j = 0; j < 8; j++) o[i][j] = 0.f;
    }
    const float scaling = 0.08838834764831845f;  // 128^-0.5

    for (int kt = 0; kt < M; kt += 32) {
#pragma unroll
        for (int l = 0; l < 4; l++) {
            int f = tid + l * 256;
            int m = f >> 5;
            int c = (f & 31) << 2;
            size_t g = baseK + (size_t)(kt + m) * EDIM + c;
            *(float4*)&Ks[m * 132 + c] = *(const float4*)&K[g];
            *(float4*)&Vs[m * 132 + c] = *(const float4*)&V[g];
        }
        if (tid < 32) smask[tid] = mask[(size_t)b * M + kt + tid];
        __syncthreads();

        float s[4][2] = {{0.f, 0.f}, {0.f, 0.f}, {0.f, 0.f}, {0.f, 0.f}};
#pragma unroll
        for (int d = 0; d < DHEAD; d += 4) {
            float4 qv[4], kv[2];
#pragma unroll
            for (int i = 0; i < 4; i++) qv[i] = *(const float4*)&Qs[(ty * 4 + i) * 132 + d];
#pragma unroll
            for (int j = 0; j < 2; j++) kv[j] = *(const float4*)&Ks[(tx * 2 + j) * 132 + d];
#pragma unroll
            for (int i = 0; i < 4; i++)
#pragma unroll
                for (int j = 0; j < 2; j++)
                    s[i][j] += qv[i].x * kv[j].x + qv[i].y * kv[j].y
                             + qv[i].z * kv[j].z + qv[i].w * kv[j].w;
        }
#pragma unroll
        for (int i = 0; i < 4; i++)
#pragma unroll
            for (int j = 0; j < 2; j++) {
                s[i][j] *= scaling;
                if (smask[tx * 2 + j] == 0) s[i][j] = -1e9f;
            }

#pragma unroll
        for (int i = 0; i < 4; i++)
            red[(ty * 4 + i) * 16 + tx] = fmaxf(s[i][0], s[i][1]);
        __syncthreads();
        float alpha[4];
#pragma unroll
        for (int i = 0; i < 4; i++) {
            int r = ty * 4 + i;
            float tm = -1e30f;
#pragma unroll
            for (int t = 0; t < 16; t++) tm = fmaxf(tm, red[r * 16 + t]);
            float mn = fmaxf(mi[i], tm);
            alpha[i] = __expf(mi[i] - mn);
            mi[i] = mn;
        }
        __syncthreads();

#pragma unroll
        for (int i = 0; i < 4; i++) {
            int r = ty * 4 + i;
            float ps = 0.f;
#pragma unroll
            for (int j = 0; j < 2; j++) {
                float p = __expf(s[i][j] - mi[i]);
                Ps[r * 33 + tx * 2 + j] = p;
                ps += p;
            }
            red[r * 16 + tx] = ps;
        }
        __syncthreads();
#pragma unroll
        for (int i = 0; i < 4; i++) {
            int r = ty * 4 + i;
            float ts = 0.f;
#pragma unroll
            for (int t = 0; t < 16; t++) ts += red[r * 16 + t];
            li[i] = li[i] * alpha[i] + ts;
#pragma unroll
            for (int j = 0; j < 8; j++) o[i][j] *= alpha[i];
        }

#pragma unroll 8
        for (int kk = 0; kk < 32; kk++) {
            float pa[4];
#pragma unroll
            for (int i = 0; i < 4; i++) pa[i] = Ps[(ty * 4 + i) * 33 + kk];
            float4 v0 = *(const float4*)&Vs[kk * 132 + tx * 8];
            float4 v1 = *(const float4*)&Vs[kk * 132 + tx * 8 + 4];
#pragma unroll
            for (int i = 0; i < 4; i++) {
                o[i][0] += pa[i] * v0.x; o[i][1] += pa[i] * v0.y;
                o[i][2] += pa[i] * v0.z; o[i][3] += pa[i] * v0.w;
                o[i][4] += pa[i] * v1.x; o[i][5] += pa[i] * v1.y;
                o[i][6] += pa[i] * v1.z; o[i][7] += pa[i] * v1.w;
            }
        }
        __syncthreads();
    }

    // epilogue: O / l, emit packed 3xbf16 [hi | lo | hi] rows (stride KP)
#pragma unroll
    for (int i = 0; i < 4; i++) {
        int r = ty * 4 + i;
        float inv = 1.0f / li[i];
        size_t rowoff = ((size_t)b * M + qrow0 + r) * KP;
        int cb = h * DHEAD + tx * 8;
#pragma unroll
        for (int jj = 0; jj < 8; jj += 2) {
            float a0 = o[i][jj] * inv, a1 = o[i][jj + 1] * inv;
            __nv_bfloat16 h0 = __float2bfloat16(a0);
            __nv_bfloat16 h1 = __float2bfloat16(a1);
            __nv_bfloat16 l0 = __float2bfloat16(a0 - __bfloat162float(h0));
            __nv_bfloat16 l1 = __float2bfloat16(a1 - __bfloat162float(h1));
            __nv_bfloat162 hp, lp;
            hp.x = h0; hp.y = h1; lp.x = l0; lp.y = l1;
            *(__nv_bfloat162*)&OB[rowoff + cb + jj] = hp;
            *(__nv_bfloat162*)&OB[rowoff + 1024 + cb + jj] = lp;
            *(__nv_bfloat162*)&OB[rowoff + 2048 + cb + jj] = hp;
        }
    }
}

// ---------------------------------------------------------------------------
// Launch sequence (single stream, graph-capturable: kernel launches only)
// ---------------------------------------------------------------------------
extern "C" void kernel_launch(void* const* d_in, const int* in_sizes, int n_in,
                              void* d_out, int out_size)
{
    const float* query  = (const float*)d_in[0];
    const float* key    = (const float*)d_in[1];
    const int*   mask   = (const int*)d_in[2];
    // d_in[3] = value1, intentionally unused (matches reference)
    const float* value2 = (const float*)d_in[4];
    const float* Wq = (const float*)d_in[5];
    const float* bq = (const float*)d_in[6];
    const float* gq = (const float*)d_in[7];
    const float* betaq = (const float*)d_in[8];
    const float* Wk = (const float*)d_in[9];
    const float* bk = (const float*)d_in[10];
    const float* gk = (const float*)d_in[11];
    const float* betak = (const float*)d_in[12];
    const float* Wv = (const float*)d_in[13];
    const float* bv = (const float*)d_in[14];
    const float* gv = (const float*)d_in[15];
    const float* betav = (const float*)d_in[16];
    const float* Wm = (const float*)d_in[17];
    const float* bm = (const float*)d_in[18];

    const int B = in_sizes[3] / EDIM;   // value1 is [B, E]
    const int Ntok = in_sizes[2];       // mask is [B, M]
    const int M = Ntok / B;

    __nv_bfloat16 *abf, *wbf;
    float *qb, *kb, *vb;
    cudaGetSymbolAddress((void**)&abf, g_abf);
    cudaGetSymbolAddress((void**)&wbf, g_wbf);
    cudaGetSymbolAddress((void**)&qb, g_q);
    cudaGetSymbolAddress((void**)&kb, g_k);
    cudaGetSymbolAddress((void**)&vb, g_v);

    cudaFuncSetAttribute(gemm_tc<true>,
                         cudaFuncAttributeMaxDynamicSharedMemorySize, GEMM_SMEM);
    cudaFuncSetAttribute(gemm_tc<false>,
                         cudaFuncAttributeMaxDynamicSharedMemorySize, GEMM_SMEM);
    cudaFuncSetAttribute(attn_kernel,
                         cudaFuncAttributeMaxDynamicSharedMemorySize, ATTN_SMEM_BYTES);

    dim3 blk(256);
    dim3 gg(EDIM / 128, Ntok / 128);

    convert3<false><<<EDIM, 256>>>(Wq, wbf);
    convert3<true><<<Ntok, 256>>>(query, abf);
    gemm_tc<true><<<gg, blk, GEMM_SMEM>>>(abf, wbf, bq, gq, betaq, qb);

    convert3<false><<<EDIM, 256>>>(Wk, wbf);
    convert3<true><<<Ntok, 256>>>(key, abf);
    gemm_tc<true><<<gg, blk, GEMM_SMEM>>>(abf, wbf, bk, gk, betak, kb);

    convert3<false><<<EDIM, 256>>>(Wv, wbf);
    convert3<true><<<Ntok, 256>>>(value2, abf);
    gemm_tc<true><<<gg, blk, GEMM_SMEM>>>(abf, wbf, bv, gv, betav, vb);

    dim3 ga(M / 64, HEADS, B);
    attn_kernel<<<ga, blk, ATTN_SMEM_BYTES>>>(qb, kb, vb, mask, abf, M);

    convert3<false><<<EDIM, 256>>>(Wm, wbf);
    gemm_tc<false><<<gg, blk, GEMM_SMEM>>>(abf, wbf, bm, nullptr, nullptr,
                                           (float*)d_out);
}

// round 4
// speedup vs baseline: 3.2437x; 2.0585x over previous
#include <cuda_runtime.h>
#include <cuda_bf16.h>
#include <cstdint>

// Problem constants (fixed by dataset): B=32, M=1024, E=1024, H=8, D=128
#define EDIM 1024
#define HEADS 8
#define DHEAD 128
#define MAXTOK 32768
#define KP 3072          // packed K for 3xbf16 split (GEMMs)
#define NCH 48           // KP / 64 k-chunks

// Scratch (__device__ globals: allocation-free rule)
__device__ __nv_bfloat16 g_abf[(size_t)MAXTOK * KP];   // packed activations
__device__ __nv_bfloat16 g_wbf[(size_t)EDIM * KP];     // packed weights
__device__ __nv_bfloat16 g_qp[(size_t)MAXTOK * 3072];  // Q packed [qh|ql|qh]/head
__device__ __nv_bfloat16 g_kp[(size_t)MAXTOK * 3072];  // K packed [kh|kh|kl]/head
__device__ __nv_bfloat16 g_vp[(size_t)MAXTOK * 2048];  // V packed [vh|vl]/head

// ---------------------------------------------------------------------------
// helpers (baseline PTX only: works on non-'a' sm_103 target)
// ---------------------------------------------------------------------------
__device__ __forceinline__ uint32_t s2u(const void* p) {
    uint32_t a;
    asm("{ .reg .u64 t; cvta.to.shared.u64 t, %1; cvt.u32.u64 %0, t; }"
        : "=r"(a) : "l"(p));
    return a;
}
__device__ __forceinline__ void ldsm_x4(uint32_t* r, uint32_t addr) {
    asm volatile("ldmatrix.sync.aligned.m8n8.x4.shared.b16 {%0,%1,%2,%3}, [%4];"
        : "=r"(r[0]), "=r"(r[1]), "=r"(r[2]), "=r"(r[3]) : "r"(addr));
}
__device__ __forceinline__ void ldsm_x4_t(uint32_t* r, uint32_t addr) {
    asm volatile("ldmatrix.sync.aligned.m8n8.x4.trans.shared.b16 {%0,%1,%2,%3}, [%4];"
        : "=r"(r[0]), "=r"(r[1]), "=r"(r[2]), "=r"(r[3]) : "r"(addr));
}
__device__ __forceinline__ void mma16816(float* d, const uint32_t* a,
                                         const uint32_t* b) {
    asm volatile("mma.sync.aligned.m16n8k16.row.col.f32.bf16.bf16.f32 "
        "{%0,%1,%2,%3}, {%4,%5,%6,%7}, {%8,%9}, {%0,%1,%2,%3};"
        : "+f"(d[0]), "+f"(d[1]), "+f"(d[2]), "+f"(d[3])
        : "r"(a[0]), "r"(a[1]), "r"(a[2]), "r"(a[3]), "r"(b[0]), "r"(b[1]));
}
__device__ __forceinline__ void cpasync16(uint32_t dst, const void* src) {
    asm volatile("cp.async.cg.shared.global [%0], [%1], 16;"
                 :: "r"(dst), "l"(src) : "memory");
}
__device__ __forceinline__ uint32_t packbf2(__nv_bfloat16 lo, __nv_bfloat16 hi) {
    __nv_bfloat162 t; t.x = lo; t.y = hi;
    return *reinterpret_cast<uint32_t*>(&t);
}
__device__ __forceinline__ uint32_t swz(uint32_t off) {
    return off ^ ((off >> 3) & 0x70);
}

// ---------------------------------------------------------------------------
// fp32 -> packed 3xbf16.  ISA(true): [hi | lo | hi]  (activations)
//                         ISA(false): [hi | hi | lo] (weights)
// ---------------------------------------------------------------------------
template <bool ISA>
__global__ void convert3(const float* __restrict__ in,
                         __nv_bfloat16* __restrict__ out) {
    size_t i = ((size_t)blockIdx.x * 256 + threadIdx.x) * 4;
    float4 v = *(const float4*)(in + i);
    size_t r = i >> 10;
    int c = (int)(i & 1023);
    float f[4] = {v.x, v.y, v.z, v.w};
    __nv_bfloat16 h[4], l[4];
#pragma unroll
    for (int j = 0; j < 4; j++) {
        h[j] = __float2bfloat16(f[j]);
        l[j] = __float2bfloat16(f[j] - __bfloat162float(h[j]));
    }
    __nv_bfloat162 h01, h23, l01, l23;
    h01.x = h[0]; h01.y = h[1]; h23.x = h[2]; h23.y = h[3];
    l01.x = l[0]; l01.y = l[1]; l23.x = l[2]; l23.y = l[3];
    __nv_bfloat16* row = out + r * KP;
    *(__nv_bfloat162*)(row + c)            = h01;
    *(__nv_bfloat162*)(row + c + 2)        = h23;
    *(__nv_bfloat162*)(row + 1024 + c)     = ISA ? l01 : h01;
    *(__nv_bfloat162*)(row + 1024 + c + 2) = ISA ? l23 : h23;
    *(__nv_bfloat162*)(row + 2048 + c)     = ISA ? h01 : l01;
    *(__nv_bfloat162*)(row + 2048 + c + 2) = ISA ? h23 : l23;
}

// ---------------------------------------------------------------------------
// HMMA GEMM: CTA 128x128, BK=64, 3-stage cp.async, 256 thr, K'=3072 (3x split)
// Epilogue MODE: 0 = +bias -> fp32 out (final projection)
//               1 = +bias+CELU+GN -> packed Q [hi|lo|hi] per head (384 stride)
//               2 = same -> packed K [hi|hi|lo]
//               3 = same -> packed V [hi|lo] (256 stride)
// ---------------------------------------------------------------------------
#define STAGE_BYTES 32768
#define GEMM_SMEM (3 * STAGE_BYTES + 2048)

template <int MODE>
__global__ void __launch_bounds__(256, 2) gemm_tc(
    const __nv_bfloat16* __restrict__ A, const __nv_bfloat16* __restrict__ W,
    const float* __restrict__ bias, const float* __restrict__ gamma,
    const float* __restrict__ beta, void* __restrict__ out)
{
    constexpr bool GN = (MODE >= 1);
    extern __shared__ char dsm[];
    const uint32_t sb = s2u(dsm);
    const int tid = threadIdx.x;
    const int lane = tid & 31;
    const int wrp = tid >> 5;
    const int wm = wrp & 1;
    const int wn = wrp >> 1;
    const int row0 = blockIdx.y << 7;
    const int col0 = blockIdx.x << 7;

    float* sp = (float*)(dsm + 3 * STAGE_BYTES);
    if (tid < 128) {
        sp[tid] = bias[col0 + tid];
        if (GN) {
            sp[128 + tid] = gamma[col0 + tid];
            sp[256 + tid] = beta[col0 + tid];
        }
    }

    const int gr = tid >> 3;
    const int q16 = (tid & 7) << 4;
    const char* Agp = (const char*)(A + (size_t)row0 * KP) + q16;
    const char* Bgp = (const char*)(W + (size_t)col0 * KP) + q16;
    const size_t rstride = (size_t)KP * 2;

    auto load_stage = [&](int c, int s) {
        uint32_t Ab = sb + s * STAGE_BYTES;
        uint32_t Bb = Ab + 16384;
#pragma unroll
        for (int l = 0; l < 4; l++) {
            int r = gr + (l << 5);
            uint32_t sw = swz((r << 7) + q16);
            cpasync16(Ab + sw, Agp + (size_t)r * rstride + (size_t)c * 128);
            cpasync16(Bb + sw, Bgp + (size_t)r * rstride + (size_t)c * 128);
        }
        asm volatile("cp.async.commit_group;" ::: "memory");
    };

    load_stage(0, 0);
    load_stage(1, 1);

    uint32_t abase[4];
#pragma unroll
    for (int i = 0; i < 4; i++) {
        int row = wm * 64 + i * 16 + (lane & 15);
        abase[i] = (row << 7) + ((lane >> 4) << 4);
    }
    uint32_t bbase[2];
#pragma unroll
    for (int j2 = 0; j2 < 2; j2++) {
        int row = wn * 32 + j2 * 16 + (lane & 7) + ((lane >> 4) << 3);
        bbase[j2] = (row << 7) + (((lane >> 3) & 1) << 4);
    }

    float acc[4][4][4];
#pragma unroll
    for (int i = 0; i < 4; i++)
#pragma unroll
        for (int j = 0; j < 4; j++)
#pragma unroll
            for (int t = 0; t < 4; t++) acc[i][j][t] = 0.f;

    for (int c = 0; c < NCH; c++) {
        if (c < NCH - 2) asm volatile("cp.async.wait_group 1;" ::: "memory");
        else             asm volatile("cp.async.wait_group 0;" ::: "memory");
        __syncthreads();
        if (c + 2 < NCH) load_stage(c + 2, (c + 2) % 3);

        const uint32_t Ab = sb + (c % 3) * STAGE_BYTES;
        const uint32_t Bb = Ab + 16384;
#pragma unroll
        for (int ks = 0; ks < 4; ks++) {
            const int kb = ks << 5;
            uint32_t a[4][4], b[2][4];
#pragma unroll
            for (int i = 0; i < 4; i++)
                ldsm_x4(a[i], Ab + swz(abase[i] + kb));
#pragma unroll
            for (int j2 = 0; j2 < 2; j2++)
                ldsm_x4(b[j2], Bb + swz(bbase[j2] + kb));
#pragma unroll
            for (int i = 0; i < 4; i++)
#pragma unroll
                for (int j2 = 0; j2 < 2; j2++) {
                    mma16816(acc[i][j2 * 2 + 0], a[i], &b[j2][0]);
                    mma16816(acc[i][j2 * 2 + 1], a[i], &b[j2][2]);
                }
        }
        __syncthreads();
    }

    // ---------------- epilogue ----------------
    const int lr = lane >> 2;
    const int lc = (lane & 3) << 1;
    const int hd = col0 >> 7;   // head index for packed modes

    if (GN) {
        float* redS = (float*)dsm;
        float* redQ = redS + 512;
#pragma unroll
        for (int i = 0; i < 4; i++) {
            float s0 = 0.f, q0 = 0.f, s1 = 0.f, q1 = 0.f;
#pragma unroll
            for (int j = 0; j < 4; j++) {
                int cl = wn * 32 + j * 8 + lc;
#pragma unroll
                for (int t = 0; t < 4; t++) {
                    float v = acc[i][j][t] + sp[cl + (t & 1)];
                    v = v > 0.f ? v : 1.3f * expm1f(v * (1.0f / 1.3f));
                    acc[i][j][t] = v;
                    if (t < 2) { s0 += v; q0 += v * v; }
                    else       { s1 += v; q1 += v * v; }
                }
            }
#pragma unroll
            for (int o = 1; o < 4; o <<= 1) {
                s0 += __shfl_xor_sync(0xFFFFFFFFu, s0, o);
                q0 += __shfl_xor_sync(0xFFFFFFFFu, q0, o);
                s1 += __shfl_xor_sync(0xFFFFFFFFu, s1, o);
                q1 += __shfl_xor_sync(0xFFFFFFFFu, q1, o);
            }
            if ((lane & 3) == 0) {
                int r = wm * 64 + i * 16 + lr;
                redS[r * 4 + wn] = s0;  redQ[r * 4 + wn] = q0;
                redS[(r + 8) * 4 + wn] = s1;  redQ[(r + 8) * 4 + wn] = q1;
            }
        }
        __syncthreads();
        __nv_bfloat16* ob = (__nv_bfloat16*)out;
#pragma unroll
        for (int i = 0; i < 4; i++) {
            int rbase = wm * 64 + i * 16 + lr;
#pragma unroll
            for (int half = 0; half < 2; half++) {
                int r = rbase + half * 8;
                float s = redS[r * 4] + redS[r * 4 + 1] + redS[r * 4 + 2] + redS[r * 4 + 3];
                float q = redQ[r * 4] + redQ[r * 4 + 1] + redQ[r * 4 + 2] + redQ[r * 4 + 3];
                float mean = s * (1.f / 128.f);
                float var = q * (1.f / 128.f) - mean * mean;
                float rs = rsqrtf(var + 1e-5f);
                int token = row0 + r;
#pragma unroll
                for (int j = 0; j < 4; j++) {
                    int cl = wn * 32 + j * 8 + lc;
                    float v0 = (acc[i][j][half * 2 + 0] - mean) * rs * sp[128 + cl]
                             + sp[256 + cl];
                    float v1 = (acc[i][j][half * 2 + 1] - mean) * rs * sp[128 + cl + 1]
                             + sp[256 + cl + 1];
                    __nv_bfloat16 h0 = __float2bfloat16(v0);
                    __nv_bfloat16 h1 = __float2bfloat16(v1);
                    __nv_bfloat16 l0 = __float2bfloat16(v0 - __bfloat162float(h0));
                    __nv_bfloat16 l1 = __float2bfloat16(v1 - __bfloat162float(h1));
                    uint32_t uh = packbf2(h0, h1), ul = packbf2(l0, l1);
                    if (MODE == 1) {
                        size_t base = (size_t)token * 3072 + hd * 384 + cl;
                        *(uint32_t*)(ob + base)       = uh;
                        *(uint32_t*)(ob + base + 128) = ul;
                        *(uint32_t*)(ob + base + 256) = uh;
                    } else if (MODE == 2) {
                        size_t base = (size_t)token * 3072 + hd * 384 + cl;
                        *(uint32_t*)(ob + base)       = uh;
                        *(uint32_t*)(ob + base + 128) = uh;
                        *(uint32_t*)(ob + base + 256) = ul;
                    } else {
                        size_t base = (size_t)token * 2048 + hd * 256 + cl;
                        *(uint32_t*)(ob + base)       = uh;
                        *(uint32_t*)(ob + base + 128) = ul;
                    }
                }
            }
        }
    } else {
        float* C = (float*)out;
#pragma unroll
        for (int i = 0; i < 4; i++) {
#pragma unroll
            for (int half = 0; half < 2; half++) {
                int r = wm * 64 + i * 16 + lr + half * 8;
                float* crow = C + (size_t)(row0 + r) * EDIM + col0;
#pragma unroll
                for (int j = 0; j < 4; j++) {
                    int cl = wn * 32 + j * 8 + lc;
                    float2 ov;
                    ov.x = acc[i][j][half * 2 + 0] + sp[cl];
                    ov.y = acc[i][j][half * 2 + 1] + sp[cl + 1];
                    *(float2*)(crow + cl) = ov;
                }
            }
        }
    }
}

// ---------------------------------------------------------------------------
// Tensor-core flash attention (split-bf16 precision).
// CTA = 128 q-rows x one (b,h). 8 warps x 16 rows. 32-key chunks, 3 stages.
// S: Q'[128x384] . K'tile[32x384]^T via mma (split baked into packing).
// PV: 3 passes ph.Vh + pl.Vh + ph.Vl, A-frags packed from S fragments.
// ---------------------------------------------------------------------------
#define AT_Q   0
#define AT_K   98304                    // 3 stages x 24576 (6 subtiles 32x128B)
#define AT_V   (98304 + 73728)          // 3 stages x 16384 (4 subtiles 32x128B)
#define AT_MK  (AT_V + 49152)           // 3 x 128B mask
#define AT_SMEM (AT_MK + 384)

__global__ void __launch_bounds__(256, 1) attn_tc(
    const __nv_bfloat16* __restrict__ Qp, const __nv_bfloat16* __restrict__ Kp,
    const __nv_bfloat16* __restrict__ Vp, const int* __restrict__ mask,
    __nv_bfloat16* __restrict__ OB, int M)
{
    extern __shared__ char dsm[];
    const uint32_t sb = s2u(dsm);
    const int tid = threadIdx.x;
    const int lane = tid & 31;
    const int wrp = tid >> 5;
    const int qrow0 = blockIdx.x * 128;
    const int hd = blockIdx.y;
    const int b = blockIdx.z;

    const char* qg = (const char*)Qp + ((size_t)(b * M + qrow0) * 3072 + hd * 384) * 2;
    const char* kg = (const char*)Kp + ((size_t)b * M * 3072 + hd * 384) * 2;
    const char* vg = (const char*)Vp + ((size_t)b * M * 2048 + hd * 256) * 2;

    // Q' resident load: 128 rows x 768B = 6144 granules
#pragma unroll
    for (int l = 0; l < 24; l++) {
        int gi = tid + 256 * l;
        int row = gi / 48, q = gi % 48;
        uint32_t off = (q / 8) * 16384 + row * 128 + (q % 8) * 16;
        cpasync16(sb + AT_Q + swz(off), qg + (size_t)row * 6144 + q * 16);
    }

    auto load_stage = [&](int c, int s) {
        uint32_t kb = sb + AT_K + s * 24576;
#pragma unroll
        for (int l = 0; l < 6; l++) {
            int gi = tid + 256 * l;
            int row = gi / 48, q = gi % 48;
            uint32_t off = (q / 8) * 4096 + row * 128 + (q % 8) * 16;
            cpasync16(kb + swz(off), kg + (size_t)(c * 32 + row) * 6144 + q * 16);
        }
        uint32_t vb = sb + AT_V + s * 16384;
#pragma unroll
        for (int l = 0; l < 4; l++) {
            int gi = tid + 256 * l;
            int row = gi / 32, q = gi % 32;
            uint32_t off = (q / 8) * 4096 + row * 128 + (q % 8) * 16;
            cpasync16(vb + swz(off), vg + (size_t)(c * 32 + row) * 4096 + q * 16);
        }
        if (tid < 8)
            cpasync16(sb + AT_MK + s * 128 + tid * 16,
                      (const char*)(mask + (size_t)b * M + c * 32) + tid * 16);
        asm volatile("cp.async.commit_group;" ::: "memory");
    };

    load_stage(0, 0);
    load_stage(1, 1);

    // fragment geometry
    const uint32_t aoff = (wrp * 16 + (lane & 15)) * 128 + ((lane >> 4) << 4);
    uint32_t boff[2];
#pragma unroll
    for (int hf = 0; hf < 2; hf++)
        boff[hf] = (hf * 16 + (lane & 7) + ((lane >> 4) << 3)) * 128
                 + (((lane >> 3) & 1) << 4);
    const uint32_t vrow = ((lane & 7) + (((lane >> 3) & 1) << 3)) * 128;
    const uint32_t vcol = ((lane >> 4) << 4);

    float O[16][4];
#pragma unroll
    for (int j = 0; j < 16; j++)
#pragma unroll
        for (int t = 0; t < 4; t++) O[j][t] = 0.f;
    float mi[2] = {-1e30f, -1e30f}, li[2] = {0.f, 0.f};
    const float scaling = 0.08838834764831845f;

    const int NCHA = M / 32;
    for (int c = 0; c < NCHA; c++) {
        if (c < NCHA - 2) asm volatile("cp.async.wait_group 1;" ::: "memory");
        else              asm volatile("cp.async.wait_group 0;" ::: "memory");
        __syncthreads();
        if (c + 2 < NCHA) load_stage(c + 2, (c + 2) % 3);

        const uint32_t Kb = sb + AT_K + (c % 3) * 24576;
        const uint32_t Vb = sb + AT_V + (c % 3) * 16384;
        const int* mk = (const int*)(dsm + AT_MK + (c % 3) * 128);

        // ---- S = Q' . K'tile^T  (K' = 384 packed: hh + lh + hl) ----
        float cS[4][4];
#pragma unroll
        for (int t = 0; t < 4; t++)
#pragma unroll
            for (int u = 0; u < 4; u++) cS[t][u] = 0.f;
#pragma unroll
        for (int kc = 0; kc < 6; kc++) {
#pragma unroll
            for (int ks = 0; ks < 4; ks++) {
                uint32_t a[4], bb[2][4];
                ldsm_x4(a, sb + AT_Q + swz(kc * 16384 + aoff + ks * 32));
#pragma unroll
                for (int hf = 0; hf < 2; hf++)
                    ldsm_x4(bb[hf], Kb + swz(kc * 4096 + boff[hf] + ks * 32));
#pragma unroll
                for (int hf = 0; hf < 2; hf++) {
                    mma16816(cS[hf * 2 + 0], a, &bb[hf][0]);
                    mma16816(cS[hf * 2 + 1], a, &bb[hf][2]);
                }
            }
        }

        // ---- softmax (warp-local rows) ----
#pragma unroll
        for (int t = 0; t < 4; t++) {
            int2 mv = *(const int2*)&mk[t * 8 + ((lane & 3) << 1)];
#pragma unroll
            for (int u = 0; u < 4; u++) {
                float s = cS[t][u] * scaling;
                int mkv = (u & 1) ? mv.y : mv.x;
                cS[t][u] = (mkv == 0) ? -1e9f : s;
            }
        }
        float tmax0 = -1e30f, tmax1 = -1e30f;
#pragma unroll
        for (int t = 0; t < 4; t++) {
            tmax0 = fmaxf(tmax0, fmaxf(cS[t][0], cS[t][1]));
            tmax1 = fmaxf(tmax1, fmaxf(cS[t][2], cS[t][3]));
        }
#pragma unroll
        for (int o = 1; o < 4; o <<= 1) {
            tmax0 = fmaxf(tmax0, __shfl_xor_sync(0xFFFFFFFFu, tmax0, o));
            tmax1 = fmaxf(tmax1, __shfl_xor_sync(0xFFFFFFFFu, tmax1, o));
        }
        float mn0 = fmaxf(mi[0], tmax0), mn1 = fmaxf(mi[1], tmax1);
        float al0 = __expf(mi[0] - mn0), al1 = __expf(mi[1] - mn1);
        mi[0] = mn0; mi[1] = mn1;

        float ps0 = 0.f, ps1 = 0.f;
#pragma unroll
        for (int t = 0; t < 4; t++) {
            cS[t][0] = __expf(cS[t][0] - mn0);
            cS[t][1] = __expf(cS[t][1] - mn0);
            cS[t][2] = __expf(cS[t][2] - mn1);
            cS[t][3] = __expf(cS[t][3] - mn1);
            ps0 += cS[t][0] + cS[t][1];
            ps1 += cS[t][2] + cS[t][3];
        }
#pragma unroll
        for (int o = 1; o < 4; o <<= 1) {
            ps0 += __shfl_xor_sync(0xFFFFFFFFu, ps0, o);
            ps1 += __shfl_xor_sync(0xFFFFFFFFu, ps1, o);
        }
        li[0] = li[0] * al0 + ps0;
        li[1] = li[1] * al1 + ps1;
#pragma unroll
        for (int j = 0; j < 16; j++) {
            O[j][0] *= al0; O[j][1] *= al0;
            O[j][2] *= al1; O[j][3] *= al1;
        }

        // pack P into A fragments: ahh (hi), alo (residual)
        uint32_t ahh[2][4], alo[2][4];
#pragma unroll
        for (int ks = 0; ks < 2; ks++) {
#pragma unroll
            for (int sub = 0; sub < 2; sub++) {   // sub: tile 2ks / 2ks+1
                int t = 2 * ks + sub;
                __nv_bfloat16 h01a = __float2bfloat16(cS[t][0]);
                __nv_bfloat16 h01b = __float2bfloat16(cS[t][1]);
                __nv_bfloat16 h23a = __float2bfloat16(cS[t][2]);
                __nv_bfloat16 h23b = __float2bfloat16(cS[t][3]);
                ahh[ks][sub * 2 + 0] = packbf2(h01a, h01b);
                ahh[ks][sub * 2 + 1] = packbf2(h23a, h23b);
                alo[ks][sub * 2 + 0] = packbf2(
                    __float2bfloat16(cS[t][0] - __bfloat162float(h01a)),
                    __float2bfloat16(cS[t][1] - __bfloat162float(h01b)));
                alo[ks][sub * 2 + 1] = packbf2(
                    __float2bfloat16(cS[t][2] - __bfloat162float(h23a)),
                    __float2bfloat16(cS[t][3] - __bfloat162float(h23b)));
            }
        }
        // fix fragment order: a[0],a[1] = rows r,r+8 of k-lo tile; a[2],a[3] = k-hi tile
        // (packbf2 above already produced: [ks][0]=t0 rows r, [1]=t0 rows r+8,
        //  [2]=t1 rows r, [3]=t1 rows r+8 — matches a0,a1,a2,a3 layout)

        // ---- O += P . V  (3 passes: hh, lh, hl) ----
#pragma unroll
        for (int g = 0; g < 8; g++) {
            const int vch = g >> 2;
            const uint32_t colb = (g & 3) * 32 + vcol;
#pragma unroll
            for (int ks = 0; ks < 2; ks++) {
                uint32_t bv[4];
                uint32_t ro = (uint32_t)(ks * 16) * 128 + vrow;
                ldsm_x4_t(bv, Vb + swz(vch * 4096 + ro + colb));
                mma16816(O[2 * g + 0], ahh[ks], &bv[0]);
                mma16816(O[2 * g + 1], ahh[ks], &bv[2]);
                mma16816(O[2 * g + 0], alo[ks], &bv[0]);
                mma16816(O[2 * g + 1], alo[ks], &bv[2]);
                ldsm_x4_t(bv, Vb + swz((vch + 2) * 4096 + ro + colb));
                mma16816(O[2 * g + 0], ahh[ks], &bv[0]);
                mma16816(O[2 * g + 1], ahh[ks], &bv[2]);
            }
        }
    }

    // ---- epilogue: O / l, emit packed [hi|lo|hi] rows into OB (stride 3072) ----
    float inv0 = 1.0f / li[0], inv1 = 1.0f / li[1];
#pragma unroll
    for (int half = 0; half < 2; half++) {
        float inv = half ? inv1 : inv0;
        int token = b * M + qrow0 + wrp * 16 + (lane >> 2) + half * 8;
        size_t rowbase = (size_t)token * 3072 + hd * 128 + ((lane & 3) << 1);
#pragma unroll
        for (int j = 0; j < 16; j++) {
            float v0 = O[j][half * 2 + 0] * inv;
            float v1 = O[j][half * 2 + 1] * inv;
            __nv_bfloat16 h0 = __float2bfloat16(v0);
            __nv_bfloat16 h1 = __float2bfloat16(v1);
            __nv_bfloat16 l0 = __float2bfloat16(v0 - __bfloat162float(h0));
            __nv_bfloat16 l1 = __float2bfloat16(v1 - __bfloat162float(h1));
            uint32_t uh = packbf2(h0, h1), ul = packbf2(l0, l1);
            size_t base = rowbase + j * 8;
            *(uint32_t*)(OB + base)        = uh;
            *(uint32_t*)(OB + base + 1024) = ul;
            *(uint32_t*)(OB + base + 2048) = uh;
        }
    }
}

// ---------------------------------------------------------------------------
// Launch sequence (single stream, graph-capturable: kernel launches only)
// ---------------------------------------------------------------------------
extern "C" void kernel_launch(void* const* d_in, const int* in_sizes, int n_in,
                              void* d_out, int out_size)
{
    const float* query  = (const float*)d_in[0];
    const float* key    = (const float*)d_in[1];
    const int*   mask   = (const int*)d_in[2];
    // d_in[3] = value1, intentionally unused (matches reference)
    const float* value2 = (const float*)d_in[4];
    const float* Wq = (const float*)d_in[5];
    const float* bq = (const float*)d_in[6];
    const float* gq = (const float*)d_in[7];
    const float* betaq = (const float*)d_in[8];
    const float* Wk = (const float*)d_in[9];
    const float* bk = (const float*)d_in[10];
    const float* gk = (const float*)d_in[11];
    const float* betak = (const float*)d_in[12];
    const float* Wv = (const float*)d_in[13];
    const float* bv = (const float*)d_in[14];
    const float* gv = (const float*)d_in[15];
    const float* betav = (const float*)d_in[16];
    const float* Wm = (const float*)d_in[17];
    const float* bm = (const float*)d_in[18];

    const int B = in_sizes[3] / EDIM;   // value1 is [B, E]
    const int Ntok = in_sizes[2];       // mask is [B, M]
    const int M = Ntok / B;

    __nv_bfloat16 *abf, *wbf, *qp, *kp, *vp;
    cudaGetSymbolAddress((void**)&abf, g_abf);
    cudaGetSymbolAddress((void**)&wbf, g_wbf);
    cudaGetSymbolAddress((void**)&qp, g_qp);
    cudaGetSymbolAddress((void**)&kp, g_kp);
    cudaGetSymbolAddress((void**)&vp, g_vp);

    cudaFuncSetAttribute(gemm_tc<0>, cudaFuncAttributeMaxDynamicSharedMemorySize, GEMM_SMEM);
    cudaFuncSetAttribute(gemm_tc<1>, cudaFuncAttributeMaxDynamicSharedMemorySize, GEMM_SMEM);
    cudaFuncSetAttribute(gemm_tc<2>, cudaFuncAttributeMaxDynamicSharedMemorySize, GEMM_SMEM);
    cudaFuncSetAttribute(gemm_tc<3>, cudaFuncAttributeMaxDynamicSharedMemorySize, GEMM_SMEM);
    cudaFuncSetAttribute(attn_tc, cudaFuncAttributeMaxDynamicSharedMemorySize, AT_SMEM);

    dim3 blk(256);
    dim3 gg(EDIM / 128, Ntok / 128);

    convert3<false><<<EDIM, 256>>>(Wq, wbf);
    convert3<true><<<Ntok, 256>>>(query, abf);
    gemm_tc<1><<<gg, blk, GEMM_SMEM>>>(abf, wbf, bq, gq, betaq, qp);

    convert3<false><<<EDIM, 256>>>(Wk, wbf);
    convert3<true><<<Ntok, 256>>>(key, abf);
    gemm_tc<2><<<gg, blk, GEMM_SMEM>>>(abf, wbf, bk, gk, betak, kp);

    convert3<false><<<EDIM, 256>>>(Wv, wbf);
    convert3<true><<<Ntok, 256>>>(value2, abf);
    gemm_tc<3><<<gg, blk, GEMM_SMEM>>>(abf, wbf, bv, gv, betav, vp);

    dim3 ga(M / 128, HEADS, B);
    attn_tc<<<ga, blk, AT_SMEM>>>(qp, kp, vp, mask, abf, M);

    convert3<false><<<EDIM, 256>>>(Wm, wbf);
    gemm_tc<0><<<gg, blk, GEMM_SMEM>>>(abf, wbf, bm, nullptr, nullptr, d_out);
}

// round 5
// speedup vs baseline: 4.4273x; 1.3649x over previous
#include <cuda_runtime.h>
#include <cuda_bf16.h>
#include <cuda_fp16.h>
#include <cstdint>

// Problem constants (fixed by dataset): B=32, M=1024, E=1024, H=8, D=128
#define EDIM 1024
#define HEADS 8
#define DHEAD 128
#define MAXTOK 32768

// Scratch (__device__ globals: allocation-free rule)
// g_abf doubles as: fp16 [ah|al] activations (proj phase, 128MB)
//                   then bf16 [hi|lo|hi] attn output (final GEMM phase, 192MB)
__device__ __nv_bfloat16 g_abf[(size_t)MAXTOK * 3072];
__device__ __nv_bfloat16 g_wbf[(size_t)EDIM * 3072];   // W packed (fp16 or bf16)
__device__ __half g_qp[(size_t)MAXTOK * 2048];         // Q packed [qh|ql]/head
__device__ __half g_kp[(size_t)MAXTOK * 2048];         // K packed [kh|kh]/head
__device__ __half g_vp[(size_t)MAXTOK * 1024];         // V plain fp16/head

// ---------------------------------------------------------------------------
// helpers (baseline PTX only: works on non-'a' sm_103 target)
// ---------------------------------------------------------------------------
__device__ __forceinline__ uint32_t s2u(const void* p) {
    uint32_t a;
    asm("{ .reg .u64 t; cvta.to.shared.u64 t, %1; cvt.u32.u64 %0, t; }"
        : "=r"(a) : "l"(p));
    return a;
}
__device__ __forceinline__ void ldsm_x4(uint32_t* r, uint32_t addr) {
    asm volatile("ldmatrix.sync.aligned.m8n8.x4.shared.b16 {%0,%1,%2,%3}, [%4];"
        : "=r"(r[0]), "=r"(r[1]), "=r"(r[2]), "=r"(r[3]) : "r"(addr));
}
__device__ __forceinline__ void ldsm_x4_t(uint32_t* r, uint32_t addr) {
    asm volatile("ldmatrix.sync.aligned.m8n8.x4.trans.shared.b16 {%0,%1,%2,%3}, [%4];"
        : "=r"(r[0]), "=r"(r[1]), "=r"(r[2]), "=r"(r[3]) : "r"(addr));
}
__device__ __forceinline__ void mma_bf16(float* d, const uint32_t* a,
                                         const uint32_t* b) {
    asm volatile("mma.sync.aligned.m16n8k16.row.col.f32.bf16.bf16.f32 "
        "{%0,%1,%2,%3}, {%4,%5,%6,%7}, {%8,%9}, {%0,%1,%2,%3};"
        : "+f"(d[0]), "+f"(d[1]), "+f"(d[2]), "+f"(d[3])
        : "r"(a[0]), "r"(a[1]), "r"(a[2]), "r"(a[3]), "r"(b[0]), "r"(b[1]));
}
__device__ __forceinline__ void mma_f16(float* d, const uint32_t* a,
                                        const uint32_t* b) {
    asm volatile("mma.sync.aligned.m16n8k16.row.col.f32.f16.f16.f32 "
        "{%0,%1,%2,%3}, {%4,%5,%6,%7}, {%8,%9}, {%0,%1,%2,%3};"
        : "+f"(d[0]), "+f"(d[1]), "+f"(d[2]), "+f"(d[3])
        : "r"(a[0]), "r"(a[1]), "r"(a[2]), "r"(a[3]), "r"(b[0]), "r"(b[1]));
}
__device__ __forceinline__ void cpasync16(uint32_t dst, const void* src) {
    asm volatile("cp.async.cg.shared.global [%0], [%1], 16;"
                 :: "r"(dst), "l"(src) : "memory");
}
__device__ __forceinline__ uint32_t packbf2(__nv_bfloat16 lo, __nv_bfloat16 hi) {
    __nv_bfloat162 t; t.x = lo; t.y = hi;
    return *reinterpret_cast<uint32_t*>(&t);
}
__device__ __forceinline__ uint32_t packh2(__half lo, __half hi) {
    __half2 t; t.x = lo; t.y = hi;
    return *reinterpret_cast<uint32_t*>(&t);
}
__device__ __forceinline__ uint32_t swz(uint32_t off) {
    return off ^ ((off >> 3) & 0x70);
}

// ---------------------------------------------------------------------------
// fp32 -> fp16 2x pack, row stride 2048.  REP: [hi|hi] (weights) / [hi|lo]
// ---------------------------------------------------------------------------
template <bool REP>
__global__ void convert2h(const float* __restrict__ in,
                          __half* __restrict__ out) {
    size_t i = ((size_t)blockIdx.x * 256 + threadIdx.x) * 4;
    float4 v = *(const float4*)(in + i);
    size_t r = i >> 10;
    int c = (int)(i & 1023);
    float f[4] = {v.x, v.y, v.z, v.w};
    __half h[4], l[4];
#pragma unroll
    for (int j = 0; j < 4; j++) {
        h[j] = __float2half(f[j]);
        l[j] = __float2half(f[j] - __half2float(h[j]));
    }
    __half* row = out + r * 2048;
    *(uint32_t*)(row + c)     = packh2(h[0], h[1]);
    *(uint32_t*)(row + c + 2) = packh2(h[2], h[3]);
    *(uint32_t*)(row + 1024 + c)     = REP ? packh2(h[0], h[1]) : packh2(l[0], l[1]);
    *(uint32_t*)(row + 1024 + c + 2) = REP ? packh2(h[2], h[3]) : packh2(l[2], l[3]);
}

// fp32 -> bf16 3x pack [hi|hi|lo] (final-GEMM weights only), stride 3072
__global__ void convert3w(const float* __restrict__ in,
                          __nv_bfloat16* __restrict__ out) {
    size_t i = ((size_t)blockIdx.x * 256 + threadIdx.x) * 4;
    float4 v = *(const float4*)(in + i);
    size_t r = i >> 10;
    int c = (int)(i & 1023);
    float f[4] = {v.x, v.y, v.z, v.w};
    __nv_bfloat16 h[4], l[4];
#pragma unroll
    for (int j = 0; j < 4; j++) {
        h[j] = __float2bfloat16(f[j]);
        l[j] = __float2bfloat16(f[j] - __bfloat162float(h[j]));
    }
    __nv_bfloat16* row = out + r * 3072;
    *(uint32_t*)(row + c)            = packbf2(h[0], h[1]);
    *(uint32_t*)(row + c + 2)        = packbf2(h[2], h[3]);
    *(uint32_t*)(row + 1024 + c)     = packbf2(h[0], h[1]);
    *(uint32_t*)(row + 1024 + c + 2) = packbf2(h[2], h[3]);
    *(uint32_t*)(row + 2048 + c)     = packbf2(l[0], l[1]);
    *(uint32_t*)(row + 2048 + c + 2) = packbf2(l[2], l[3]);
}

// ---------------------------------------------------------------------------
// HMMA GEMM: CTA 128x128, BK=64 (128B rows), 3-stage cp.async, 256 thr.
// MODE 0: bf16 K'=3072 (3x split), +bias -> fp32 (final projection)
// MODE 1: fp16 K'=2048, +bias+CELU+GN -> Q packed [qh|ql] (256/head)
// MODE 2: same -> K packed [kh|kh]
// MODE 3: same -> V plain fp16 (128/head)
// ---------------------------------------------------------------------------
#define STAGE_BYTES 32768
#define GEMM_SMEM (3 * STAGE_BYTES + 2048)

template <int MODE>
__global__ void __launch_bounds__(256, 2) gemm_tc(
    const void* __restrict__ Av, const void* __restrict__ Wv,
    const float* __restrict__ bias, const float* __restrict__ gamma,
    const float* __restrict__ beta, void* __restrict__ out)
{
    constexpr bool GN = (MODE >= 1);
    constexpr int KEL = GN ? 2048 : 3072;
    constexpr int NCHT = KEL / 64;
    extern __shared__ char dsm[];
    const uint32_t sb = s2u(dsm);
    const int tid = threadIdx.x;
    const int lane = tid & 31;
    const int wrp = tid >> 5;
    const int wm = wrp & 1;
    const int wn = wrp >> 1;
    const int row0 = blockIdx.y << 7;
    const int col0 = blockIdx.x << 7;

    float* sp = (float*)(dsm + 3 * STAGE_BYTES);
    if (tid < 128) {
        sp[tid] = bias[col0 + tid];
        if (GN) {
            sp[128 + tid] = gamma[col0 + tid];
            sp[256 + tid] = beta[col0 + tid];
        }
    }

    const int gr = tid >> 3;
    const int q16 = (tid & 7) << 4;
    const size_t rstride = (size_t)KEL * 2;
    const char* Agp = (const char*)Av + (size_t)row0 * rstride + q16;
    const char* Bgp = (const char*)Wv + (size_t)col0 * rstride + q16;

    auto load_stage = [&](int c, int s) {
        uint32_t Ab = sb + s * STAGE_BYTES;
        uint32_t Bb = Ab + 16384;
#pragma unroll
        for (int l = 0; l < 4; l++) {
            int r = gr + (l << 5);
            uint32_t sw = swz((r << 7) + q16);
            cpasync16(Ab + sw, Agp + (size_t)r * rstride + (size_t)c * 128);
            cpasync16(Bb + sw, Bgp + (size_t)r * rstride + (size_t)c * 128);
        }
        asm volatile("cp.async.commit_group;" ::: "memory");
    };

    load_stage(0, 0);
    load_stage(1, 1);

    uint32_t abase[4];
#pragma unroll
    for (int i = 0; i < 4; i++) {
        int row = wm * 64 + i * 16 + (lane & 15);
        abase[i] = (row << 7) + ((lane >> 4) << 4);
    }
    uint32_t bbase[2];
#pragma unroll
    for (int j2 = 0; j2 < 2; j2++) {
        int row = wn * 32 + j2 * 16 + (lane & 7) + ((lane >> 4) << 3);
        bbase[j2] = (row << 7) + (((lane >> 3) & 1) << 4);
    }

    float acc[4][4][4];
#pragma unroll
    for (int i = 0; i < 4; i++)
#pragma unroll
        for (int j = 0; j < 4; j++)
#pragma unroll
            for (int t = 0; t < 4; t++) acc[i][j][t] = 0.f;

    for (int c = 0; c < NCHT; c++) {
        if (c < NCHT - 2) asm volatile("cp.async.wait_group 1;" ::: "memory");
        else              asm volatile("cp.async.wait_group 0;" ::: "memory");
        __syncthreads();
        if (c + 2 < NCHT) load_stage(c + 2, (c + 2) % 3);

        const uint32_t Ab = sb + (c % 3) * STAGE_BYTES;
        const uint32_t Bb = Ab + 16384;
#pragma unroll
        for (int ks = 0; ks < 4; ks++) {
            const int kb = ks << 5;
            uint32_t a[4][4], b[2][4];
#pragma unroll
            for (int i = 0; i < 4; i++)
                ldsm_x4(a[i], Ab + swz(abase[i] + kb));
#pragma unroll
            for (int j2 = 0; j2 < 2; j2++)
                ldsm_x4(b[j2], Bb + swz(bbase[j2] + kb));
#pragma unroll
            for (int i = 0; i < 4; i++)
#pragma unroll
                for (int j2 = 0; j2 < 2; j2++) {
                    if (GN) {
                        mma_f16(acc[i][j2 * 2 + 0], a[i], &b[j2][0]);
                        mma_f16(acc[i][j2 * 2 + 1], a[i], &b[j2][2]);
                    } else {
                        mma_bf16(acc[i][j2 * 2 + 0], a[i], &b[j2][0]);
                        mma_bf16(acc[i][j2 * 2 + 1], a[i], &b[j2][2]);
                    }
                }
        }
        __syncthreads();
    }

    // ---------------- epilogue ----------------
    const int lr = lane >> 2;
    const int lc = (lane & 3) << 1;
    const int hd = col0 >> 7;   // head index for packed modes

    if (GN) {
        float* redS = (float*)dsm;
        float* redQ = redS + 512;
#pragma unroll
        for (int i = 0; i < 4; i++) {
            float s0 = 0.f, q0 = 0.f, s1 = 0.f, q1 = 0.f;
#pragma unroll
            for (int j = 0; j < 4; j++) {
                int cl = wn * 32 + j * 8 + lc;
#pragma unroll
                for (int t = 0; t < 4; t++) {
                    float v = acc[i][j][t] + sp[cl + (t & 1)];
                    v = v > 0.f ? v : 1.3f * expm1f(v * (1.0f / 1.3f));
                    acc[i][j][t] = v;
                    if (t < 2) { s0 += v; q0 += v * v; }
                    else       { s1 += v; q1 += v * v; }
                }
            }
#pragma unroll
            for (int o = 1; o < 4; o <<= 1) {
                s0 += __shfl_xor_sync(0xFFFFFFFFu, s0, o);
                q0 += __shfl_xor_sync(0xFFFFFFFFu, q0, o);
                s1 += __shfl_xor_sync(0xFFFFFFFFu, s1, o);
                q1 += __shfl_xor_sync(0xFFFFFFFFu, q1, o);
            }
            if ((lane & 3) == 0) {
                int r = wm * 64 + i * 16 + lr;
                redS[r * 4 + wn] = s0;  redQ[r * 4 + wn] = q0;
                redS[(r + 8) * 4 + wn] = s1;  redQ[(r + 8) * 4 + wn] = q1;
            }
        }
        __syncthreads();
        __half* ob = (__half*)out;
#pragma unroll
        for (int i = 0; i < 4; i++) {
            int rbase = wm * 64 + i * 16 + lr;
#pragma unroll
            for (int half_ = 0; half_ < 2; half_++) {
                int r = rbase + half_ * 8;
                float s = redS[r * 4] + redS[r * 4 + 1] + redS[r * 4 + 2] + redS[r * 4 + 3];
                float q = redQ[r * 4] + redQ[r * 4 + 1] + redQ[r * 4 + 2] + redQ[r * 4 + 3];
                float mean = s * (1.f / 128.f);
                float var = q * (1.f / 128.f) - mean * mean;
                float rs = rsqrtf(var + 1e-5f);
                int token = row0 + r;
#pragma unroll
                for (int j = 0; j < 4; j++) {
                    int cl = wn * 32 + j * 8 + lc;
                    float v0 = (acc[i][j][half_ * 2 + 0] - mean) * rs * sp[128 + cl]
                             + sp[256 + cl];
                    float v1 = (acc[i][j][half_ * 2 + 1] - mean) * rs * sp[128 + cl + 1]
                             + sp[256 + cl + 1];
                    __half h0 = __float2half(v0);
                    __half h1 = __float2half(v1);
                    uint32_t uh = packh2(h0, h1);
                    if (MODE == 1) {
                        uint32_t ul = packh2(__float2half(v0 - __half2float(h0)),
                                             __float2half(v1 - __half2float(h1)));
                        size_t base = (size_t)token * 2048 + hd * 256 + cl;
                        *(uint32_t*)(ob + base)       = uh;
                        *(uint32_t*)(ob + base + 128) = ul;
                    } else if (MODE == 2) {
                        size_t base = (size_t)token * 2048 + hd * 256 + cl;
                        *(uint32_t*)(ob + base)       = uh;
                        *(uint32_t*)(ob + base + 128) = uh;
                    } else {
                        size_t base = (size_t)token * 1024 + hd * 128 + cl;
                        *(uint32_t*)(ob + base) = uh;
                    }
                }
            }
        }
    } else {
        float* C = (float*)out;
#pragma unroll
        for (int i = 0; i < 4; i++) {
#pragma unroll
            for (int half_ = 0; half_ < 2; half_++) {
                int r = wm * 64 + i * 16 + lr + half_ * 8;
                float* crow = C + (size_t)(row0 + r) * EDIM + col0;
#pragma unroll
                for (int j = 0; j < 4; j++) {
                    int cl = wn * 32 + j * 8 + lc;
                    float2 ov;
                    ov.x = acc[i][j][half_ * 2 + 0] + sp[cl];
                    ov.y = acc[i][j][half_ * 2 + 1] + sp[cl + 1];
                    *(float2*)(crow + cl) = ov;
                }
            }
        }
    }
}

// ---------------------------------------------------------------------------
// Tensor-core flash attention, fp16 2-pass precision.
// CTA = 128 q-rows x one (b,h). 8 warps x 16 rows. 32-key chunks, 3 stages.
// S: Q'[128x256] . K'tile[32x256]^T  ((qh+ql).kh baked into packing)
// PV: 2 passes (ph + pl) . v,  V plain fp16.
// ---------------------------------------------------------------------------
#define AT_Q   0
#define AT_K   65536                   // 3 stages x 16384 (4 subtiles 32x128B)
#define AT_V   (65536 + 49152)         // 3 stages x 8192  (2 subtiles 32x128B)
#define AT_MK  (AT_V + 24576)          // 3 x 128B mask
#define AT_SMEM (AT_MK + 384)

__global__ void __launch_bounds__(256, 1) attn_tc(
    const __half* __restrict__ Qp, const __half* __restrict__ Kp,
    const __half* __restrict__ Vp, const int* __restrict__ mask,
    __nv_bfloat16* __restrict__ OB, int M)
{
    extern __shared__ char dsm[];
    const uint32_t sb = s2u(dsm);
    const int tid = threadIdx.x;
    const int lane = tid & 31;
    const int wrp = tid >> 5;
    const int qrow0 = blockIdx.x * 128;
    const int hd = blockIdx.y;
    const int b = blockIdx.z;

    const char* qg = (const char*)(Qp + (size_t)(b * M + qrow0) * 2048 + hd * 256);
    const char* kg = (const char*)(Kp + (size_t)b * M * 2048 + hd * 256);
    const char* vg = (const char*)(Vp + (size_t)b * M * 1024 + hd * 128);

    // Q' resident: 128 rows x 512B = 4096 granules
#pragma unroll
    for (int l = 0; l < 16; l++) {
        int gi = tid + 256 * l;
        int row = gi >> 5, q = gi & 31;
        uint32_t off = (q >> 3) * 16384 + row * 128 + (q & 7) * 16;
        cpasync16(sb + AT_Q + swz(off), qg + (size_t)row * 4096 + q * 16);
    }

    auto load_stage = [&](int c, int s) {
        uint32_t kb = sb + AT_K + s * 16384;
#pragma unroll
        for (int l = 0; l < 4; l++) {
            int gi = tid + 256 * l;
            int row = gi >> 5, q = gi & 31;
            uint32_t off = (q >> 3) * 4096 + row * 128 + (q & 7) * 16;
            cpasync16(kb + swz(off), kg + (size_t)(c * 32 + row) * 4096 + q * 16);
        }
        uint32_t vb = sb + AT_V + s * 8192;
#pragma unroll
        for (int l = 0; l < 2; l++) {
            int gi = tid + 256 * l;
            int row = gi >> 4, q = gi & 15;
            uint32_t off = (q >> 3) * 4096 + row * 128 + (q & 7) * 16;
            cpasync16(vb + swz(off), vg + (size_t)(c * 32 + row) * 2048 + q * 16);
        }
        if (tid < 8)
            cpasync16(sb + AT_MK + s * 128 + tid * 16,
                      (const char*)(mask + (size_t)b * M + c * 32) + tid * 16);
        asm volatile("cp.async.commit_group;" ::: "memory");
    };

    load_stage(0, 0);
    load_stage(1, 1);

    const uint32_t aoff = (wrp * 16 + (lane & 15)) * 128 + ((lane >> 4) << 4);
    uint32_t boff[2];
#pragma unroll
    for (int hf = 0; hf < 2; hf++)
        boff[hf] = (hf * 16 + (lane & 7) + ((lane >> 4) << 3)) * 128
                 + (((lane >> 3) & 1) << 4);
    const uint32_t vrow = ((lane & 7) + (((lane >> 3) & 1) << 3)) * 128;
    const uint32_t vcol = ((lane >> 4) << 4);

    float O[16][4];
#pragma unroll
    for (int j = 0; j < 16; j++)
#pragma unroll
        for (int t = 0; t < 4; t++) O[j][t] = 0.f;
    float mi[2] = {-1e30f, -1e30f}, li[2] = {0.f, 0.f};
    const float scaling = 0.08838834764831845f;

    const int NCHA = M / 32;
    for (int c = 0; c < NCHA; c++) {
        if (c < NCHA - 2) asm volatile("cp.async.wait_group 1;" ::: "memory");
        else              asm volatile("cp.async.wait_group 0;" ::: "memory");
        __syncthreads();
        if (c + 2 < NCHA) load_stage(c + 2, (c + 2) % 3);

        const uint32_t Kb = sb + AT_K + (c % 3) * 16384;
        const uint32_t Vb = sb + AT_V + (c % 3) * 8192;
        const int* mk = (const int*)(dsm + AT_MK + (c % 3) * 128);

        // ---- S = Q' . K'tile^T  (K' = 256 packed: (qh+ql).kh) ----
        float cS[4][4];
#pragma unroll
        for (int t = 0; t < 4; t++)
#pragma unroll
            for (int u = 0; u < 4; u++) cS[t][u] = 0.f;
#pragma unroll
        for (int kc = 0; kc < 4; kc++) {
#pragma unroll
            for (int ks = 0; ks < 4; ks++) {
                uint32_t a[4], bb[2][4];
                ldsm_x4(a, sb + AT_Q + swz(kc * 16384 + aoff + ks * 32));
#pragma unroll
                for (int hf = 0; hf < 2; hf++)
                    ldsm_x4(bb[hf], Kb + swz(kc * 4096 + boff[hf] + ks * 32));
#pragma unroll
                for (int hf = 0; hf < 2; hf++) {
                    mma_f16(cS[hf * 2 + 0], a, &bb[hf][0]);
                    mma_f16(cS[hf * 2 + 1], a, &bb[hf][2]);
                }
            }
        }

        // ---- softmax (warp-local rows) ----
#pragma unroll
        for (int t = 0; t < 4; t++) {
            int2 mv = *(const int2*)&mk[t * 8 + ((lane & 3) << 1)];
#pragma unroll
            for (int u = 0; u < 4; u++) {
                float s = cS[t][u] * scaling;
                int mkv = (u & 1) ? mv.y : mv.x;
                cS[t][u] = (mkv == 0) ? -1e9f : s;
            }
        }
        float tmax0 = -1e30f, tmax1 = -1e30f;
#pragma unroll
        for (int t = 0; t < 4; t++) {
            tmax0 = fmaxf(tmax0, fmaxf(cS[t][0], cS[t][1]));
            tmax1 = fmaxf(tmax1, fmaxf(cS[t][2], cS[t][3]));
        }
#pragma unroll
        for (int o = 1; o < 4; o <<= 1) {
            tmax0 = fmaxf(tmax0, __shfl_xor_sync(0xFFFFFFFFu, tmax0, o));
            tmax1 = fmaxf(tmax1, __shfl_xor_sync(0xFFFFFFFFu, tmax1, o));
        }
        float mn0 = fmaxf(mi[0], tmax0), mn1 = fmaxf(mi[1], tmax1);
        float al0 = __expf(mi[0] - mn0), al1 = __expf(mi[1] - mn1);
        mi[0] = mn0; mi[1] = mn1;

        float ps0 = 0.f, ps1 = 0.f;
#pragma unroll
        for (int t = 0; t < 4; t++) {
            cS[t][0] = __expf(cS[t][0] - mn0);
            cS[t][1] = __expf(cS[t][1] - mn0);
            cS[t][2] = __expf(cS[t][2] - mn1);
            cS[t][3] = __expf(cS[t][3] - mn1);
            ps0 += cS[t][0] + cS[t][1];
            ps1 += cS[t][2] + cS[t][3];
        }
#pragma unroll
        for (int o = 1; o < 4; o <<= 1) {
            ps0 += __shfl_xor_sync(0xFFFFFFFFu, ps0, o);
            ps1 += __shfl_xor_sync(0xFFFFFFFFu, ps1, o);
        }
        li[0] = li[0] * al0 + ps0;
        li[1] = li[1] * al1 + ps1;
#pragma unroll
        for (int j = 0; j < 16; j++) {
            O[j][0] *= al0; O[j][1] *= al0;
            O[j][2] *= al1; O[j][3] *= al1;
        }

        // pack P into A fragments: ahh (hi), alo (residual), fp16
        uint32_t ahh[2][4], alo[2][4];
#pragma unroll
        for (int ks = 0; ks < 2; ks++) {
#pragma unroll
            for (int sub = 0; sub < 2; sub++) {
                int t = 2 * ks + sub;
                __half h01a = __float2half(cS[t][0]);
                __half h01b = __float2half(cS[t][1]);
                __half h23a = __float2half(cS[t][2]);
                __half h23b = __float2half(cS[t][3]);
                ahh[ks][sub * 2 + 0] = packh2(h01a, h01b);
                ahh[ks][sub * 2 + 1] = packh2(h23a, h23b);
                alo[ks][sub * 2 + 0] = packh2(
                    __float2half(cS[t][0] - __half2float(h01a)),
                    __float2half(cS[t][1] - __half2float(h01b)));
                alo[ks][sub * 2 + 1] = packh2(
                    __float2half(cS[t][2] - __half2float(h23a)),
                    __float2half(cS[t][3] - __half2float(h23b)));
            }
        }

        // ---- O += (P_hi + P_lo) . V ----
#pragma unroll
        for (int g = 0; g < 8; g++) {
            const int vch = g >> 2;
            const uint32_t colb = (g & 3) * 32 + vcol;
#pragma unroll
            for (int ks = 0; ks < 2; ks++) {
                uint32_t bv[4];
                uint32_t ro = (uint32_t)(ks * 16) * 128 + vrow;
                ldsm_x4_t(bv, Vb + swz(vch * 4096 + ro + colb));
                mma_f16(O[2 * g + 0], ahh[ks], &bv[0]);
                mma_f16(O[2 * g + 1], ahh[ks], &bv[2]);
                mma_f16(O[2 * g + 0], alo[ks], &bv[0]);
                mma_f16(O[2 * g + 1], alo[ks], &bv[2]);
            }
        }
    }

    // ---- epilogue: O / l, emit packed bf16 [hi|lo|hi] rows (stride 3072) ----
    float inv0 = 1.0f / li[0], inv1 = 1.0f / li[1];
#pragma unroll
    for (int half_ = 0; half_ < 2; half_++) {
        float inv = half_ ? inv1 : inv0;
        int token = b * M + qrow0 + wrp * 16 + (lane >> 2) + half_ * 8;
        size_t rowbase = (size_t)token * 3072 + hd * 128 + ((lane & 3) << 1);
#pragma unroll
        for (int j = 0; j < 16; j++) {
            float v0 = O[j][half_ * 2 + 0] * inv;
            float v1 = O[j][half_ * 2 + 1] * inv;
            __nv_bfloat16 h0 = __float2bfloat16(v0);
            __nv_bfloat16 h1 = __float2bfloat16(v1);
            __nv_bfloat16 l0 = __float2bfloat16(v0 - __bfloat162float(h0));
            __nv_bfloat16 l1 = __float2bfloat16(v1 - __bfloat162float(h1));
            uint32_t uh = packbf2(h0, h1), ul = packbf2(l0, l1);
            size_t base = rowbase + j * 8;
            *(uint32_t*)(OB + base)        = uh;
            *(uint32_t*)(OB + base + 1024) = ul;
            *(uint32_t*)(OB + base + 2048) = uh;
        }
    }
}

// ---------------------------------------------------------------------------
// Launch sequence (single stream, graph-capturable: kernel launches only)
// ---------------------------------------------------------------------------
extern "C" void kernel_launch(void* const* d_in, const int* in_sizes, int n_in,
                              void* d_out, int out_size)
{
    const float* query  = (const float*)d_in[0];
    const float* key    = (const float*)d_in[1];
    const int*   mask   = (const int*)d_in[2];
    // d_in[3] = value1, intentionally unused (matches reference)
    const float* value2 = (const float*)d_in[4];
    const float* Wq = (const float*)d_in[5];
    const float* bq = (const float*)d_in[6];
    const float* gq = (const float*)d_in[7];
    const float* betaq = (const float*)d_in[8];
    const float* Wk = (const float*)d_in[9];
    const float* bk = (const float*)d_in[10];
    const float* gk = (const float*)d_in[11];
    const float* betak = (const float*)d_in[12];
    const float* Wv = (const float*)d_in[13];
    const float* bv = (const float*)d_in[14];
    const float* gv = (const float*)d_in[15];
    const float* betav = (const float*)d_in[16];
    const float* Wm = (const float*)d_in[17];
    const float* bm = (const float*)d_in[18];

    const int B = in_sizes[3] / EDIM;   // value1 is [B, E]
    const int Ntok = in_sizes[2];       // mask is [B, M]
    const int M = Ntok / B;

    __nv_bfloat16 *abf, *wbf;
    __half *qp, *kp, *vp;
    cudaGetSymbolAddress((void**)&abf, g_abf);
    cudaGetSymbolAddress((void**)&wbf, g_wbf);
    cudaGetSymbolAddress((void**)&qp, g_qp);
    cudaGetSymbolAddress((void**)&kp, g_kp);
    cudaGetSymbolAddress((void**)&vp, g_vp);
    __half* ah = (__half*)abf;   // fp16 activation alias (proj phase only)
    __half* wh = (__half*)wbf;   // fp16 weight alias

    cudaFuncSetAttribute(gemm_tc<0>, cudaFuncAttributeMaxDynamicSharedMemorySize, GEMM_SMEM);
    cudaFuncSetAttribute(gemm_tc<1>, cudaFuncAttributeMaxDynamicSharedMemorySize, GEMM_SMEM);
    cudaFuncSetAttribute(gemm_tc<2>, cudaFuncAttributeMaxDynamicSharedMemorySize, GEMM_SMEM);
    cudaFuncSetAttribute(gemm_tc<3>, cudaFuncAttributeMaxDynamicSharedMemorySize, GEMM_SMEM);
    cudaFuncSetAttribute(attn_tc, cudaFuncAttributeMaxDynamicSharedMemorySize, AT_SMEM);

    dim3 blk(256);
    dim3 gg(EDIM / 128, Ntok / 128);

    convert2h<true><<<EDIM, 256>>>(Wq, wh);
    convert2h<false><<<Ntok, 256>>>(query, ah);
    gemm_tc<1><<<gg, blk, GEMM_SMEM>>>(ah, wh, bq, gq, betaq, qp);

    convert2h<true><<<EDIM, 256>>>(Wk, wh);
    convert2h<false><<<Ntok, 256>>>(key, ah);
    gemm_tc<2><<<gg, blk, GEMM_SMEM>>>(ah, wh, bk, gk, betak, kp);

    convert2h<true><<<EDIM, 256>>>(Wv, wh);
    convert2h<false><<<Ntok, 256>>>(value2, ah);
    gemm_tc<3><<<gg, blk, GEMM_SMEM>>>(ah, wh, bv, gv, betav, vp);

    dim3 ga(M / 128, HEADS, B);
    attn_tc<<<ga, blk, AT_SMEM>>>(qp, kp, vp, mask, abf, M);

    convert3w<<<EDIM, 256>>>(Wm, wbf);
    gemm_tc<0><<<gg, blk, GEMM_SMEM>>>(abf, wbf, bm, nullptr, nullptr, d_out);
}

// round 6
// speedup vs baseline: 5.0009x; 1.1296x over previous
#include <cuda_runtime.h>
#include <cuda_fp16.h>
#include <cstdint>

// Problem constants (fixed by dataset): B=32, M=1024, E=1024, H=8, D=128
#define EDIM 1024
#define HEADS 8
#define DHEAD 128
#define MAXTOK 32768

// Scratch (__device__ globals: allocation-free rule)
// g_ah: fp16 [hi|lo] activations (proj phase) / attn output [oh|ol] (final phase)
__device__ __half g_ah[(size_t)MAXTOK * 2048];
__device__ __half g_wh[(size_t)EDIM * 2048];     // W packed fp16 [hi|hi]
__device__ __half g_qp[(size_t)MAXTOK * 2048];   // Q packed [qh|ql]/head
__device__ __half g_kp[(size_t)MAXTOK * 2048];   // K packed [kh|kh]/head
__device__ __half g_vp[(size_t)MAXTOK * 1024];   // V plain fp16/head

// ---------------------------------------------------------------------------
// helpers (baseline PTX only: works on non-'a' sm_103 target)
// ---------------------------------------------------------------------------
__device__ __forceinline__ uint32_t s2u(const void* p) {
    uint32_t a;
    asm("{ .reg .u64 t; cvta.to.shared.u64 t, %1; cvt.u32.u64 %0, t; }"
        : "=r"(a) : "l"(p));
    return a;
}
__device__ __forceinline__ void ldsm_x4(uint32_t* r, uint32_t addr) {
    asm volatile("ldmatrix.sync.aligned.m8n8.x4.shared.b16 {%0,%1,%2,%3}, [%4];"
        : "=r"(r[0]), "=r"(r[1]), "=r"(r[2]), "=r"(r[3]) : "r"(addr));
}
__device__ __forceinline__ void ldsm_x4_t(uint32_t* r, uint32_t addr) {
    asm volatile("ldmatrix.sync.aligned.m8n8.x4.trans.shared.b16 {%0,%1,%2,%3}, [%4];"
        : "=r"(r[0]), "=r"(r[1]), "=r"(r[2]), "=r"(r[3]) : "r"(addr));
}
__device__ __forceinline__ void mma_f16(float* d, const uint32_t* a,
                                        const uint32_t* b) {
    asm volatile("mma.sync.aligned.m16n8k16.row.col.f32.f16.f16.f32 "
        "{%0,%1,%2,%3}, {%4,%5,%6,%7}, {%8,%9}, {%0,%1,%2,%3};"
        : "+f"(d[0]), "+f"(d[1]), "+f"(d[2]), "+f"(d[3])
        : "r"(a[0]), "r"(a[1]), "r"(a[2]), "r"(a[3]), "r"(b[0]), "r"(b[1]));
}
__device__ __forceinline__ void cpasync16(uint32_t dst, const void* src) {
    asm volatile("cp.async.cg.shared.global [%0], [%1], 16;"
                 :: "r"(dst), "l"(src) : "memory");
}
__device__ __forceinline__ uint32_t packh2(__half lo, __half hi) {
    __half2 t; t.x = lo; t.y = hi;
    return *reinterpret_cast<uint32_t*>(&t);
}
__device__ __forceinline__ uint32_t swz(uint32_t off) {
    return off ^ ((off >> 3) & 0x70);
}

// ---------------------------------------------------------------------------
// fp32 -> fp16 2x pack, row stride 2048.  REP: [hi|hi] (weights) / [hi|lo]
// ---------------------------------------------------------------------------
template <bool REP>
__global__ void convert2h(const float* __restrict__ in,
                          __half* __restrict__ out) {
    size_t i = ((size_t)blockIdx.x * 256 + threadIdx.x) * 4;
    float4 v = *(const float4*)(in + i);
    size_t r = i >> 10;
    int c = (int)(i & 1023);
    float f[4] = {v.x, v.y, v.z, v.w};
    __half h[4], l[4];
#pragma unroll
    for (int j = 0; j < 4; j++) {
        h[j] = __float2half(f[j]);
        l[j] = __float2half(f[j] - __half2float(h[j]));
    }
    __half* row = out + r * 2048;
    *(uint32_t*)(row + c)     = packh2(h[0], h[1]);
    *(uint32_t*)(row + c + 2) = packh2(h[2], h[3]);
    *(uint32_t*)(row + 1024 + c)     = REP ? packh2(h[0], h[1]) : packh2(l[0], l[1]);
    *(uint32_t*)(row + 1024 + c + 2) = REP ? packh2(h[2], h[3]) : packh2(l[2], l[3]);
}

// ---------------------------------------------------------------------------
// HMMA fp16 GEMM: CTA 128x128, BK=64 (128B rows), 3-stage cp.async, 256 thr.
// All modes K'=2048 fp16 ([a_hi|a_lo] x [w_hi|w_hi] split).
// MODE 0: +bias -> fp32 out (final projection)
// MODE 1: +bias+CELU+GN -> Q packed [qh|ql] (256/head)
// MODE 2: same -> K packed [kh|kh]
// MODE 3: same -> V plain fp16 (128/head)
// ---------------------------------------------------------------------------
#define STAGE_BYTES 32768
#define GEMM_SMEM (3 * STAGE_BYTES + 2048)
#define KEL 2048
#define NCHT 32

template <int MODE>
__global__ void __launch_bounds__(256, 2) gemm_tc(
    const __half* __restrict__ Av, const __half* __restrict__ Wv,
    const float* __restrict__ bias, const float* __restrict__ gamma,
    const float* __restrict__ beta, void* __restrict__ out)
{
    constexpr bool GN = (MODE >= 1);
    extern __shared__ char dsm[];
    const uint32_t sb = s2u(dsm);
    const int tid = threadIdx.x;
    const int lane = tid & 31;
    const int wrp = tid >> 5;
    const int wm = wrp & 1;
    const int wn = wrp >> 1;
    const int row0 = blockIdx.y << 7;
    const int col0 = blockIdx.x << 7;

    float* sp = (float*)(dsm + 3 * STAGE_BYTES);
    if (tid < 128) {
        sp[tid] = bias[col0 + tid];
        if (GN) {
            sp[128 + tid] = gamma[col0 + tid];
            sp[256 + tid] = beta[col0 + tid];
        }
    }

    const int gr = tid >> 3;
    const int q16 = (tid & 7) << 4;
    const size_t rstride = (size_t)KEL * 2;
    const char* Agp = (const char*)Av + (size_t)row0 * rstride + q16;
    const char* Bgp = (const char*)Wv + (size_t)col0 * rstride + q16;

    auto load_stage = [&](int c, int s) {
        uint32_t Ab = sb + s * STAGE_BYTES;
        uint32_t Bb = Ab + 16384;
#pragma unroll
        for (int l = 0; l < 4; l++) {
            int r = gr + (l << 5);
            uint32_t sw = swz((r << 7) + q16);
            cpasync16(Ab + sw, Agp + (size_t)r * rstride + (size_t)c * 128);
            cpasync16(Bb + sw, Bgp + (size_t)r * rstride + (size_t)c * 128);
        }
        asm volatile("cp.async.commit_group;" ::: "memory");
    };

    load_stage(0, 0);
    load_stage(1, 1);

    uint32_t abase[4];
#pragma unroll
    for (int i = 0; i < 4; i++) {
        int row = wm * 64 + i * 16 + (lane & 15);
        abase[i] = (row << 7) + ((lane >> 4) << 4);
    }
    uint32_t bbase[2];
#pragma unroll
    for (int j2 = 0; j2 < 2; j2++) {
        int row = wn * 32 + j2 * 16 + (lane & 7) + ((lane >> 4) << 3);
        bbase[j2] = (row << 7) + (((lane >> 3) & 1) << 4);
    }

    float acc[4][4][4];
#pragma unroll
    for (int i = 0; i < 4; i++)
#pragma unroll
        for (int j = 0; j < 4; j++)
#pragma unroll
            for (int t = 0; t < 4; t++) acc[i][j][t] = 0.f;

    for (int c = 0; c < NCHT; c++) {
        if (c < NCHT - 2) asm volatile("cp.async.wait_group 1;" ::: "memory");
        else              asm volatile("cp.async.wait_group 0;" ::: "memory");
        __syncthreads();
        if (c + 2 < NCHT) load_stage(c + 2, (c + 2) % 3);

        const uint32_t Ab = sb + (c % 3) * STAGE_BYTES;
        const uint32_t Bb = Ab + 16384;
#pragma unroll
        for (int ks = 0; ks < 4; ks++) {
            const int kb = ks << 5;
            uint32_t a[4][4], b[2][4];
#pragma unroll
            for (int i = 0; i < 4; i++)
                ldsm_x4(a[i], Ab + swz(abase[i] + kb));
#pragma unroll
            for (int j2 = 0; j2 < 2; j2++)
                ldsm_x4(b[j2], Bb + swz(bbase[j2] + kb));
#pragma unroll
            for (int i = 0; i < 4; i++)
#pragma unroll
                for (int j2 = 0; j2 < 2; j2++) {
                    mma_f16(acc[i][j2 * 2 + 0], a[i], &b[j2][0]);
                    mma_f16(acc[i][j2 * 2 + 1], a[i], &b[j2][2]);
                }
        }
        __syncthreads();
    }

    // ---------------- epilogue ----------------
    const int lr = lane >> 2;
    const int lc = (lane & 3) << 1;
    const int hd = col0 >> 7;   // head index for packed modes

    if (GN) {
        float* redS = (float*)dsm;
        float* redQ = redS + 512;
#pragma unroll
        for (int i = 0; i < 4; i++) {
            float s0 = 0.f, q0 = 0.f, s1 = 0.f, q1 = 0.f;
#pragma unroll
            for (int j = 0; j < 4; j++) {
                int cl = wn * 32 + j * 8 + lc;
#pragma unroll
                for (int t = 0; t < 4; t++) {
                    float v = acc[i][j][t] + sp[cl + (t & 1)];
                    v = v > 0.f ? v : 1.3f * expm1f(v * (1.0f / 1.3f));
                    acc[i][j][t] = v;
                    if (t < 2) { s0 += v; q0 += v * v; }
                    else       { s1 += v; q1 += v * v; }
                }
            }
#pragma unroll
            for (int o = 1; o < 4; o <<= 1) {
                s0 += __shfl_xor_sync(0xFFFFFFFFu, s0, o);
                q0 += __shfl_xor_sync(0xFFFFFFFFu, q0, o);
                s1 += __shfl_xor_sync(0xFFFFFFFFu, s1, o);
                q1 += __shfl_xor_sync(0xFFFFFFFFu, q1, o);
            }
            if ((lane & 3) == 0) {
                int r = wm * 64 + i * 16 + lr;
                redS[r * 4 + wn] = s0;  redQ[r * 4 + wn] = q0;
                redS[(r + 8) * 4 + wn] = s1;  redQ[(r + 8) * 4 + wn] = q1;
            }
        }
        __syncthreads();
        __half* ob = (__half*)out;
#pragma unroll
        for (int i = 0; i < 4; i++) {
            int rbase = wm * 64 + i * 16 + lr;
#pragma unroll
            for (int half_ = 0; half_ < 2; half_++) {
                int r = rbase + half_ * 8;
                float s = redS[r * 4] + redS[r * 4 + 1] + redS[r * 4 + 2] + redS[r * 4 + 3];
                float q = redQ[r * 4] + redQ[r * 4 + 1] + redQ[r * 4 + 2] + redQ[r * 4 + 3];
                float mean = s * (1.f / 128.f);
                float var = q * (1.f / 128.f) - mean * mean;
                float rs = rsqrtf(var + 1e-5f);
                int token = row0 + r;
#pragma unroll
                for (int j = 0; j < 4; j++) {
                    int cl = wn * 32 + j * 8 + lc;
                    float v0 = (acc[i][j][half_ * 2 + 0] - mean) * rs * sp[128 + cl]
                             + sp[256 + cl];
                    float v1 = (acc[i][j][half_ * 2 + 1] - mean) * rs * sp[128 + cl + 1]
                             + sp[256 + cl + 1];
                    __half h0 = __float2half(v0);
                    __half h1 = __float2half(v1);
                    uint32_t uh = packh2(h0, h1);
                    if (MODE == 1) {
                        uint32_t ul = packh2(__float2half(v0 - __half2float(h0)),
                                             __float2half(v1 - __half2float(h1)));
                        size_t base = (size_t)token * 2048 + hd * 256 + cl;
                        *(uint32_t*)(ob + base)       = uh;
                        *(uint32_t*)(ob + base + 128) = ul;
                    } else if (MODE == 2) {
                        size_t base = (size_t)token * 2048 + hd * 256 + cl;
                        *(uint32_t*)(ob + base)       = uh;
                        *(uint32_t*)(ob + base + 128) = uh;
                    } else {
                        size_t base = (size_t)token * 1024 + hd * 128 + cl;
                        *(uint32_t*)(ob + base) = uh;
                    }
                }
            }
        }
    } else {
        float* C = (float*)out;
#pragma unroll
        for (int i = 0; i < 4; i++) {
#pragma unroll
            for (int half_ = 0; half_ < 2; half_++) {
                int r = wm * 64 + i * 16 + lr + half_ * 8;
                float* crow = C + (size_t)(row0 + r) * EDIM + col0;
#pragma unroll
                for (int j = 0; j < 4; j++) {
                    int cl = wn * 32 + j * 8 + lc;
                    float2 ov;
                    ov.x = acc[i][j][half_ * 2 + 0] + sp[cl];
                    ov.y = acc[i][j][half_ * 2 + 1] + sp[cl + 1];
                    *(float2*)(crow + cl) = ov;
                }
            }
        }
    }
}

// ---------------------------------------------------------------------------
// Tensor-core flash attention, fp16.
// CTA = 128 q-rows x one (b,h). 8 warps x 16 rows. 32-key chunks, 3 stages.
// S: Q'[128x256] . K'tile[32x256]^T  ((qh+ql).kh baked into packing)
// PV: single pass P_hi . V (P rounding contributes ~7e-5 rel on O).
// Epilogue: O/l -> packed fp16 [oh|ol], stride 2048 (feeds final GEMM).
// ---------------------------------------------------------------------------
#define AT_Q   0
#define AT_K   65536                   // 3 stages x 16384 (4 subtiles 32x128B)
#define AT_V   (65536 + 49152)         // 3 stages x 8192  (2 subtiles 32x128B)
#define AT_MK  (AT_V + 24576)          // 3 x 128B mask
#define AT_SMEM (AT_MK + 384)

__global__ void __launch_bounds__(256, 1) attn_tc(
    const __half* __restrict__ Qp, const __half* __restrict__ Kp,
    const __half* __restrict__ Vp, const int* __restrict__ mask,
    __half* __restrict__ OB, int M)
{
    extern __shared__ char dsm[];
    const uint32_t sb = s2u(dsm);
    const int tid = threadIdx.x;
    const int lane = tid & 31;
    const int wrp = tid >> 5;
    const int qrow0 = blockIdx.x * 128;
    const int hd = blockIdx.y;
    const int b = blockIdx.z;

    const char* qg = (const char*)(Qp + (size_t)(b * M + qrow0) * 2048 + hd * 256);
    const char* kg = (const char*)(Kp + (size_t)b * M * 2048 + hd * 256);
    const char* vg = (const char*)(Vp + (size_t)b * M * 1024 + hd * 128);

    // Q' resident: 128 rows x 512B = 4096 granules
#pragma unroll
    for (int l = 0; l < 16; l++) {
        int gi = tid + 256 * l;
        int row = gi >> 5, q = gi & 31;
        uint32_t off = (q >> 3) * 16384 + row * 128 + (q & 7) * 16;
        cpasync16(sb + AT_Q + swz(off), qg + (size_t)row * 4096 + q * 16);
    }

    auto load_stage = [&](int c, int s) {
        uint32_t kb = sb + AT_K + s * 16384;
#pragma unroll
        for (int l = 0; l < 4; l++) {
            int gi = tid + 256 * l;
            int row = gi >> 5, q = gi & 31;
            uint32_t off = (q >> 3) * 4096 + row * 128 + (q & 7) * 16;
            cpasync16(kb + swz(off), kg + (size_t)(c * 32 + row) * 4096 + q * 16);
        }
        uint32_t vb = sb + AT_V + s * 8192;
#pragma unroll
        for (int l = 0; l < 2; l++) {
            int gi = tid + 256 * l;
            int row = gi >> 4, q = gi & 15;
            uint32_t off = (q >> 3) * 4096 + row * 128 + (q & 7) * 16;
            cpasync16(vb + swz(off), vg + (size_t)(c * 32 + row) * 2048 + q * 16);
        }
        if (tid < 8)
            cpasync16(sb + AT_MK + s * 128 + tid * 16,
                      (const char*)(mask + (size_t)b * M + c * 32) + tid * 16);
        asm volatile("cp.async.commit_group;" ::: "memory");
    };

    load_stage(0, 0);
    load_stage(1, 1);

    const uint32_t aoff = (wrp * 16 + (lane & 15)) * 128 + ((lane >> 4) << 4);
    uint32_t boff[2];
#pragma unroll
    for (int hf = 0; hf < 2; hf++)
        boff[hf] = (hf * 16 + (lane & 7) + ((lane >> 4) << 3)) * 128
                 + (((lane >> 3) & 1) << 4);
    const uint32_t vrow = ((lane & 7) + (((lane >> 3) & 1) << 3)) * 128;
    const uint32_t vcol = ((lane >> 4) << 4);

    float O[16][4];
#pragma unroll
    for (int j = 0; j < 16; j++)
#pragma unroll
        for (int t = 0; t < 4; t++) O[j][t] = 0.f;
    float mi[2] = {-1e30f, -1e30f}, li[2] = {0.f, 0.f};
    const float scaling = 0.08838834764831845f;

    const int NCHA = M / 32;
    for (int c = 0; c < NCHA; c++) {
        if (c < NCHA - 2) asm volatile("cp.async.wait_group 1;" ::: "memory");
        else              asm volatile("cp.async.wait_group 0;" ::: "memory");
        __syncthreads();
        if (c + 2 < NCHA) load_stage(c + 2, (c + 2) % 3);

        const uint32_t Kb = sb + AT_K + (c % 3) * 16384;
        const uint32_t Vb = sb + AT_V + (c % 3) * 8192;
        const int* mk = (const int*)(dsm + AT_MK + (c % 3) * 128);

        // ---- S = Q' . K'tile^T  (K' = 256 packed: (qh+ql).kh) ----
        float cS[4][4];
#pragma unroll
        for (int t = 0; t < 4; t++)
#pragma unroll
            for (int u = 0; u < 4; u++) cS[t][u] = 0.f;
#pragma unroll
        for (int kc = 0; kc < 4; kc++) {
#pragma unroll
            for (int ks = 0; ks < 4; ks++) {
                uint32_t a[4], bb[2][4];
                ldsm_x4(a, sb + AT_Q + swz(kc * 16384 + aoff + ks * 32));
#pragma unroll
                for (int hf = 0; hf < 2; hf++)
                    ldsm_x4(bb[hf], Kb + swz(kc * 4096 + boff[hf] + ks * 32));
#pragma unroll
                for (int hf = 0; hf < 2; hf++) {
                    mma_f16(cS[hf * 2 + 0], a, &bb[hf][0]);
                    mma_f16(cS[hf * 2 + 1], a, &bb[hf][2]);
                }
            }
        }

        // ---- softmax (warp-local rows) ----
#pragma unroll
        for (int t = 0; t < 4; t++) {
            int2 mv = *(const int2*)&mk[t * 8 + ((lane & 3) << 1)];
#pragma unroll
            for (int u = 0; u < 4; u++) {
                float s = cS[t][u] * scaling;
                int mkv = (u & 1) ? mv.y : mv.x;
                cS[t][u] = (mkv == 0) ? -1e9f : s;
            }
        }
        float tmax0 = -1e30f, tmax1 = -1e30f;
#pragma unroll
        for (int t = 0; t < 4; t++) {
            tmax0 = fmaxf(tmax0, fmaxf(cS[t][0], cS[t][1]));
            tmax1 = fmaxf(tmax1, fmaxf(cS[t][2], cS[t][3]));
        }
#pragma unroll
        for (int o = 1; o < 4; o <<= 1) {
            tmax0 = fmaxf(tmax0, __shfl_xor_sync(0xFFFFFFFFu, tmax0, o));
            tmax1 = fmaxf(tmax1, __shfl_xor_sync(0xFFFFFFFFu, tmax1, o));
        }
        float mn0 = fmaxf(mi[0], tmax0), mn1 = fmaxf(mi[1], tmax1);
        float al0 = __expf(mi[0] - mn0), al1 = __expf(mi[1] - mn1);
        mi[0] = mn0; mi[1] = mn1;

        float ps0 = 0.f, ps1 = 0.f;
#pragma unroll
        for (int t = 0; t < 4; t++) {
            cS[t][0] = __expf(cS[t][0] - mn0);
            cS[t][1] = __expf(cS[t][1] - mn0);
            cS[t][2] = __expf(cS[t][2] - mn1);
            cS[t][3] = __expf(cS[t][3] - mn1);
            ps0 += cS[t][0] + cS[t][1];
            ps1 += cS[t][2] + cS[t][3];
        }
#pragma unroll
        for (int o = 1; o < 4; o <<= 1) {
            ps0 += __shfl_xor_sync(0xFFFFFFFFu, ps0, o);
            ps1 += __shfl_xor_sync(0xFFFFFFFFu, ps1, o);
        }
        li[0] = li[0] * al0 + ps0;
        li[1] = li[1] * al1 + ps1;
#pragma unroll
        for (int j = 0; j < 16; j++) {
            O[j][0] *= al0; O[j][1] *= al0;
            O[j][2] *= al1; O[j][3] *= al1;
        }

        // pack P (hi only) into A fragments
        uint32_t ahh[2][4];
#pragma unroll
        for (int ks = 0; ks < 2; ks++) {
#pragma unroll
            for (int sub = 0; sub < 2; sub++) {
                int t = 2 * ks + sub;
                ahh[ks][sub * 2 + 0] = packh2(__float2half(cS[t][0]),
                                              __float2half(cS[t][1]));
                ahh[ks][sub * 2 + 1] = packh2(__float2half(cS[t][2]),
                                              __float2half(cS[t][3]));
            }
        }

        // ---- O += P . V  (single hi pass) ----
#pragma unroll
        for (int g = 0; g < 8; g++) {
            const int vch = g >> 2;
            const uint32_t colb = (g & 3) * 32 + vcol;
#pragma unroll
            for (int ks = 0; ks < 2; ks++) {
                uint32_t bv[4];
                uint32_t ro = (uint32_t)(ks * 16) * 128 + vrow;
                ldsm_x4_t(bv, Vb + swz(vch * 4096 + ro + colb));
                mma_f16(O[2 * g + 0], ahh[ks], &bv[0]);
                mma_f16(O[2 * g + 1], ahh[ks], &bv[2]);
            }
        }
    }

    // ---- epilogue: O / l, emit packed fp16 [oh|ol] rows (stride 2048) ----
    float inv0 = 1.0f / li[0], inv1 = 1.0f / li[1];
#pragma unroll
    for (int half_ = 0; half_ < 2; half_++) {
        float inv = half_ ? inv1 : inv0;
        int token = b * M + qrow0 + wrp * 16 + (lane >> 2) + half_ * 8;
        size_t rowbase = (size_t)token * 2048 + hd * 128 + ((lane & 3) << 1);
#pragma unroll
        for (int j = 0; j < 16; j++) {
            float v0 = O[j][half_ * 2 + 0] * inv;
            float v1 = O[j][half_ * 2 + 1] * inv;
            __half h0 = __float2half(v0);
            __half h1 = __float2half(v1);
            uint32_t uh = packh2(h0, h1);
            uint32_t ul = packh2(__float2half(v0 - __half2float(h0)),
                                 __float2half(v1 - __half2float(h1)));
            size_t base = rowbase + j * 8;
            *(uint32_t*)(OB + base)        = uh;
            *(uint32_t*)(OB + base + 1024) = ul;
        }
    }
}

// ---------------------------------------------------------------------------
// Launch sequence (single stream, graph-capturable: kernel launches only)
// ---------------------------------------------------------------------------
extern "C" void kernel_launch(void* const* d_in, const int* in_sizes, int n_in,
                              void* d_out, int out_size)
{
    const float* query  = (const float*)d_in[0];
    const float* key    = (const float*)d_in[1];
    const int*   mask   = (const int*)d_in[2];
    // d_in[3] = value1, intentionally unused (matches reference)
    const float* value2 = (const float*)d_in[4];
    const float* Wq = (const float*)d_in[5];
    const float* bq = (const float*)d_in[6];
    const float* gq = (const float*)d_in[7];
    const float* betaq = (const float*)d_in[8];
    const float* Wk = (const float*)d_in[9];
    const float* bk = (const float*)d_in[10];
    const float* gk = (const float*)d_in[11];
    const float* betak = (const float*)d_in[12];
    const float* Wv = (const float*)d_in[13];
    const float* bv = (const float*)d_in[14];
    const float* gv = (const float*)d_in[15];
    const float* betav = (const float*)d_in[16];
    const float* Wm = (const float*)d_in[17];
    const float* bm = (const float*)d_in[18];

    const int B = in_sizes[3] / EDIM;   // value1 is [B, E]
    const int Ntok = in_sizes[2];       // mask is [B, M]
    const int M = Ntok / B;

    __half *ah, *wh, *qp, *kp, *vp;
    cudaGetSymbolAddress((void**)&ah, g_ah);
    cudaGetSymbolAddress((void**)&wh, g_wh);
    cudaGetSymbolAddress((void**)&qp, g_qp);
    cudaGetSymbolAddress((void**)&kp, g_kp);
    cudaGetSymbolAddress((void**)&vp, g_vp);

    cudaFuncSetAttribute(gemm_tc<0>, cudaFuncAttributeMaxDynamicSharedMemorySize, GEMM_SMEM);
    cudaFuncSetAttribute(gemm_tc<1>, cudaFuncAttributeMaxDynamicSharedMemorySize, GEMM_SMEM);
    cudaFuncSetAttribute(gemm_tc<2>, cudaFuncAttributeMaxDynamicSharedMemorySize, GEMM_SMEM);
    cudaFuncSetAttribute(gemm_tc<3>, cudaFuncAttributeMaxDynamicSharedMemorySize, GEMM_SMEM);
    cudaFuncSetAttribute(attn_tc, cudaFuncAttributeMaxDynamicSharedMemorySize, AT_SMEM);

    dim3 blk(256);
    dim3 gg(EDIM / 128, Ntok / 128);

    convert2h<true><<<EDIM, 256>>>(Wq, wh);
    convert2h<false><<<Ntok, 256>>>(query, ah);
    gemm_tc<1><<<gg, blk, GEMM_SMEM>>>(ah, wh, bq, gq, betaq, qp);

    convert2h<true><<<EDIM, 256>>>(Wk, wh);
    convert2h<false><<<Ntok, 256>>>(key, ah);
    gemm_tc<2><<<gg, blk, GEMM_SMEM>>>(ah, wh, bk, gk, betak, kp);

    convert2h<true><<<EDIM, 256>>>(Wv, wh);
    convert2h<false><<<Ntok, 256>>>(value2, ah);
    gemm_tc<3><<<gg, blk, GEMM_SMEM>>>(ah, wh, bv, gv, betav, vp);

    dim3 ga(M / 128, HEADS, B);
    attn_tc<<<ga, blk, AT_SMEM>>>(qp, kp, vp, mask, ah, M);

    convert2h<true><<<EDIM, 256>>>(Wm, wh);
    gemm_tc<0><<<gg, blk, GEMM_SMEM>>>(ah, wh, bm, nullptr, nullptr, d_out);
}

// round 7
// speedup vs baseline: 7.1547x; 1.4307x over previous
#include <cuda_runtime.h>
#include <cuda_fp16.h>
#include <cstdint>

// Problem constants (fixed by dataset): B=32, M=1024, E=1024, H=8, D=128
#define EDIM 1024
#define HEADS 8
#define DHEAD 128
#define MAXTOK 32768

// Scratch (__device__ globals: allocation-free rule)
// g_ah: fp16 activations (proj phase, stride 1024) /
//       attn output [oh|ol] (final phase, stride 2048)
__device__ __half g_ah[(size_t)MAXTOK * 2048];
__device__ __half g_wh[(size_t)EDIM * 2048];     // W fp16 (stride 1024 or 2048)
__device__ __half g_qp[(size_t)MAXTOK * 1024];   // Q fp16/head (128/head)
__device__ __half g_kp[(size_t)MAXTOK * 1024];   // K fp16/head
__device__ __half g_vp[(size_t)MAXTOK * 1024];   // V fp16/head

// ---------------------------------------------------------------------------
// helpers (baseline PTX only: works on non-'a' sm_103 target)
// ---------------------------------------------------------------------------
__device__ __forceinline__ uint32_t s2u(const void* p) {
    uint32_t a;
    asm("{ .reg .u64 t; cvta.to.shared.u64 t, %1; cvt.u32.u64 %0, t; }"
        : "=r"(a) : "l"(p));
    return a;
}
__device__ __forceinline__ void ldsm_x4(uint32_t* r, uint32_t addr) {
    asm volatile("ldmatrix.sync.aligned.m8n8.x4.shared.b16 {%0,%1,%2,%3}, [%4];"
        : "=r"(r[0]), "=r"(r[1]), "=r"(r[2]), "=r"(r[3]) : "r"(addr));
}
__device__ __forceinline__ void ldsm_x4_t(uint32_t* r, uint32_t addr) {
    asm volatile("ldmatrix.sync.aligned.m8n8.x4.trans.shared.b16 {%0,%1,%2,%3}, [%4];"
        : "=r"(r[0]), "=r"(r[1]), "=r"(r[2]), "=r"(r[3]) : "r"(addr));
}
__device__ __forceinline__ void mma_f16(float* d, const uint32_t* a,
                                        const uint32_t* b) {
    asm volatile("mma.sync.aligned.m16n8k16.row.col.f32.f16.f16.f32 "
        "{%0,%1,%2,%3}, {%4,%5,%6,%7}, {%8,%9}, {%0,%1,%2,%3};"
        : "+f"(d[0]), "+f"(d[1]), "+f"(d[2]), "+f"(d[3])
        : "r"(a[0]), "r"(a[1]), "r"(a[2]), "r"(a[3]), "r"(b[0]), "r"(b[1]));
}
__device__ __forceinline__ void cpasync16(uint32_t dst, const void* src) {
    asm volatile("cp.async.cg.shared.global [%0], [%1], 16;"
                 :: "r"(dst), "l"(src) : "memory");
}
__device__ __forceinline__ uint32_t packh2(__half lo, __half hi) {
    __half2 t; t.x = lo; t.y = hi;
    return *reinterpret_cast<uint32_t*>(&t);
}
__device__ __forceinline__ uint32_t swz(uint32_t off) {
    return off ^ ((off >> 3) & 0x70);
}

// ---------------------------------------------------------------------------
// fp32 -> fp16 plain, row stride 1024 (proj activations + proj weights)
// ---------------------------------------------------------------------------
__global__ void convert1h(const float* __restrict__ in,
                          __half* __restrict__ out) {
    size_t i = ((size_t)blockIdx.x * 256 + threadIdx.x) * 4;
    float4 v = *(const float4*)(in + i);
    *(uint32_t*)(out + i)     = packh2(__float2half(v.x), __float2half(v.y));
    *(uint32_t*)(out + i + 2) = packh2(__float2half(v.z), __float2half(v.w));
}

// fp32 -> fp16 2x replicated [hi|hi], stride 2048 (final-GEMM weights)
__global__ void convert2w(const float* __restrict__ in,
                          __half* __restrict__ out) {
    size_t i = ((size_t)blockIdx.x * 256 + threadIdx.x) * 4;
    float4 v = *(const float4*)(in + i);
    size_t r = i >> 10;
    int c = (int)(i & 1023);
    uint32_t u01 = packh2(__float2half(v.x), __float2half(v.y));
    uint32_t u23 = packh2(__float2half(v.z), __float2half(v.w));
    __half* row = out + r * 2048;
    *(uint32_t*)(row + c)            = u01;
    *(uint32_t*)(row + c + 2)        = u23;
    *(uint32_t*)(row + 1024 + c)     = u01;
    *(uint32_t*)(row + 1024 + c + 2) = u23;
}

// ---------------------------------------------------------------------------
// HMMA fp16 GEMM: CTA 128x128, BK=64 (128B rows), 3-stage cp.async, 256 thr.
// MODE 0: K'=2048 ([o_hi|o_lo] x [w|w]), +bias -> fp32 out (final projection)
// MODE 1: K=1024 single-pass, +bias+CELU+GN -> plain fp16 per-head (q/k/v)
// ---------------------------------------------------------------------------
#define STAGE_BYTES 32768
#define GEMM_SMEM (3 * STAGE_BYTES + 2048)

template <int MODE>
__global__ void __launch_bounds__(256, 2) gemm_tc(
    const __half* __restrict__ Av, const __half* __restrict__ Wv,
    const float* __restrict__ bias, const float* __restrict__ gamma,
    const float* __restrict__ beta, void* __restrict__ out)
{
    constexpr bool GN = (MODE == 1);
    constexpr int KEL = GN ? 1024 : 2048;
    constexpr int NCHT = KEL / 64;
    extern __shared__ char dsm[];
    const uint32_t sb = s2u(dsm);
    const int tid = threadIdx.x;
    const int lane = tid & 31;
    const int wrp = tid >> 5;
    const int wm = wrp & 1;
    const int wn = wrp >> 1;
    const int row0 = blockIdx.y << 7;
    const int col0 = blockIdx.x << 7;

    float* sp = (float*)(dsm + 3 * STAGE_BYTES);
    if (tid < 128) {
        sp[tid] = bias[col0 + tid];
        if (GN) {
            sp[128 + tid] = gamma[col0 + tid];
            sp[256 + tid] = beta[col0 + tid];
        }
    }

    const int gr = tid >> 3;
    const int q16 = (tid & 7) << 4;
    const size_t rstride = (size_t)KEL * 2;
    const char* Agp = (const char*)Av + (size_t)row0 * rstride + q16;
    const char* Bgp = (const char*)Wv + (size_t)col0 * rstride + q16;

    auto load_stage = [&](int c, int s) {
        uint32_t Ab = sb + s * STAGE_BYTES;
        uint32_t Bb = Ab + 16384;
#pragma unroll
        for (int l = 0; l < 4; l++) {
            int r = gr + (l << 5);
            uint32_t sw = swz((r << 7) + q16);
            cpasync16(Ab + sw, Agp + (size_t)r * rstride + (size_t)c * 128);
            cpasync16(Bb + sw, Bgp + (size_t)r * rstride + (size_t)c * 128);
        }
        asm volatile("cp.async.commit_group;" ::: "memory");
    };

    load_stage(0, 0);
    load_stage(1, 1);

    uint32_t abase[4];
#pragma unroll
    for (int i = 0; i < 4; i++) {
        int row = wm * 64 + i * 16 + (lane & 15);
        abase[i] = (row << 7) + ((lane >> 4) << 4);
    }
    uint32_t bbase[2];
#pragma unroll
    for (int j2 = 0; j2 < 2; j2++) {
        int row = wn * 32 + j2 * 16 + (lane & 7) + ((lane >> 4) << 3);
        bbase[j2] = (row << 7) + (((lane >> 3) & 1) << 4);
    }

    float acc[4][4][4];
#pragma unroll
    for (int i = 0; i < 4; i++)
#pragma unroll
        for (int j = 0; j < 4; j++)
#pragma unroll
            for (int t = 0; t < 4; t++) acc[i][j][t] = 0.f;

    for (int c = 0; c < NCHT; c++) {
        if (c < NCHT - 2) asm volatile("cp.async.wait_group 1;" ::: "memory");
        else              asm volatile("cp.async.wait_group 0;" ::: "memory");
        __syncthreads();
        if (c + 2 < NCHT) load_stage(c + 2, (c + 2) % 3);

        const uint32_t Ab = sb + (c % 3) * STAGE_BYTES;
        const uint32_t Bb = Ab + 16384;
#pragma unroll
        for (int ks = 0; ks < 4; ks++) {
            const int kb = ks << 5;
            uint32_t a[4][4], b[2][4];
#pragma unroll
            for (int i = 0; i < 4; i++)
                ldsm_x4(a[i], Ab + swz(abase[i] + kb));
#pragma unroll
            for (int j2 = 0; j2 < 2; j2++)
                ldsm_x4(b[j2], Bb + swz(bbase[j2] + kb));
#pragma unroll
            for (int i = 0; i < 4; i++)
#pragma unroll
                for (int j2 = 0; j2 < 2; j2++) {
                    mma_f16(acc[i][j2 * 2 + 0], a[i], &b[j2][0]);
                    mma_f16(acc[i][j2 * 2 + 1], a[i], &b[j2][2]);
                }
        }
        __syncthreads();
    }

    // ---------------- epilogue ----------------
    const int lr = lane >> 2;
    const int lc = (lane & 3) << 1;
    const int hd = col0 >> 7;   // head index (proj mode)

    if (GN) {
        float* redS = (float*)dsm;
        float* redQ = redS + 512;
#pragma unroll
        for (int i = 0; i < 4; i++) {
            float s0 = 0.f, q0 = 0.f, s1 = 0.f, q1 = 0.f;
#pragma unroll
            for (int j = 0; j < 4; j++) {
                int cl = wn * 32 + j * 8 + lc;
#pragma unroll
                for (int t = 0; t < 4; t++) {
                    float v = acc[i][j][t] + sp[cl + (t & 1)];
                    v = v > 0.f ? v : 1.3f * expm1f(v * (1.0f / 1.3f));
                    acc[i][j][t] = v;
                    if (t < 2) { s0 += v; q0 += v * v; }
                    else       { s1 += v; q1 += v * v; }
                }
            }
#pragma unroll
            for (int o = 1; o < 4; o <<= 1) {
                s0 += __shfl_xor_sync(0xFFFFFFFFu, s0, o);
                q0 += __shfl_xor_sync(0xFFFFFFFFu, q0, o);
                s1 += __shfl_xor_sync(0xFFFFFFFFu, s1, o);
                q1 += __shfl_xor_sync(0xFFFFFFFFu, q1, o);
            }
            if ((lane & 3) == 0) {
                int r = wm * 64 + i * 16 + lr;
                redS[r * 4 + wn] = s0;  redQ[r * 4 + wn] = q0;
                redS[(r + 8) * 4 + wn] = s1;  redQ[(r + 8) * 4 + wn] = q1;
            }
        }
        __syncthreads();
        __half* ob = (__half*)out;
#pragma unroll
        for (int i = 0; i < 4; i++) {
            int rbase = wm * 64 + i * 16 + lr;
#pragma unroll
            for (int half_ = 0; half_ < 2; half_++) {
                int r = rbase + half_ * 8;
                float s = redS[r * 4] + redS[r * 4 + 1] + redS[r * 4 + 2] + redS[r * 4 + 3];
                float q = redQ[r * 4] + redQ[r * 4 + 1] + redQ[r * 4 + 2] + redQ[r * 4 + 3];
                float mean = s * (1.f / 128.f);
                float var = q * (1.f / 128.f) - mean * mean;
                float rs = rsqrtf(var + 1e-5f);
                int token = row0 + r;
#pragma unroll
                for (int j = 0; j < 4; j++) {
                    int cl = wn * 32 + j * 8 + lc;
                    float v0 = (acc[i][j][half_ * 2 + 0] - mean) * rs * sp[128 + cl]
                             + sp[256 + cl];
                    float v1 = (acc[i][j][half_ * 2 + 1] - mean) * rs * sp[128 + cl + 1]
                             + sp[256 + cl + 1];
                    size_t base = (size_t)token * 1024 + hd * 128 + cl;
                    *(uint32_t*)(ob + base) = packh2(__float2half(v0),
                                                     __float2half(v1));
                }
            }
        }
    } else {
        float* C = (float*)out;
#pragma unroll
        for (int i = 0; i < 4; i++) {
#pragma unroll
            for (int half_ = 0; half_ < 2; half_++) {
                int r = wm * 64 + i * 16 + lr + half_ * 8;
                float* crow = C + (size_t)(row0 + r) * EDIM + col0;
#pragma unroll
                for (int j = 0; j < 4; j++) {
                    int cl = wn * 32 + j * 8 + lc;
                    float2 ov;
                    ov.x = acc[i][j][half_ * 2 + 0] + sp[cl];
                    ov.y = acc[i][j][half_ * 2 + 1] + sp[cl + 1];
                    *(float2*)(crow + cl) = ov;
                }
            }
        }
    }
}

// ---------------------------------------------------------------------------
// Tensor-core flash attention, plain fp16 Q/K/V (single S pass, single PV).
// CTA = 128 q-rows x one (b,h). 8 warps x 16 rows. 32-key chunks, 3 stages.
// Epilogue: O/l -> packed fp16 [oh|ol], stride 2048 (feeds split final GEMM).
// ---------------------------------------------------------------------------
#define AT_Q   0                        // 128 x 256B = 32768
#define AT_K   32768                    // 3 stages x 8192 (2 subtiles 32x128B)
#define AT_V   (32768 + 24576)          // 3 stages x 8192
#define AT_MK  (AT_V + 24576)           // 3 x 128B mask
#define AT_SMEM (AT_MK + 384)

__global__ void __launch_bounds__(256, 1) attn_tc(
    const __half* __restrict__ Qp, const __half* __restrict__ Kp,
    const __half* __restrict__ Vp, const int* __restrict__ mask,
    __half* __restrict__ OB, int M)
{
    extern __shared__ char dsm[];
    const uint32_t sb = s2u(dsm);
    const int tid = threadIdx.x;
    const int lane = tid & 31;
    const int wrp = tid >> 5;
    const int qrow0 = blockIdx.x * 128;
    const int hd = blockIdx.y;
    const int b = blockIdx.z;

    const char* qg = (const char*)(Qp + (size_t)(b * M + qrow0) * 1024 + hd * 128);
    const char* kg = (const char*)(Kp + (size_t)b * M * 1024 + hd * 128);
    const char* vg = (const char*)(Vp + (size_t)b * M * 1024 + hd * 128);

    // Q resident: 128 rows x 256B = 2048 granules
#pragma unroll
    for (int l = 0; l < 8; l++) {
        int gi = tid + 256 * l;
        int row = gi >> 4, q = gi & 15;
        uint32_t off = (q >> 3) * 16384 + row * 128 + (q & 7) * 16;
        cpasync16(sb + AT_Q + swz(off), qg + (size_t)row * 2048 + q * 16);
    }

    auto load_stage = [&](int c, int s) {
        uint32_t kb = sb + AT_K + s * 8192;
        uint32_t vb = sb + AT_V + s * 8192;
#pragma unroll
        for (int l = 0; l < 2; l++) {
            int gi = tid + 256 * l;
            int row = gi >> 4, q = gi & 15;
            uint32_t off = (q >> 3) * 4096 + row * 128 + (q & 7) * 16;
            cpasync16(kb + swz(off), kg + (size_t)(c * 32 + row) * 2048 + q * 16);
            cpasync16(vb + swz(off), vg + (size_t)(c * 32 + row) * 2048 + q * 16);
        }
        if (tid < 8)
            cpasync16(sb + AT_MK + s * 128 + tid * 16,
                      (const char*)(mask + (size_t)b * M + c * 32) + tid * 16);
        asm volatile("cp.async.commit_group;" ::: "memory");
    };

    load_stage(0, 0);
    load_stage(1, 1);

    const uint32_t aoff = (wrp * 16 + (lane & 15)) * 128 + ((lane >> 4) << 4);
    uint32_t boff[2];
#pragma unroll
    for (int hf = 0; hf < 2; hf++)
        boff[hf] = (hf * 16 + (lane & 7) + ((lane >> 4) << 3)) * 128
                 + (((lane >> 3) & 1) << 4);
    const uint32_t vrow = ((lane & 7) + (((lane >> 3) & 1) << 3)) * 128;
    const uint32_t vcol = ((lane >> 4) << 4);

    float O[16][4];
#pragma unroll
    for (int j = 0; j < 16; j++)
#pragma unroll
        for (int t = 0; t < 4; t++) O[j][t] = 0.f;
    float mi[2] = {-1e30f, -1e30f}, li[2] = {0.f, 0.f};
    const float scaling = 0.08838834764831845f;

    const int NCHA = M / 32;
    for (int c = 0; c < NCHA; c++) {
        if (c < NCHA - 2) asm volatile("cp.async.wait_group 1;" ::: "memory");
        else              asm volatile("cp.async.wait_group 0;" ::: "memory");
        __syncthreads();
        if (c + 2 < NCHA) load_stage(c + 2, (c + 2) % 3);

        const uint32_t Kb = sb + AT_K + (c % 3) * 8192;
        const uint32_t Vb = sb + AT_V + (c % 3) * 8192;
        const int* mk = (const int*)(dsm + AT_MK + (c % 3) * 128);

        // ---- S = Q . Ktile^T  (D = 128) ----
        float cS[4][4];
#pragma unroll
        for (int t = 0; t < 4; t++)
#pragma unroll
            for (int u = 0; u < 4; u++) cS[t][u] = 0.f;
#pragma unroll
        for (int kc = 0; kc < 2; kc++) {
#pragma unroll
            for (int ks = 0; ks < 4; ks++) {
                uint32_t a[4], bb[2][4];
                ldsm_x4(a, sb + AT_Q + swz(kc * 16384 + aoff + ks * 32));
#pragma unroll
                for (int hf = 0; hf < 2; hf++)
                    ldsm_x4(bb[hf], Kb + swz(kc * 4096 + boff[hf] + ks * 32));
#pragma unroll
                for (int hf = 0; hf < 2; hf++) {
                    mma_f16(cS[hf * 2 + 0], a, &bb[hf][0]);
                    mma_f16(cS[hf * 2 + 1], a, &bb[hf][2]);
                }
            }
        }

        // ---- softmax (warp-local rows) ----
#pragma unroll
        for (int t = 0; t < 4; t++) {
            int2 mv = *(const int2*)&mk[t * 8 + ((lane & 3) << 1)];
#pragma unroll
            for (int u = 0; u < 4; u++) {
                float s = cS[t][u] * scaling;
                int mkv = (u & 1) ? mv.y : mv.x;
                cS[t][u] = (mkv == 0) ? -1e9f : s;
            }
        }
        float tmax0 = -1e30f, tmax1 = -1e30f;
#pragma unroll
        for (int t = 0; t < 4; t++) {
            tmax0 = fmaxf(tmax0, fmaxf(cS[t][0], cS[t][1]));
            tmax1 = fmaxf(tmax1, fmaxf(cS[t][2], cS[t][3]));
        }
#pragma unroll
        for (int o = 1; o < 4; o <<= 1) {
            tmax0 = fmaxf(tmax0, __shfl_xor_sync(0xFFFFFFFFu, tmax0, o));
            tmax1 = fmaxf(tmax1, __shfl_xor_sync(0xFFFFFFFFu, tmax1, o));
        }
        float mn0 = fmaxf(mi[0], tmax0), mn1 = fmaxf(mi[1], tmax1);
        float al0 = __expf(mi[0] - mn0), al1 = __expf(mi[1] - mn1);
        mi[0] = mn0; mi[1] = mn1;

        float ps0 = 0.f, ps1 = 0.f;
#pragma unroll
        for (int t = 0; t < 4; t++) {
            cS[t][0] = __expf(cS[t][0] - mn0);
            cS[t][1] = __expf(cS[t][1] - mn0);
            cS[t][2] = __expf(cS[t][2] - mn1);
            cS[t][3] = __expf(cS[t][3] - mn1);
            ps0 += cS[t][0] + cS[t][1];
            ps1 += cS[t][2] + cS[t][3];
        }
#pragma unroll
        for (int o = 1; o < 4; o <<= 1) {
            ps0 += __shfl_xor_sync(0xFFFFFFFFu, ps0, o);
            ps1 += __shfl_xor_sync(0xFFFFFFFFu, ps1, o);
        }
        li[0] = li[0] * al0 + ps0;
        li[1] = li[1] * al1 + ps1;
#pragma unroll
        for (int j = 0; j < 16; j++) {
            O[j][0] *= al0; O[j][1] *= al0;
            O[j][2] *= al1; O[j][3] *= al1;
        }

        // pack P into A fragments (fp16 hi)
        uint32_t ahh[2][4];
#pragma unroll
        for (int ks = 0; ks < 2; ks++) {
#pragma unroll
            for (int sub = 0; sub < 2; sub++) {
                int t = 2 * ks + sub;
                ahh[ks][sub * 2 + 0] = packh2(__float2half(cS[t][0]),
                                              __float2half(cS[t][1]));
                ahh[ks][sub * 2 + 1] = packh2(__float2half(cS[t][2]),
                                              __float2half(cS[t][3]));
            }
        }

        // ---- O += P . V ----
#pragma unroll
        for (int g = 0; g < 8; g++) {
            const int vch = g >> 2;
            const uint32_t colb = (g & 3) * 32 + vcol;
#pragma unroll
            for (int ks = 0; ks < 2; ks++) {
                uint32_t bv[4];
                uint32_t ro = (uint32_t)(ks * 16) * 128 + vrow;
                ldsm_x4_t(bv, Vb + swz(vch * 4096 + ro + colb));
                mma_f16(O[2 * g + 0], ahh[ks], &bv[0]);
                mma_f16(O[2 * g + 1], ahh[ks], &bv[2]);
            }
        }
    }

    // ---- epilogue: O / l, emit packed fp16 [oh|ol] rows (stride 2048) ----
    float inv0 = 1.0f / li[0], inv1 = 1.0f / li[1];
#pragma unroll
    for (int half_ = 0; half_ < 2; half_++) {
        float inv = half_ ? inv1 : inv0;
        int token = b * M + qrow0 + wrp * 16 + (lane >> 2) + half_ * 8;
        size_t rowbase = (size_t)token * 2048 + hd * 128 + ((lane & 3) << 1);
#pragma unroll
        for (int j = 0; j < 16; j++) {
            float v0 = O[j][half_ * 2 + 0] * inv;
            float v1 = O[j][half_ * 2 + 1] * inv;
            __half h0 = __float2half(v0);
            __half h1 = __float2half(v1);
            uint32_t uh = packh2(h0, h1);
            uint32_t ul = packh2(__float2half(v0 - __half2float(h0)),
                                 __float2half(v1 - __half2float(h1)));
            size_t base = rowbase + j * 8;
            *(uint32_t*)(OB + base)        = uh;
            *(uint32_t*)(OB + base + 1024) = ul;
        }
    }
}

// ---------------------------------------------------------------------------
// Launch sequence (single stream, graph-capturable: kernel launches only)
// ---------------------------------------------------------------------------
extern "C" void kernel_launch(void* const* d_in, const int* in_sizes, int n_in,
                              void* d_out, int out_size)
{
    const float* query  = (const float*)d_in[0];
    const float* key    = (const float*)d_in[1];
    const int*   mask   = (const int*)d_in[2];
    // d_in[3] = value1, intentionally unused (matches reference)
    const float* value2 = (const float*)d_in[4];
    const float* Wq = (const float*)d_in[5];
    const float* bq = (const float*)d_in[6];
    const float* gq = (const float*)d_in[7];
    const float* betaq = (const float*)d_in[8];
    const float* Wk = (const float*)d_in[9];
    const float* bk = (const float*)d_in[10];
    const float* gk = (const float*)d_in[11];
    const float* betak = (const float*)d_in[12];
    const float* Wv = (const float*)d_in[13];
    const float* bv = (const float*)d_in[14];
    const float* gv = (const float*)d_in[15];
    const float* betav = (const float*)d_in[16];
    const float* Wm = (const float*)d_in[17];
    const float* bm = (const float*)d_in[18];

    const int B = in_sizes[3] / EDIM;   // value1 is [B, E]
    const int Ntok = in_sizes[2];       // mask is [B, M]
    const int M = Ntok / B;

    __half *ah, *wh, *qp, *kp, *vp;
    cudaGetSymbolAddress((void**)&ah, g_ah);
    cudaGetSymbolAddress((void**)&wh, g_wh);
    cudaGetSymbolAddress((void**)&qp, g_qp);
    cudaGetSymbolAddress((void**)&kp, g_kp);
    cudaGetSymbolAddress((void**)&vp, g_vp);

    cudaFuncSetAttribute(gemm_tc<0>, cudaFuncAttributeMaxDynamicSharedMemorySize, GEMM_SMEM);
    cudaFuncSetAttribute(gemm_tc<1>, cudaFuncAttributeMaxDynamicSharedMemorySize, GEMM_SMEM);
    cudaFuncSetAttribute(attn_tc, cudaFuncAttributeMaxDynamicSharedMemorySize, AT_SMEM);

    dim3 blk(256);
    dim3 gg(EDIM / 128, Ntok / 128);

    convert1h<<<EDIM, 256>>>(Wq, wh);
    convert1h<<<Ntok, 256>>>(query, ah);
    gemm_tc<1><<<gg, blk, GEMM_SMEM>>>(ah, wh, bq, gq, betaq, qp);

    convert1h<<<EDIM, 256>>>(Wk, wh);
    convert1h<<<Ntok, 256>>>(key, ah);
    gemm_tc<1><<<gg, blk, GEMM_SMEM>>>(ah, wh, bk, gk, betak, kp);

    convert1h<<<EDIM, 256>>>(Wv, wh);
    convert1h<<<Ntok, 256>>>(value2, ah);
    gemm_tc<1><<<gg, blk, GEMM_SMEM>>>(ah, wh, bv, gv, betav, vp);

    dim3 ga(M / 128, HEADS, B);
    attn_tc<<<ga, blk, AT_SMEM>>>(qp, kp, vp, mask, ah, M);

    convert2w<<<EDIM, 256>>>(Wm, wh);
    gemm_tc<0><<<gg, blk, GEMM_SMEM>>>(ah, wh, bm, nullptr, nullptr, d_out);
}

// round 8
// speedup vs baseline: 8.3506x; 1.1671x over previous
#include <cuda_runtime.h>
#include <cuda_fp16.h>
#include <cstdint>

// Problem constants (fixed by dataset): B=32, M=1024, E=1024, H=8, D=128
#define EDIM 1024
#define HEADS 8
#define DHEAD 128
#define MAXTOK 32768

// Scratch (__device__ globals: allocation-free rule)
__device__ __half g_ah[(size_t)MAXTOK * 1024];   // fp16 activations / attn out
__device__ __half g_wh[(size_t)EDIM * 1024];     // W fp16
__device__ __half g_qp[(size_t)MAXTOK * 1024];   // Q fp16/head (128/head)
__device__ __half g_kp[(size_t)MAXTOK * 1024];   // K fp16/head
__device__ __half g_vp[(size_t)MAXTOK * 1024];   // V fp16/head

// ---------------------------------------------------------------------------
// helpers (baseline PTX only: works on non-'a' sm_103 target)
// ---------------------------------------------------------------------------
__device__ __forceinline__ uint32_t s2u(const void* p) {
    uint32_t a;
    asm("{ .reg .u64 t; cvta.to.shared.u64 t, %1; cvt.u32.u64 %0, t; }"
        : "=r"(a) : "l"(p));
    return a;
}
__device__ __forceinline__ void ldsm_x4(uint32_t* r, uint32_t addr) {
    asm volatile("ldmatrix.sync.aligned.m8n8.x4.shared.b16 {%0,%1,%2,%3}, [%4];"
        : "=r"(r[0]), "=r"(r[1]), "=r"(r[2]), "=r"(r[3]) : "r"(addr));
}
__device__ __forceinline__ void ldsm_x4_t(uint32_t* r, uint32_t addr) {
    asm volatile("ldmatrix.sync.aligned.m8n8.x4.trans.shared.b16 {%0,%1,%2,%3}, [%4];"
        : "=r"(r[0]), "=r"(r[1]), "=r"(r[2]), "=r"(r[3]) : "r"(addr));
}
__device__ __forceinline__ void mma_f16(float* d, const uint32_t* a,
                                        const uint32_t* b) {
    asm volatile("mma.sync.aligned.m16n8k16.row.col.f32.f16.f16.f32 "
        "{%0,%1,%2,%3}, {%4,%5,%6,%7}, {%8,%9}, {%0,%1,%2,%3};"
        : "+f"(d[0]), "+f"(d[1]), "+f"(d[2]), "+f"(d[3])
        : "r"(a[0]), "r"(a[1]), "r"(a[2]), "r"(a[3]), "r"(b[0]), "r"(b[1]));
}
__device__ __forceinline__ void cpasync16(uint32_t dst, const void* src) {
    asm volatile("cp.async.cg.shared.global [%0], [%1], 16;"
                 :: "r"(dst), "l"(src) : "memory");
}
__device__ __forceinline__ uint32_t packh2(__half lo, __half hi) {
    __half2 t; t.x = lo; t.y = hi;
    return *reinterpret_cast<uint32_t*>(&t);
}
__device__ __forceinline__ uint32_t swz(uint32_t off) {
    return off ^ ((off >> 3) & 0x70);
}

// ---------------------------------------------------------------------------
// fp32 -> fp16 plain, row stride 1024 (all activations + all weights)
// ---------------------------------------------------------------------------
__global__ void convert1h(const float* __restrict__ in,
                          __half* __restrict__ out) {
    size_t i = ((size_t)blockIdx.x * 256 + threadIdx.x) * 4;
    float4 v = *(const float4*)(in + i);
    *(uint32_t*)(out + i)     = packh2(__float2half(v.x), __float2half(v.y));
    *(uint32_t*)(out + i + 2) = packh2(__float2half(v.z), __float2half(v.w));
}

// ---------------------------------------------------------------------------
// HMMA fp16 GEMM: CTA 128x128, K=1024, BK=64 (128B rows), 3-stage cp.async.
// MODE 0: +bias -> fp32 out (final projection)
// MODE 1: +bias+CELU+GN -> plain fp16 per-head (q/k/v projections)
// ---------------------------------------------------------------------------
#define STAGE_BYTES 32768
#define GEMM_SMEM (3 * STAGE_BYTES + 2048)
#define KEL 1024
#define NCHT 16

template <int MODE>
__global__ void __launch_bounds__(256, 2) gemm_tc(
    const __half* __restrict__ Av, const __half* __restrict__ Wv,
    const float* __restrict__ bias, const float* __restrict__ gamma,
    const float* __restrict__ beta, void* __restrict__ out)
{
    constexpr bool GN = (MODE == 1);
    extern __shared__ char dsm[];
    const uint32_t sb = s2u(dsm);
    const int tid = threadIdx.x;
    const int lane = tid & 31;
    const int wrp = tid >> 5;
    const int wm = wrp & 1;
    const int wn = wrp >> 1;
    const int row0 = blockIdx.y << 7;
    const int col0 = blockIdx.x << 7;

    float* sp = (float*)(dsm + 3 * STAGE_BYTES);
    if (tid < 128) {
        sp[tid] = bias[col0 + tid];
        if (GN) {
            sp[128 + tid] = gamma[col0 + tid];
            sp[256 + tid] = beta[col0 + tid];
        }
    }

    const int gr = tid >> 3;
    const int q16 = (tid & 7) << 4;
    const size_t rstride = (size_t)KEL * 2;
    const char* Agp = (const char*)Av + (size_t)row0 * rstride + q16;
    const char* Bgp = (const char*)Wv + (size_t)col0 * rstride + q16;

    auto load_stage = [&](int c, int s) {
        uint32_t Ab = sb + s * STAGE_BYTES;
        uint32_t Bb = Ab + 16384;
#pragma unroll
        for (int l = 0; l < 4; l++) {
            int r = gr + (l << 5);
            uint32_t sw = swz((r << 7) + q16);
            cpasync16(Ab + sw, Agp + (size_t)r * rstride + (size_t)c * 128);
            cpasync16(Bb + sw, Bgp + (size_t)r * rstride + (size_t)c * 128);
        }
        asm volatile("cp.async.commit_group;" ::: "memory");
    };

    load_stage(0, 0);
    load_stage(1, 1);

    uint32_t abase[4];
#pragma unroll
    for (int i = 0; i < 4; i++) {
        int row = wm * 64 + i * 16 + (lane & 15);
        abase[i] = (row << 7) + ((lane >> 4) << 4);
    }
    uint32_t bbase[2];
#pragma unroll
    for (int j2 = 0; j2 < 2; j2++) {
        int row = wn * 32 + j2 * 16 + (lane & 7) + ((lane >> 4) << 3);
        bbase[j2] = (row << 7) + (((lane >> 3) & 1) << 4);
    }

    float acc[4][4][4];
#pragma unroll
    for (int i = 0; i < 4; i++)
#pragma unroll
        for (int j = 0; j < 4; j++)
#pragma unroll
            for (int t = 0; t < 4; t++) acc[i][j][t] = 0.f;

    for (int c = 0; c < NCHT; c++) {
        if (c < NCHT - 2) asm volatile("cp.async.wait_group 1;" ::: "memory");
        else              asm volatile("cp.async.wait_group 0;" ::: "memory");
        __syncthreads();
        if (c + 2 < NCHT) load_stage(c + 2, (c + 2) % 3);

        const uint32_t Ab = sb + (c % 3) * STAGE_BYTES;
        const uint32_t Bb = Ab + 16384;
#pragma unroll
        for (int ks = 0; ks < 4; ks++) {
            const int kb = ks << 5;
            uint32_t a[4][4], b[2][4];
#pragma unroll
            for (int i = 0; i < 4; i++)
                ldsm_x4(a[i], Ab + swz(abase[i] + kb));
#pragma unroll
            for (int j2 = 0; j2 < 2; j2++)
                ldsm_x4(b[j2], Bb + swz(bbase[j2] + kb));
#pragma unroll
            for (int i = 0; i < 4; i++)
#pragma unroll
                for (int j2 = 0; j2 < 2; j2++) {
                    mma_f16(acc[i][j2 * 2 + 0], a[i], &b[j2][0]);
                    mma_f16(acc[i][j2 * 2 + 1], a[i], &b[j2][2]);
                }
        }
        __syncthreads();
    }

    // ---------------- epilogue ----------------
    const int lr = lane >> 2;
    const int lc = (lane & 3) << 1;
    const int hd = col0 >> 7;   // head index (proj mode)

    if (GN) {
        float* redS = (float*)dsm;
        float* redQ = redS + 512;
#pragma unroll
        for (int i = 0; i < 4; i++) {
            float s0 = 0.f, q0 = 0.f, s1 = 0.f, q1 = 0.f;
#pragma unroll
            for (int j = 0; j < 4; j++) {
                int cl = wn * 32 + j * 8 + lc;
#pragma unroll
                for (int t = 0; t < 4; t++) {
                    float v = acc[i][j][t] + sp[cl + (t & 1)];
                    v = v > 0.f ? v : 1.3f * expm1f(v * (1.0f / 1.3f));
                    acc[i][j][t] = v;
                    if (t < 2) { s0 += v; q0 += v * v; }
                    else       { s1 += v; q1 += v * v; }
                }
            }
#pragma unroll
            for (int o = 1; o < 4; o <<= 1) {
                s0 += __shfl_xor_sync(0xFFFFFFFFu, s0, o);
                q0 += __shfl_xor_sync(0xFFFFFFFFu, q0, o);
                s1 += __shfl_xor_sync(0xFFFFFFFFu, s1, o);
                q1 += __shfl_xor_sync(0xFFFFFFFFu, q1, o);
            }
            if ((lane & 3) == 0) {
                int r = wm * 64 + i * 16 + lr;
                redS[r * 4 + wn] = s0;  redQ[r * 4 + wn] = q0;
                redS[(r + 8) * 4 + wn] = s1;  redQ[(r + 8) * 4 + wn] = q1;
            }
        }
        __syncthreads();
        __half* ob = (__half*)out;
#pragma unroll
        for (int i = 0; i < 4; i++) {
            int rbase = wm * 64 + i * 16 + lr;
#pragma unroll
            for (int half_ = 0; half_ < 2; half_++) {
                int r = rbase + half_ * 8;
                float s = redS[r * 4] + redS[r * 4 + 1] + redS[r * 4 + 2] + redS[r * 4 + 3];
                float q = redQ[r * 4] + redQ[r * 4 + 1] + redQ[r * 4 + 2] + redQ[r * 4 + 3];
                float mean = s * (1.f / 128.f);
                float var = q * (1.f / 128.f) - mean * mean;
                float rs = rsqrtf(var + 1e-5f);
                int token = row0 + r;
#pragma unroll
                for (int j = 0; j < 4; j++) {
                    int cl = wn * 32 + j * 8 + lc;
                    float v0 = (acc[i][j][half_ * 2 + 0] - mean) * rs * sp[128 + cl]
                             + sp[256 + cl];
                    float v1 = (acc[i][j][half_ * 2 + 1] - mean) * rs * sp[128 + cl + 1]
                             + sp[256 + cl + 1];
                    size_t base = (size_t)token * 1024 + hd * 128 + cl;
                    *(uint32_t*)(ob + base) = packh2(__float2half(v0),
                                                     __float2half(v1));
                }
            }
        }
    } else {
        float* C = (float*)out;
#pragma unroll
        for (int i = 0; i < 4; i++) {
#pragma unroll
            for (int half_ = 0; half_ < 2; half_++) {
                int r = wm * 64 + i * 16 + lr + half_ * 8;
                float* crow = C + (size_t)(row0 + r) * EDIM + col0;
#pragma unroll
                for (int j = 0; j < 4; j++) {
                    int cl = wn * 32 + j * 8 + lc;
                    float2 ov;
                    ov.x = acc[i][j][half_ * 2 + 0] + sp[cl];
                    ov.y = acc[i][j][half_ * 2 + 1] + sp[cl + 1];
                    *(float2*)(crow + cl) = ov;
                }
            }
        }
    }
}

// ---------------------------------------------------------------------------
// Tensor-core flash attention, plain fp16 Q/K/V, 2 CTAs/SM.
// CTA = 128 q-rows x one (b,h). 8 warps x 16 rows. 32-key chunks, 3 stages.
// Epilogue: O/l -> plain fp16, stride 1024 (feeds single-pass final GEMM).
// ---------------------------------------------------------------------------
#define AT_Q   0                        // 128 x 256B = 32768
#define AT_K   32768                    // 3 stages x 8192 (2 subtiles 32x128B)
#define AT_V   (32768 + 24576)          // 3 stages x 8192
#define AT_MK  (AT_V + 24576)           // 3 x 128B mask
#define AT_SMEM (AT_MK + 384)

__global__ void __launch_bounds__(256, 2) attn_tc(
    const __half* __restrict__ Qp, const __half* __restrict__ Kp,
    const __half* __restrict__ Vp, const int* __restrict__ mask,
    __half* __restrict__ OB, int M)
{
    extern __shared__ char dsm[];
    const uint32_t sb = s2u(dsm);
    const int tid = threadIdx.x;
    const int lane = tid & 31;
    const int wrp = tid >> 5;
    const int qrow0 = blockIdx.x * 128;
    const int hd = blockIdx.y;
    const int b = blockIdx.z;

    const char* qg = (const char*)(Qp + (size_t)(b * M + qrow0) * 1024 + hd * 128);
    const char* kg = (const char*)(Kp + (size_t)b * M * 1024 + hd * 128);
    const char* vg = (const char*)(Vp + (size_t)b * M * 1024 + hd * 128);

    // Q resident: 128 rows x 256B = 2048 granules
#pragma unroll
    for (int l = 0; l < 8; l++) {
        int gi = tid + 256 * l;
        int row = gi >> 4, q = gi & 15;
        uint32_t off = (q >> 3) * 16384 + row * 128 + (q & 7) * 16;
        cpasync16(sb + AT_Q + swz(off), qg + (size_t)row * 2048 + q * 16);
    }

    auto load_stage = [&](int c, int s) {
        uint32_t kb = sb + AT_K + s * 8192;
        uint32_t vb = sb + AT_V + s * 8192;
#pragma unroll
        for (int l = 0; l < 2; l++) {
            int gi = tid + 256 * l;
            int row = gi >> 4, q = gi & 15;
            uint32_t off = (q >> 3) * 4096 + row * 128 + (q & 7) * 16;
            cpasync16(kb + swz(off), kg + (size_t)(c * 32 + row) * 2048 + q * 16);
            cpasync16(vb + swz(off), vg + (size_t)(c * 32 + row) * 2048 + q * 16);
        }
        if (tid < 8)
            cpasync16(sb + AT_MK + s * 128 + tid * 16,
                      (const char*)(mask + (size_t)b * M + c * 32) + tid * 16);
        asm volatile("cp.async.commit_group;" ::: "memory");
    };

    load_stage(0, 0);
    load_stage(1, 1);

    const uint32_t aoff = (wrp * 16 + (lane & 15)) * 128 + ((lane >> 4) << 4);
    uint32_t boff[2];
#pragma unroll
    for (int hf = 0; hf < 2; hf++)
        boff[hf] = (hf * 16 + (lane & 7) + ((lane >> 4) << 3)) * 128
                 + (((lane >> 3) & 1) << 4);
    const uint32_t vrow = ((lane & 7) + (((lane >> 3) & 1) << 3)) * 128;
    const uint32_t vcol = ((lane >> 4) << 4);

    float O[16][4];
#pragma unroll
    for (int j = 0; j < 16; j++)
#pragma unroll
        for (int t = 0; t < 4; t++) O[j][t] = 0.f;
    float mi[2] = {-1e30f, -1e30f}, li[2] = {0.f, 0.f};
    const float scaling = 0.08838834764831845f;

    const int NCHA = M / 32;
    for (int c = 0; c < NCHA; c++) {
        if (c < NCHA - 2) asm volatile("cp.async.wait_group 1;" ::: "memory");
        else              asm volatile("cp.async.wait_group 0;" ::: "memory");
        __syncthreads();
        if (c + 2 < NCHA) load_stage(c + 2, (c + 2) % 3);

        const uint32_t Kb = sb + AT_K + (c % 3) * 8192;
        const uint32_t Vb = sb + AT_V + (c % 3) * 8192;
        const int* mk = (const int*)(dsm + AT_MK + (c % 3) * 128);

        // ---- S = Q . Ktile^T  (D = 128) ----
        float cS[4][4];
#pragma unroll
        for (int t = 0; t < 4; t++)
#pragma unroll
            for (int u = 0; u < 4; u++) cS[t][u] = 0.f;
#pragma unroll
        for (int kc = 0; kc < 2; kc++) {
#pragma unroll
            for (int ks = 0; ks < 4; ks++) {
                uint32_t a[4], bb[2][4];
                ldsm_x4(a, sb + AT_Q + swz(kc * 16384 + aoff + ks * 32));
#pragma unroll
                for (int hf = 0; hf < 2; hf++)
                    ldsm_x4(bb[hf], Kb + swz(kc * 4096 + boff[hf] + ks * 32));
#pragma unroll
                for (int hf = 0; hf < 2; hf++) {
                    mma_f16(cS[hf * 2 + 0], a, &bb[hf][0]);
                    mma_f16(cS[hf * 2 + 1], a, &bb[hf][2]);
                }
            }
        }

        // ---- softmax (warp-local rows) ----
#pragma unroll
        for (int t = 0; t < 4; t++) {
            int2 mv = *(const int2*)&mk[t * 8 + ((lane & 3) << 1)];
#pragma unroll
            for (int u = 0; u < 4; u++) {
                float s = cS[t][u] * scaling;
                int mkv = (u & 1) ? mv.y : mv.x;
                cS[t][u] = (mkv == 0) ? -1e9f : s;
            }
        }
        float tmax0 = -1e30f, tmax1 = -1e30f;
#pragma unroll
        for (int t = 0; t < 4; t++) {
            tmax0 = fmaxf(tmax0, fmaxf(cS[t][0], cS[t][1]));
            tmax1 = fmaxf(tmax1, fmaxf(cS[t][2], cS[t][3]));
        }
#pragma unroll
        for (int o = 1; o < 4; o <<= 1) {
            tmax0 = fmaxf(tmax0, __shfl_xor_sync(0xFFFFFFFFu, tmax0, o));
            tmax1 = fmaxf(tmax1, __shfl_xor_sync(0xFFFFFFFFu, tmax1, o));
        }
        float mn0 = fmaxf(mi[0], tmax0), mn1 = fmaxf(mi[1], tmax1);
        float al0 = __expf(mi[0] - mn0), al1 = __expf(mi[1] - mn1);
        mi[0] = mn0; mi[1] = mn1;

        float ps0 = 0.f, ps1 = 0.f;
#pragma unroll
        for (int t = 0; t < 4; t++) {
            cS[t][0] = __expf(cS[t][0] - mn0);
            cS[t][1] = __expf(cS[t][1] - mn0);
            cS[t][2] = __expf(cS[t][2] - mn1);
            cS[t][3] = __expf(cS[t][3] - mn1);
            ps0 += cS[t][0] + cS[t][1];
            ps1 += cS[t][2] + cS[t][3];
        }
#pragma unroll
        for (int o = 1; o < 4; o <<= 1) {
            ps0 += __shfl_xor_sync(0xFFFFFFFFu, ps0, o);
            ps1 += __shfl_xor_sync(0xFFFFFFFFu, ps1, o);
        }
        li[0] = li[0] * al0 + ps0;
        li[1] = li[1] * al1 + ps1;
#pragma unroll
        for (int j = 0; j < 16; j++) {
            O[j][0] *= al0; O[j][1] *= al0;
            O[j][2] *= al1; O[j][3] *= al1;
        }

        // pack P into A fragments (fp16)
        uint32_t ahh[2][4];
#pragma unroll
        for (int ks = 0; ks < 2; ks++) {
#pragma unroll
            for (int sub = 0; sub < 2; sub++) {
                int t = 2 * ks + sub;
                ahh[ks][sub * 2 + 0] = packh2(__float2half(cS[t][0]),
                                              __float2half(cS[t][1]));
                ahh[ks][sub * 2 + 1] = packh2(__float2half(cS[t][2]),
                                              __float2half(cS[t][3]));
            }
        }

        // ---- O += P . V ----
#pragma unroll
        for (int g = 0; g < 8; g++) {
            const int vch = g >> 2;
            const uint32_t colb = (g & 3) * 32 + vcol;
#pragma unroll
            for (int ks = 0; ks < 2; ks++) {
                uint32_t bv[4];
                uint32_t ro = (uint32_t)(ks * 16) * 128 + vrow;
                ldsm_x4_t(bv, Vb + swz(vch * 4096 + ro + colb));
                mma_f16(O[2 * g + 0], ahh[ks], &bv[0]);
                mma_f16(O[2 * g + 1], ahh[ks], &bv[2]);
            }
        }
    }

    // ---- epilogue: O / l, plain fp16 rows (stride 1024) ----
    float inv0 = 1.0f / li[0], inv1 = 1.0f / li[1];
#pragma unroll
    for (int half_ = 0; half_ < 2; half_++) {
        float inv = half_ ? inv1 : inv0;
        int token = b * M + qrow0 + wrp * 16 + (lane >> 2) + half_ * 8;
        size_t rowbase = (size_t)token * 1024 + hd * 128 + ((lane & 3) << 1);
#pragma unroll
        for (int j = 0; j < 16; j++) {
            float v0 = O[j][half_ * 2 + 0] * inv;
            float v1 = O[j][half_ * 2 + 1] * inv;
            *(uint32_t*)(OB + rowbase + j * 8) = packh2(__float2half(v0),
                                                        __float2half(v1));
        }
    }
}

// ---------------------------------------------------------------------------
// Launch sequence (single stream, graph-capturable: kernel launches only)
// ---------------------------------------------------------------------------
extern "C" void kernel_launch(void* const* d_in, const int* in_sizes, int n_in,
                              void* d_out, int out_size)
{
    const float* query  = (const float*)d_in[0];
    const float* key    = (const float*)d_in[1];
    const int*   mask   = (const int*)d_in[2];
    // d_in[3] = value1, intentionally unused (matches reference)
    const float* value2 = (const float*)d_in[4];
    const float* Wq = (const float*)d_in[5];
    const float* bq = (const float*)d_in[6];
    const float* gq = (const float*)d_in[7];
    const float* betaq = (const float*)d_in[8];
    const float* Wk = (const float*)d_in[9];
    const float* bk = (const float*)d_in[10];
    const float* gk = (const float*)d_in[11];
    const float* betak = (const float*)d_in[12];
    const float* Wv = (const float*)d_in[13];
    const float* bv = (const float*)d_in[14];
    const float* gv = (const float*)d_in[15];
    const float* betav = (const float*)d_in[16];
    const float* Wm = (const float*)d_in[17];
    const float* bm = (const float*)d_in[18];

    const int B = in_sizes[3] / EDIM;   // value1 is [B, E]
    const int Ntok = in_sizes[2];       // mask is [B, M]
    const int M = Ntok / B;

    __half *ah, *wh, *qp, *kp, *vp;
    cudaGetSymbolAddress((void**)&ah, g_ah);
    cudaGetSymbolAddress((void**)&wh, g_wh);
    cudaGetSymbolAddress((void**)&qp, g_qp);
    cudaGetSymbolAddress((void**)&kp, g_kp);
    cudaGetSymbolAddress((void**)&vp, g_vp);

    cudaFuncSetAttribute(gemm_tc<0>, cudaFuncAttributeMaxDynamicSharedMemorySize, GEMM_SMEM);
    cudaFuncSetAttribute(gemm_tc<1>, cudaFuncAttributeMaxDynamicSharedMemorySize, GEMM_SMEM);
    cudaFuncSetAttribute(attn_tc, cudaFuncAttributeMaxDynamicSharedMemorySize, AT_SMEM);

    dim3 blk(256);
    dim3 gg(EDIM / 128, Ntok / 128);

    convert1h<<<EDIM, 256>>>(Wq, wh);
    convert1h<<<Ntok, 256>>>(query, ah);
    gemm_tc<1><<<gg, blk, GEMM_SMEM>>>(ah, wh, bq, gq, betaq, qp);

    convert1h<<<EDIM, 256>>>(Wk, wh);
    convert1h<<<Ntok, 256>>>(key, ah);
    gemm_tc<1><<<gg, blk, GEMM_SMEM>>>(ah, wh, bk, gk, betak, kp);

    convert1h<<<EDIM, 256>>>(Wv, wh);
    convert1h<<<Ntok, 256>>>(value2, ah);
    gemm_tc<1><<<gg, blk, GEMM_SMEM>>>(ah, wh, bv, gv, betav, vp);

    dim3 ga(M / 128, HEADS, B);
    attn_tc<<<ga, blk, AT_SMEM>>>(qp, kp, vp, mask, ah, M);

    convert1h<<<EDIM, 256>>>(Wm, wh);
    gemm_tc<0><<<gg, blk, GEMM_SMEM>>>(ah, wh, bm, nullptr, nullptr, d_out);
}

// round 9
// speedup vs baseline: 8.6968x; 1.0414x over previous
#include <cuda_runtime.h>
#include <cuda_fp16.h>
#include <cstdint>

// Problem constants (fixed by dataset): B=32, M=1024, E=1024, H=8, D=128
#define EDIM 1024
#define HEADS 8
#define DHEAD 128
#define MAXTOK 32768

// Scratch (__device__ globals: allocation-free rule). Separate buffers per
// chain so Q/K/V pipelines can run concurrently on forked streams.
__device__ __half g_aq[(size_t)MAXTOK * 1024];   // query fp16
__device__ __half g_ak[(size_t)MAXTOK * 1024];   // key fp16
__device__ __half g_av[(size_t)MAXTOK * 1024];   // value2 fp16
__device__ __half g_ao[(size_t)MAXTOK * 1024];   // attention output fp16
__device__ __half g_wq2[(size_t)EDIM * 1024];    // Wq fp16
__device__ __half g_wk2[(size_t)EDIM * 1024];    // Wk fp16
__device__ __half g_wv2[(size_t)EDIM * 1024];    // Wv fp16
__device__ __half g_wm2[(size_t)EDIM * 1024];    // Wm fp16
__device__ __half g_qp[(size_t)MAXTOK * 1024];   // Q proj (128/head)
__device__ __half g_kp[(size_t)MAXTOK * 1024];   // K proj
__device__ __half g_vp[(size_t)MAXTOK * 1024];   // V proj

// ---------------------------------------------------------------------------
// helpers (baseline PTX only: works on non-'a' sm_103 target)
// ---------------------------------------------------------------------------
__device__ __forceinline__ uint32_t s2u(const void* p) {
    uint32_t a;
    asm("{ .reg .u64 t; cvta.to.shared.u64 t, %1; cvt.u32.u64 %0, t; }"
        : "=r"(a) : "l"(p));
    return a;
}
__device__ __forceinline__ void ldsm_x4(uint32_t* r, uint32_t addr) {
    asm volatile("ldmatrix.sync.aligned.m8n8.x4.shared.b16 {%0,%1,%2,%3}, [%4];"
        : "=r"(r[0]), "=r"(r[1]), "=r"(r[2]), "=r"(r[3]) : "r"(addr));
}
__device__ __forceinline__ void ldsm_x4_t(uint32_t* r, uint32_t addr) {
    asm volatile("ldmatrix.sync.aligned.m8n8.x4.trans.shared.b16 {%0,%1,%2,%3}, [%4];"
        : "=r"(r[0]), "=r"(r[1]), "=r"(r[2]), "=r"(r[3]) : "r"(addr));
}
__device__ __forceinline__ void mma_f16(float* d, const uint32_t* a,
                                        const uint32_t* b) {
    asm volatile("mma.sync.aligned.m16n8k16.row.col.f32.f16.f16.f32 "
        "{%0,%1,%2,%3}, {%4,%5,%6,%7}, {%8,%9}, {%0,%1,%2,%3};"
        : "+f"(d[0]), "+f"(d[1]), "+f"(d[2]), "+f"(d[3])
        : "r"(a[0]), "r"(a[1]), "r"(a[2]), "r"(a[3]), "r"(b[0]), "r"(b[1]));
}
__device__ __forceinline__ void cpasync16(uint32_t dst, const void* src) {
    asm volatile("cp.async.cg.shared.global [%0], [%1], 16;"
                 :: "r"(dst), "l"(src) : "memory");
}
__device__ __forceinline__ uint32_t packh2(__half lo, __half hi) {
    __half2 t; t.x = lo; t.y = hi;
    return *reinterpret_cast<uint32_t*>(&t);
}
__device__ __forceinline__ uint32_t swz(uint32_t off) {
    return off ^ ((off >> 3) & 0x70);
}

// ---------------------------------------------------------------------------
// fp32 -> fp16 plain, 8 elements per thread
// ---------------------------------------------------------------------------
__global__ void convert1h(const float* __restrict__ in,
                          __half* __restrict__ out) {
    size_t i = ((size_t)blockIdx.x * 256 + threadIdx.x) * 8;
    float4 a = *(const float4*)(in + i);
    float4 b = *(const float4*)(in + i + 4);
    *(uint32_t*)(out + i)     = packh2(__float2half(a.x), __float2half(a.y));
    *(uint32_t*)(out + i + 2) = packh2(__float2half(a.z), __float2half(a.w));
    *(uint32_t*)(out + i + 4) = packh2(__float2half(b.x), __float2half(b.y));
    *(uint32_t*)(out + i + 6) = packh2(__float2half(b.z), __float2half(b.w));
}

// ---------------------------------------------------------------------------
// HMMA fp16 GEMM: CTA 128x128, K=1024, BK=64 (128B rows), 3-stage cp.async.
// MODE 0: +bias -> fp32 out (final projection)
// MODE 1: +bias+CELU+GN -> plain fp16 per-head (q/k/v projections)
// ---------------------------------------------------------------------------
#define STAGE_BYTES 32768
#define GEMM_SMEM (3 * STAGE_BYTES + 2048)
#define KEL 1024
#define NCHT 16

template <int MODE>
__global__ void __launch_bounds__(256, 2) gemm_tc(
    const __half* __restrict__ Av, const __half* __restrict__ Wv,
    const float* __restrict__ bias, const float* __restrict__ gamma,
    const float* __restrict__ beta, void* __restrict__ out)
{
    constexpr bool GN = (MODE == 1);
    extern __shared__ char dsm[];
    const uint32_t sb = s2u(dsm);
    const int tid = threadIdx.x;
    const int lane = tid & 31;
    const int wrp = tid >> 5;
    const int wm = wrp & 1;
    const int wn = wrp >> 1;
    const int row0 = blockIdx.y << 7;
    const int col0 = blockIdx.x << 7;

    float* sp = (float*)(dsm + 3 * STAGE_BYTES);
    if (tid < 128) {
        sp[tid] = bias[col0 + tid];
        if (GN) {
            sp[128 + tid] = gamma[col0 + tid];
            sp[256 + tid] = beta[col0 + tid];
        }
    }

    const int gr = tid >> 3;
    const int q16 = (tid & 7) << 4;
    const size_t rstride = (size_t)KEL * 2;
    const char* Agp = (const char*)Av + (size_t)row0 * rstride + q16;
    const char* Bgp = (const char*)Wv + (size_t)col0 * rstride + q16;

    auto load_stage = [&](int c, int s) {
        uint32_t Ab = sb + s * STAGE_BYTES;
        uint32_t Bb = Ab + 16384;
#pragma unroll
        for (int l = 0; l < 4; l++) {
            int r = gr + (l << 5);
            uint32_t sw = swz((r << 7) + q16);
            cpasync16(Ab + sw, Agp + (size_t)r * rstride + (size_t)c * 128);
            cpasync16(Bb + sw, Bgp + (size_t)r * rstride + (size_t)c * 128);
        }
        asm volatile("cp.async.commit_group;" ::: "memory");
    };

    load_stage(0, 0);
    load_stage(1, 1);

    uint32_t abase[4];
#pragma unroll
    for (int i = 0; i < 4; i++) {
        int row = wm * 64 + i * 16 + (lane & 15);
        abase[i] = (row << 7) + ((lane >> 4) << 4);
    }
    uint32_t bbase[2];
#pragma unroll
    for (int j2 = 0; j2 < 2; j2++) {
        int row = wn * 32 + j2 * 16 + (lane & 7) + ((lane >> 4) << 3);
        bbase[j2] = (row << 7) + (((lane >> 3) & 1) << 4);
    }

    float acc[4][4][4];
#pragma unroll
    for (int i = 0; i < 4; i++)
#pragma unroll
        for (int j = 0; j < 4; j++)
#pragma unroll
            for (int t = 0; t < 4; t++) acc[i][j][t] = 0.f;

    for (int c = 0; c < NCHT; c++) {
        if (c < NCHT - 2) asm volatile("cp.async.wait_group 1;" ::: "memory");
        else              asm volatile("cp.async.wait_group 0;" ::: "memory");
        __syncthreads();
        if (c + 2 < NCHT) load_stage(c + 2, (c + 2) % 3);

        const uint32_t Ab = sb + (c % 3) * STAGE_BYTES;
        const uint32_t Bb = Ab + 16384;
#pragma unroll
        for (int ks = 0; ks < 4; ks++) {
            const int kb = ks << 5;
            uint32_t a[4][4], b[2][4];
#pragma unroll
            for (int i = 0; i < 4; i++)
                ldsm_x4(a[i], Ab + swz(abase[i] + kb));
#pragma unroll
            for (int j2 = 0; j2 < 2; j2++)
                ldsm_x4(b[j2], Bb + swz(bbase[j2] + kb));
#pragma unroll
            for (int i = 0; i < 4; i++)
#pragma unroll
                for (int j2 = 0; j2 < 2; j2++) {
                    mma_f16(acc[i][j2 * 2 + 0], a[i], &b[j2][0]);
                    mma_f16(acc[i][j2 * 2 + 1], a[i], &b[j2][2]);
                }
        }
        __syncthreads();
    }

    // ---------------- epilogue ----------------
    const int lr = lane >> 2;
    const int lc = (lane & 3) << 1;
    const int hd = col0 >> 7;   // head index (proj mode)

    if (GN) {
        float* redS = (float*)dsm;
        float* redQ = redS + 512;
#pragma unroll
        for (int i = 0; i < 4; i++) {
            float s0 = 0.f, q0 = 0.f, s1 = 0.f, q1 = 0.f;
#pragma unroll
            for (int j = 0; j < 4; j++) {
                int cl = wn * 32 + j * 8 + lc;
#pragma unroll
                for (int t = 0; t < 4; t++) {
                    float v = acc[i][j][t] + sp[cl + (t & 1)];
                    v = v > 0.f ? v : 1.3f * expm1f(v * (1.0f / 1.3f));
                    acc[i][j][t] = v;
                    if (t < 2) { s0 += v; q0 += v * v; }
                    else       { s1 += v; q1 += v * v; }
                }
            }
#pragma unroll
            for (int o = 1; o < 4; o <<= 1) {
                s0 += __shfl_xor_sync(0xFFFFFFFFu, s0, o);
                q0 += __shfl_xor_sync(0xFFFFFFFFu, q0, o);
                s1 += __shfl_xor_sync(0xFFFFFFFFu, s1, o);
                q1 += __shfl_xor_sync(0xFFFFFFFFu, q1, o);
            }
            if ((lane & 3) == 0) {
                int r = wm * 64 + i * 16 + lr;
                redS[r * 4 + wn] = s0;  redQ[r * 4 + wn] = q0;
                redS[(r + 8) * 4 + wn] = s1;  redQ[(r + 8) * 4 + wn] = q1;
            }
        }
        __syncthreads();
        __half* ob = (__half*)out;
#pragma unroll
        for (int i = 0; i < 4; i++) {
            int rbase = wm * 64 + i * 16 + lr;
#pragma unroll
            for (int half_ = 0; half_ < 2; half_++) {
                int r = rbase + half_ * 8;
                float s = redS[r * 4] + redS[r * 4 + 1] + redS[r * 4 + 2] + redS[r * 4 + 3];
                float q = redQ[r * 4] + redQ[r * 4 + 1] + redQ[r * 4 + 2] + redQ[r * 4 + 3];
                float mean = s * (1.f / 128.f);
                float var = q * (1.f / 128.f) - mean * mean;
                float rs = rsqrtf(var + 1e-5f);
                int token = row0 + r;
#pragma unroll
                for (int j = 0; j < 4; j++) {
                    int cl = wn * 32 + j * 8 + lc;
                    float v0 = (acc[i][j][half_ * 2 + 0] - mean) * rs * sp[128 + cl]
                             + sp[256 + cl];
                    float v1 = (acc[i][j][half_ * 2 + 1] - mean) * rs * sp[128 + cl + 1]
                             + sp[256 + cl + 1];
                    size_t base = (size_t)token * 1024 + hd * 128 + cl;
                    *(uint32_t*)(ob + base) = packh2(__float2half(v0),
                                                     __float2half(v1));
                }
            }
        }
    } else {
        float* C = (float*)out;
#pragma unroll
        for (int i = 0; i < 4; i++) {
#pragma unroll
            for (int half_ = 0; half_ < 2; half_++) {
                int r = wm * 64 + i * 16 + lr + half_ * 8;
                float* crow = C + (size_t)(row0 + r) * EDIM + col0;
#pragma unroll
                for (int j = 0; j < 4; j++) {
                    int cl = wn * 32 + j * 8 + lc;
                    float2 ov;
                    ov.x = acc[i][j][half_ * 2 + 0] + sp[cl];
                    ov.y = acc[i][j][half_ * 2 + 1] + sp[cl + 1];
                    *(float2*)(crow + cl) = ov;
                }
            }
        }
    }
}

// ---------------------------------------------------------------------------
// Tensor-core flash attention, plain fp16 Q/K/V, 2 CTAs/SM.
// CTA = 128 q-rows x one (b,h). 8 warps x 16 rows. 32-key chunks, 3 stages.
// Epilogue: O/l -> plain fp16, stride 1024 (feeds single-pass final GEMM).
// ---------------------------------------------------------------------------
#define AT_Q   0                        // 128 x 256B = 32768
#define AT_K   32768                    // 3 stages x 8192 (2 subtiles 32x128B)
#define AT_V   (32768 + 24576)          // 3 stages x 8192
#define AT_MK  (AT_V + 24576)           // 3 x 128B mask
#define AT_SMEM (AT_MK + 384)

__global__ void __launch_bounds__(256, 2) attn_tc(
    const __half* __restrict__ Qp, const __half* __restrict__ Kp,
    const __half* __restrict__ Vp, const int* __restrict__ mask,
    __half* __restrict__ OB, int M)
{
    extern __shared__ char dsm[];
    const uint32_t sb = s2u(dsm);
    const int tid = threadIdx.x;
    const int lane = tid & 31;
    const int wrp = tid >> 5;
    const int qrow0 = blockIdx.x * 128;
    const int hd = blockIdx.y;
    const int b = blockIdx.z;

    const char* qg = (const char*)(Qp + (size_t)(b * M + qrow0) * 1024 + hd * 128);
    const char* kg = (const char*)(Kp + (size_t)b * M * 1024 + hd * 128);
    const char* vg = (const char*)(Vp + (size_t)b * M * 1024 + hd * 128);

    // Q resident: 128 rows x 256B = 2048 granules
#pragma unroll
    for (int l = 0; l < 8; l++) {
        int gi = tid + 256 * l;
        int row = gi >> 4, q = gi & 15;
        uint32_t off = (q >> 3) * 16384 + row * 128 + (q & 7) * 16;
        cpasync16(sb + AT_Q + swz(off), qg + (size_t)row * 2048 + q * 16);
    }

    auto load_stage = [&](int c, int s) {
        uint32_t kb = sb + AT_K + s * 8192;
        uint32_t vb = sb + AT_V + s * 8192;
#pragma unroll
        for (int l = 0; l < 2; l++) {
            int gi = tid + 256 * l;
            int row = gi >> 4, q = gi & 15;
            uint32_t off = (q >> 3) * 4096 + row * 128 + (q & 7) * 16;
            cpasync16(kb + swz(off), kg + (size_t)(c * 32 + row) * 2048 + q * 16);
            cpasync16(vb + swz(off), vg + (size_t)(c * 32 + row) * 2048 + q * 16);
        }
        if (tid < 8)
            cpasync16(sb + AT_MK + s * 128 + tid * 16,
                      (const char*)(mask + (size_t)b * M + c * 32) + tid * 16);
        asm volatile("cp.async.commit_group;" ::: "memory");
    };

    load_stage(0, 0);
    load_stage(1, 1);

    const uint32_t aoff = (wrp * 16 + (lane & 15)) * 128 + ((lane >> 4) << 4);
    uint32_t boff[2];
#pragma unroll
    for (int hf = 0; hf < 2; hf++)
        boff[hf] = (hf * 16 + (lane & 7) + ((lane >> 4) << 3)) * 128
                 + (((lane >> 3) & 1) << 4);
    const uint32_t vrow = ((lane & 7) + (((lane >> 3) & 1) << 3)) * 128;
    const uint32_t vcol = ((lane >> 4) << 4);

    float O[16][4];
#pragma unroll
    for (int j = 0; j < 16; j++)
#pragma unroll
        for (int t = 0; t < 4; t++) O[j][t] = 0.f;
    float mi[2] = {-1e30f, -1e30f}, li[2] = {0.f, 0.f};
    const float scaling = 0.08838834764831845f;

    const int NCHA = M / 32;
    for (int c = 0; c < NCHA; c++) {
        if (c < NCHA - 2) asm volatile("cp.async.wait_group 1;" ::: "memory");
        else              asm volatile("cp.async.wait_group 0;" ::: "memory");
        __syncthreads();
        if (c + 2 < NCHA) load_stage(c + 2, (c + 2) % 3);

        const uint32_t Kb = sb + AT_K + (c % 3) * 8192;
        const uint32_t Vb = sb + AT_V + (c % 3) * 8192;
        const int* mk = (const int*)(dsm + AT_MK + (c % 3) * 128);

        // ---- S = Q . Ktile^T  (D = 128) ----
        float cS[4][4];
#pragma unroll
        for (int t = 0; t < 4; t++)
#pragma unroll
            for (int u = 0; u < 4; u++) cS[t][u] = 0.f;
#pragma unroll
        for (int kc = 0; kc < 2; kc++) {
#pragma unroll
            for (int ks = 0; ks < 4; ks++) {
                uint32_t a[4], bb[2][4];
                ldsm_x4(a, sb + AT_Q + swz(kc * 16384 + aoff + ks * 32));
#pragma unroll
                for (int hf = 0; hf < 2; hf++)
                    ldsm_x4(bb[hf], Kb + swz(kc * 4096 + boff[hf] + ks * 32));
#pragma unroll
                for (int hf = 0; hf < 2; hf++) {
                    mma_f16(cS[hf * 2 + 0], a, &bb[hf][0]);
                    mma_f16(cS[hf * 2 + 1], a, &bb[hf][2]);
                }
            }
        }

        // ---- softmax (warp-local rows) ----
#pragma unroll
        for (int t = 0; t < 4; t++) {
            int2 mv = *(const int2*)&mk[t * 8 + ((lane & 3) << 1)];
#pragma unroll
            for (int u = 0; u < 4; u++) {
                float s = cS[t][u] * scaling;
                int mkv = (u & 1) ? mv.y : mv.x;
                cS[t][u] = (mkv == 0) ? -1e9f : s;
            }
        }
        float tmax0 = -1e30f, tmax1 = -1e30f;
#pragma unroll
        for (int t = 0; t < 4; t++) {
            tmax0 = fmaxf(tmax0, fmaxf(cS[t][0], cS[t][1]));
            tmax1 = fmaxf(tmax1, fmaxf(cS[t][2], cS[t][3]));
        }
#pragma unroll
        for (int o = 1; o < 4; o <<= 1) {
            tmax0 = fmaxf(tmax0, __shfl_xor_sync(0xFFFFFFFFu, tmax0, o));
            tmax1 = fmaxf(tmax1, __shfl_xor_sync(0xFFFFFFFFu, tmax1, o));
        }
        float mn0 = fmaxf(mi[0], tmax0), mn1 = fmaxf(mi[1], tmax1);
        float al0 = __expf(mi[0] - mn0), al1 = __expf(mi[1] - mn1);
        mi[0] = mn0; mi[1] = mn1;

        float ps0 = 0.f, ps1 = 0.f;
#pragma unroll
        for (int t = 0; t < 4; t++) {
            cS[t][0] = __expf(cS[t][0] - mn0);
            cS[t][1] = __expf(cS[t][1] - mn0);
            cS[t][2] = __expf(cS[t][2] - mn1);
            cS[t][3] = __expf(cS[t][3] - mn1);
            ps0 += cS[t][0] + cS[t][1];
            ps1 += cS[t][2] + cS[t][3];
        }
#pragma unroll
        for (int o = 1; o < 4; o <<= 1) {
            ps0 += __shfl_xor_sync(0xFFFFFFFFu, ps0, o);
            ps1 += __shfl_xor_sync(0xFFFFFFFFu, ps1, o);
        }
        li[0] = li[0] * al0 + ps0;
        li[1] = li[1] * al1 + ps1;
#pragma unroll
        for (int j = 0; j < 16; j++) {
            O[j][0] *= al0; O[j][1] *= al0;
            O[j][2] *= al1; O[j][3] *= al1;
        }

        // pack P into A fragments (fp16)
        uint32_t ahh[2][4];
#pragma unroll
        for (int ks = 0; ks < 2; ks++) {
#pragma unroll
            for (int sub = 0; sub < 2; sub++) {
                int t = 2 * ks + sub;
                ahh[ks][sub * 2 + 0] = packh2(__float2half(cS[t][0]),
                                              __float2half(cS[t][1]));
                ahh[ks][sub * 2 + 1] = packh2(__float2half(cS[t][2]),
                                              __float2half(cS[t][3]));
            }
        }

        // ---- O += P . V ----
#pragma unroll
        for (int g = 0; g < 8; g++) {
            const int vch = g >> 2;
            const uint32_t colb = (g & 3) * 32 + vcol;
#pragma unroll
            for (int ks = 0; ks < 2; ks++) {
                uint32_t bv[4];
                uint32_t ro = (uint32_t)(ks * 16) * 128 + vrow;
                ldsm_x4_t(bv, Vb + swz(vch * 4096 + ro + colb));
                mma_f16(O[2 * g + 0], ahh[ks], &bv[0]);
                mma_f16(O[2 * g + 1], ahh[ks], &bv[2]);
            }
        }
    }

    // ---- epilogue: O / l, plain fp16 rows (stride 1024) ----
    float inv0 = 1.0f / li[0], inv1 = 1.0f / li[1];
#pragma unroll
    for (int half_ = 0; half_ < 2; half_++) {
        float inv = half_ ? inv1 : inv0;
        int token = b * M + qrow0 + wrp * 16 + (lane >> 2) + half_ * 8;
        size_t rowbase = (size_t)token * 1024 + hd * 128 + ((lane & 3) << 1);
#pragma unroll
        for (int j = 0; j < 16; j++) {
            float v0 = O[j][half_ * 2 + 0] * inv;
            float v1 = O[j][half_ * 2 + 1] * inv;
            *(uint32_t*)(OB + rowbase + j * 8) = packh2(__float2half(v0),
                                                        __float2half(v1));
        }
    }
}

// ---------------------------------------------------------------------------
// Launch sequence: fork Q/K/V chains across streams (graph-capture-safe
// event fork/join), join before attention. Kernel launches + event ops only.
// ---------------------------------------------------------------------------
extern "C" void kernel_launch(void* const* d_in, const int* in_sizes, int n_in,
                              void* d_out, int out_size)
{
    const float* query  = (const float*)d_in[0];
    const float* key    = (const float*)d_in[1];
    const int*   mask   = (const int*)d_in[2];
    // d_in[3] = value1, intentionally unused (matches reference)
    const float* value2 = (const float*)d_in[4];
    const float* Wq = (const float*)d_in[5];
    const float* bq = (const float*)d_in[6];
    const float* gq = (const float*)d_in[7];
    const float* betaq = (const float*)d_in[8];
    const float* Wk = (const float*)d_in[9];
    const float* bk = (const float*)d_in[10];
    const float* gk = (const float*)d_in[11];
    const float* betak = (const float*)d_in[12];
    const float* Wv = (const float*)d_in[13];
    const float* bv = (const float*)d_in[14];
    const float* gv = (const float*)d_in[15];
    const float* betav = (const float*)d_in[16];
    const float* Wm = (const float*)d_in[17];
    const float* bm = (const float*)d_in[18];

    const int B = in_sizes[3] / EDIM;   // value1 is [B, E]
    const int Ntok = in_sizes[2];       // mask is [B, M]
    const int M = Ntok / B;

    __half *aq, *ak, *av, *ao, *wq2, *wk2, *wv2, *wm2, *qp, *kp, *vp;
    cudaGetSymbolAddress((void**)&aq, g_aq);
    cudaGetSymbolAddress((void**)&ak, g_ak);
    cudaGetSymbolAddress((void**)&av, g_av);
    cudaGetSymbolAddress((void**)&ao, g_ao);
    cudaGetSymbolAddress((void**)&wq2, g_wq2);
    cudaGetSymbolAddress((void**)&wk2, g_wk2);
    cudaGetSymbolAddress((void**)&wv2, g_wv2);
    cudaGetSymbolAddress((void**)&wm2, g_wm2);
    cudaGetSymbolAddress((void**)&qp, g_qp);
    cudaGetSymbolAddress((void**)&kp, g_kp);
    cudaGetSymbolAddress((void**)&vp, g_vp);

    // One-time host-side resources (no device memory involved).
    static cudaStream_t s2 = nullptr, s3 = nullptr, s4 = nullptr;
    static cudaEvent_t evRoot = nullptr, evK = nullptr, evV = nullptr,
                       evW = nullptr;
    if (!s2) {
        cudaStreamCreateWithFlags(&s2, cudaStreamNonBlocking);
        cudaStreamCreateWithFlags(&s3, cudaStreamNonBlocking);
        cudaStreamCreateWithFlags(&s4, cudaStreamNonBlocking);
        cudaEventCreateWithFlags(&evRoot, cudaEventDisableTiming);
        cudaEventCreateWithFlags(&evK, cudaEventDisableTiming);
        cudaEventCreateWithFlags(&evV, cudaEventDisableTiming);
        cudaEventCreateWithFlags(&evW, cudaEventDisableTiming);
        cudaFuncSetAttribute(gemm_tc<0>,
            cudaFuncAttributeMaxDynamicSharedMemorySize, GEMM_SMEM);
        cudaFuncSetAttribute(gemm_tc<1>,
            cudaFuncAttributeMaxDynamicSharedMemorySize, GEMM_SMEM);
        cudaFuncSetAttribute(attn_tc,
            cudaFuncAttributeMaxDynamicSharedMemorySize, AT_SMEM);
    }

    dim3 blk(256);
    dim3 gg(EDIM / 128, Ntok / 128);
    const int CAW = EDIM * EDIM / 2048;   // weight convert grid (512)
    const int CAA = Ntok * EDIM / 2048;   // activation convert grid (16384)

    // ---- fork ----
    cudaEventRecord(evRoot, 0);
    cudaStreamWaitEvent(s2, evRoot, 0);
    cudaStreamWaitEvent(s3, evRoot, 0);
    cudaStreamWaitEvent(s4, evRoot, 0);

    // Q chain (capture stream)
    convert1h<<<CAW, 256>>>(Wq, wq2);
    convert1h<<<CAA, 256>>>(query, aq);
    gemm_tc<1><<<gg, blk, GEMM_SMEM>>>(aq, wq2, bq, gq, betaq, qp);

    // K chain (s2)
    convert1h<<<CAW, 256, 0, s2>>>(Wk, wk2);
    convert1h<<<CAA, 256, 0, s2>>>(key, ak);
    gemm_tc<1><<<gg, blk, GEMM_SMEM, s2>>>(ak, wk2, bk, gk, betak, kp);

    // V chain (s3)
    convert1h<<<CAW, 256, 0, s3>>>(Wv, wv2);
    convert1h<<<CAA, 256, 0, s3>>>(value2, av);
    gemm_tc<1><<<gg, blk, GEMM_SMEM, s3>>>(av, wv2, bv, gv, betav, vp);

    // Wm convert (s4) — needed only by the final GEMM
    convert1h<<<CAW, 256, 0, s4>>>(Wm, wm2);

    // ---- join ----
    cudaEventRecord(evK, s2);
    cudaStreamWaitEvent(0, evK, 0);
    cudaEventRecord(evV, s3);
    cudaStreamWaitEvent(0, evV, 0);
    cudaEventRecord(evW, s4);
    cudaStreamWaitEvent(0, evW, 0);

    dim3 ga(M / 128, HEADS, B);
    attn_tc<<<ga, blk, AT_SMEM>>>(qp, kp, vp, mask, ao, M);

    gemm_tc<0><<<gg, blk, GEMM_SMEM>>>(ao, wm2, bm, nullptr, nullptr, d_out);
}